// round 1
// baseline (speedup 1.0000x reference)
#include <cuda_runtime.h>

// ---------------------------------------------------------------------------
// CrossOnlyAttention  (B=64, T=469, C=1024, H=16, hd=64)
//   qkv  = x @ W_attn + b_attn
//   attn = softmax(q k^T / 8 + cross_bias) @ v
//   out  = y @ W_proj + b_proj
// Round 0: correct fp32 baseline (FFMA SGEMM + smem-resident attention).
// ---------------------------------------------------------------------------

#define TSEQ   469
#define NB     64
#define NC     1024
#define NH     16
#define HD     64
#define MROWS  (NB * TSEQ)   // 30016
#define NQKV   (3 * NC)      // 3072

// scratch (allocation-free rule: __device__ globals)
__device__ float g_qkv[(size_t)MROWS * NQKV];  // 368.8 MB
__device__ float g_y[(size_t)MROWS * NC];      // 123.0 MB

// ---------------------------------------------------------------------------
// SGEMM: C[M,N] = A[M,K] @ B[K,N] + bias[N]
// 128x128 block, BK=8, 256 threads, 8x8 per-thread tile, A transposed in smem,
// register prefetch of next K-slice.
// ---------------------------------------------------------------------------
template <bool A_IS_Y, bool C_IS_QKV>
__global__ void __launch_bounds__(256, 2)
sgemm_bias(const float* __restrict__ A, const float* __restrict__ Bm,
           const float* __restrict__ bias, float* __restrict__ Cm,
           int M, int N, int K)
{
    if (A_IS_Y)   A  = g_y;
    if (C_IS_QKV) Cm = g_qkv;

    __shared__ float As[8][128];
    __shared__ float Bs[8][128];

    const int tid  = threadIdx.x;
    const int trow = tid >> 4;          // 0..15
    const int tcol = tid & 15;          // 0..15
    const int row0 = blockIdx.y * 128;
    const int col0 = blockIdx.x * 128;

    // load mappings
    const int aRow = tid >> 1;          // 0..127
    const int aK   = (tid & 1) * 4;     // 0 or 4
    const int bRow = tid >> 5;          // 0..7
    const int bCol = (tid & 31) * 4;    // 0..124

    const bool aValid = (row0 + aRow) < M;
    const float* aPtr = A + (size_t)(row0 + aRow) * K + aK;
    const float* bPtr = Bm + (size_t)bRow * N + col0 + bCol;

    float acc[8][8];
#pragma unroll
    for (int i = 0; i < 8; i++)
#pragma unroll
        for (int j = 0; j < 8; j++) acc[i][j] = 0.f;

    float4 a4 = aValid ? *(const float4*)(aPtr) : make_float4(0.f, 0.f, 0.f, 0.f);
    float4 b4 = *(const float4*)(bPtr);

    for (int k0 = 0; k0 < K; k0 += 8) {
        As[aK + 0][aRow] = a4.x;
        As[aK + 1][aRow] = a4.y;
        As[aK + 2][aRow] = a4.z;
        As[aK + 3][aRow] = a4.w;
        *(float4*)&Bs[bRow][bCol] = b4;
        __syncthreads();

        const int k1 = k0 + 8;
        if (k1 < K) {   // prefetch next slice while computing
            a4 = aValid ? *(const float4*)(aPtr + k1) : make_float4(0.f, 0.f, 0.f, 0.f);
            b4 = *(const float4*)(bPtr + (size_t)k1 * N);
        }

#pragma unroll
        for (int kk = 0; kk < 8; kk++) {
            float ar[8], br[8];
            *(float4*)&ar[0] = *(const float4*)&As[kk][trow * 8];
            *(float4*)&ar[4] = *(const float4*)&As[kk][trow * 8 + 4];
            *(float4*)&br[0] = *(const float4*)&Bs[kk][tcol * 8];
            *(float4*)&br[4] = *(const float4*)&Bs[kk][tcol * 8 + 4];
#pragma unroll
            for (int i = 0; i < 8; i++)
#pragma unroll
                for (int j = 0; j < 8; j++)
                    acc[i][j] += ar[i] * br[j];
        }
        __syncthreads();
    }

    float bv[8];
#pragma unroll
    for (int j = 0; j < 8; j++) bv[j] = bias[col0 + tcol * 8 + j];

#pragma unroll
    for (int i = 0; i < 8; i++) {
        const int r = row0 + trow * 8 + i;
        if (r < M) {
            float4 o0, o1;
            o0.x = acc[i][0] + bv[0]; o0.y = acc[i][1] + bv[1];
            o0.z = acc[i][2] + bv[2]; o0.w = acc[i][3] + bv[3];
            o1.x = acc[i][4] + bv[4]; o1.y = acc[i][5] + bv[5];
            o1.z = acc[i][6] + bv[6]; o1.w = acc[i][7] + bv[7];
            float* dst = Cm + (size_t)r * N + col0 + tcol * 8;
            *(float4*)(dst)     = o0;
            *(float4*)(dst + 4) = o1;
        }
    }
}

// ---------------------------------------------------------------------------
// Attention: one block = one (b, h, 64 q-rows) tile; scores row-resident in smem
// ---------------------------------------------------------------------------
#define QR      64
#define SPITCH  472     // 469 padded
#define KPITCH  68      // 64 padded (16B-aligned rows, conflict-free)
#define ATTN_SMEM_FLOATS (QR * SPITCH + QR * KPITCH + 64 * KPITCH + QR)
#define ATTN_SMEM_BYTES  (ATTN_SMEM_FLOATS * 4)

__device__ __forceinline__ float cross_bias(int i, int j)
{
    // full[0,:]=1, full[:,0]=1, full[1+a,1+b] = (a<234) xor (b<234)
    if (i == 0 || j == 0) return 1.0f;
    const bool i1 = (i <= 234);
    const bool j1 = (j <= 234);
    return (i1 != j1) ? 1.0f : 0.0f;
}

__global__ void __launch_bounds__(256, 1)
attn_kernel()
{
    extern __shared__ float sm[];
    float* S    = sm;                       // [QR][SPITCH]
    float* qs   = S + QR * SPITCH;          // [QR][KPITCH]
    float* kv   = qs + QR * KPITCH;         // [64][KPITCH]
    float* rinv = kv + 64 * KPITCH;         // [QR]

    const int tid = threadIdx.x;
    const int bh  = blockIdx.y;
    const int b   = bh >> 4;
    const int h   = bh & 15;
    const int q0  = blockIdx.x * QR;

    const float* base = g_qkv + (size_t)b * TSEQ * NQKV + h * HD;

    // ---- load Q tile (64 x 64) ----
    {
        const int r  = tid >> 2;
        const int d0 = (tid & 3) * 16;
        float* dst = qs + r * KPITCH + d0;
        const int t = q0 + r;
        if (t < TSEQ) {
            const float* src = base + (size_t)t * NQKV + d0;
#pragma unroll
            for (int q = 0; q < 4; q++)
                *(float4*)(dst + 4 * q) = *(const float4*)(src + 4 * q);
        } else {
#pragma unroll
            for (int q = 0; q < 16; q++) dst[q] = 0.f;
        }
    }

    const int r0 = tid >> 3;      // rows r0 and r0+32
    const int l8 = tid & 7;       // cols/dims l8 + 8*i
    const float scale = 0.125f;

    // ---- phase 1: S = q k^T * scale + bias ----
    for (int j0 = 0; j0 < TSEQ; j0 += 64) {
        const int jn = min(64, TSEQ - j0);
        __syncthreads();  // prev-iter kv reads done; q tile visible (iter 0)
        {
            const int c  = tid >> 2;
            const int d0 = (tid & 3) * 16;
            if (c < jn) {
                const float* src = base + NC + (size_t)(j0 + c) * NQKV + d0;
                float* dst = kv + c * KPITCH + d0;
#pragma unroll
                for (int q = 0; q < 4; q++)
                    *(float4*)(dst + 4 * q) = *(const float4*)(src + 4 * q);
            }
        }
        __syncthreads();

        float acc0[8], acc1[8];
#pragma unroll
        for (int i = 0; i < 8; i++) { acc0[i] = 0.f; acc1[i] = 0.f; }

#pragma unroll 4
        for (int d = 0; d < 64; d++) {
            const float qa = qs[r0 * KPITCH + d];
            const float qb = qs[(r0 + 32) * KPITCH + d];
#pragma unroll
            for (int i = 0; i < 8; i++) {
                const float kvv = kv[(l8 + 8 * i) * KPITCH + d];
                acc0[i] += qa * kvv;
                acc1[i] += qb * kvv;
            }
        }
#pragma unroll
        for (int i = 0; i < 8; i++) {
            const int j = l8 + 8 * i;
            if (j < jn) {
                const int jg = j0 + j;
                S[r0 * SPITCH + jg]        = acc0[i] * scale + cross_bias(q0 + r0, jg);
                S[(r0 + 32) * SPITCH + jg] = acc1[i] * scale + cross_bias(q0 + r0 + 32, jg);
            }
        }
    }
    __syncthreads();

    // ---- phase 2: softmax rows (4 threads / row) ----
    {
        const int row = tid >> 2;
        const int l4  = tid & 3;
        float m = -1e30f;
        for (int j = l4; j < TSEQ; j += 4) m = fmaxf(m, S[row * SPITCH + j]);
        m = fmaxf(m, __shfl_xor_sync(0xffffffffu, m, 1, 4));
        m = fmaxf(m, __shfl_xor_sync(0xffffffffu, m, 2, 4));
        float s = 0.f;
        for (int j = l4; j < TSEQ; j += 4) {
            const float e = __expf(S[row * SPITCH + j] - m);
            S[row * SPITCH + j] = e;
            s += e;
        }
        s += __shfl_xor_sync(0xffffffffu, s, 1, 4);
        s += __shfl_xor_sync(0xffffffffu, s, 2, 4);
        if (l4 == 0) rinv[row] = 1.0f / s;
    }
    __syncthreads();

    // ---- phase 3: y = P @ V, normalized ----
    float y0[8], y1[8];
#pragma unroll
    for (int i = 0; i < 8; i++) { y0[i] = 0.f; y1[i] = 0.f; }

    for (int j0 = 0; j0 < TSEQ; j0 += 64) {
        const int jn = min(64, TSEQ - j0);
        __syncthreads();  // prev-iter kv reads done
        {
            const int c  = tid >> 2;
            const int d0 = (tid & 3) * 16;
            if (c < jn) {
                const float* src = base + 2 * NC + (size_t)(j0 + c) * NQKV + d0;
                float* dst = kv + c * KPITCH + d0;
#pragma unroll
                for (int q = 0; q < 4; q++)
                    *(float4*)(dst + 4 * q) = *(const float4*)(src + 4 * q);
            }
        }
        __syncthreads();

        for (int j = 0; j < jn; j++) {
            const float p0 = S[r0 * SPITCH + j0 + j];
            const float p1 = S[(r0 + 32) * SPITCH + j0 + j];
#pragma unroll
            for (int i = 0; i < 8; i++) {
                const float vv = kv[j * KPITCH + l8 + 8 * i];
                y0[i] += p0 * vv;
                y1[i] += p1 * vv;
            }
        }
    }

    {
        const float s0 = rinv[r0];
        const float s1 = rinv[r0 + 32];
        const int t0 = q0 + r0;
        const int t1 = q0 + r0 + 32;
        if (t0 < TSEQ) {
            float* dst = g_y + (size_t)(b * TSEQ + t0) * NC + h * HD;
#pragma unroll
            for (int i = 0; i < 8; i++) dst[l8 + 8 * i] = y0[i] * s0;
        }
        if (t1 < TSEQ) {
            float* dst = g_y + (size_t)(b * TSEQ + t1) * NC + h * HD;
#pragma unroll
            for (int i = 0; i < 8; i++) dst[l8 + 8 * i] = y1[i] * s1;
        }
    }
}

// ---------------------------------------------------------------------------
extern "C" void kernel_launch(void* const* d_in, const int* in_sizes, int n_in,
                              void* d_out, int out_size)
{
    const float* x      = (const float*)d_in[0];
    const float* W_attn = (const float*)d_in[1];
    const float* b_attn = (const float*)d_in[2];
    const float* W_proj = (const float*)d_in[3];
    const float* b_proj = (const float*)d_in[4];
    float* out = (float*)d_out;

    // attribute persists per-function; harmless if re-issued during capture
    cudaFuncSetAttribute(attn_kernel,
                         cudaFuncAttributeMaxDynamicSharedMemorySize,
                         ATTN_SMEM_BYTES);

    // 1) qkv = x @ W_attn + b_attn
    dim3 g1(NQKV / 128, (MROWS + 127) / 128);
    sgemm_bias<false, true><<<g1, 256>>>(x, W_attn, b_attn, nullptr,
                                         MROWS, NQKV, NC);

    // 2) attention
    dim3 ga((TSEQ + QR - 1) / QR, NB * NH);
    attn_kernel<<<ga, 256, ATTN_SMEM_BYTES>>>();

    // 3) out = y @ W_proj + b_proj
    dim3 g2(NC / 128, (MROWS + 127) / 128);
    sgemm_bias<true, false><<<g2, 256>>>(nullptr, W_proj, b_proj, out,
                                         MROWS, NC, NC);
}

// round 3
// speedup vs baseline: 1.5680x; 1.5680x over previous
#include <cuda_runtime.h>
#include <cuda_bf16.h>
#include <cstdint>

// ---------------------------------------------------------------------------
// CrossOnlyAttention  (B=64, T=469, C=1024, H=16, hd=64)
// Round 2: GEMMs on mma.sync bf16 (hi/lo split, fp32 accum) — the harness's
// ptxas targets plain sm_100, so tcgen05 is unavailable; use the legacy
// HMMA path (mma.sync + ldmatrix + cp.async). Attention unchanged.
// ---------------------------------------------------------------------------

#define TSEQ   469
#define NB     64
#define NC     1024
#define NH     16
#define HD     64
#define MROWS  (NB * TSEQ)   // 30016
#define NQKV   (3 * NC)      // 3072
#define GK     1024

// scratch (__device__ globals: allocation-free rule)
__device__ float g_qkv[(size_t)MROWS * NQKV];
__device__ float g_y[(size_t)MROWS * NC];
__device__ __nv_bfloat16 g_a_hi[(size_t)MROWS * NC];
__device__ __nv_bfloat16 g_a_lo[(size_t)MROWS * NC];
__device__ __nv_bfloat16 g_wq_hi[(size_t)NQKV * GK];
__device__ __nv_bfloat16 g_wq_lo[(size_t)NQKV * GK];
__device__ __nv_bfloat16 g_wp_hi[(size_t)NC * GK];
__device__ __nv_bfloat16 g_wp_lo[(size_t)NC * GK];

// ---------------------------------------------------------------------------
// helpers
// ---------------------------------------------------------------------------
__device__ __forceinline__ uint32_t smem_u32(const void* p) {
    uint32_t a;
    asm("{ .reg .u64 t; cvta.to.shared.u64 t, %1; cvt.u32.u64 %0, t; }" : "=r"(a) : "l"(p));
    return a;
}

#define CP_ASYNC16(dst, src, sz) \
    asm volatile("cp.async.cg.shared.global [%0], [%1], 16, %2;" \
                 :: "r"(dst), "l"(src), "r"(sz) : "memory")
#define CP_COMMIT() asm volatile("cp.async.commit_group;" ::: "memory")
#define CP_WAIT(N)  asm volatile("cp.async.wait_group %0;" :: "n"(N) : "memory")

__device__ __forceinline__ void ldmatrix_x4(uint32_t* r, uint32_t addr) {
    asm volatile("ldmatrix.sync.aligned.m8n8.x4.shared.b16 {%0,%1,%2,%3}, [%4];"
                 : "=r"(r[0]), "=r"(r[1]), "=r"(r[2]), "=r"(r[3]) : "r"(addr));
}
__device__ __forceinline__ void ldmatrix_x2(uint32_t* r, uint32_t addr) {
    asm volatile("ldmatrix.sync.aligned.m8n8.x2.shared.b16 {%0,%1}, [%2];"
                 : "=r"(r[0]), "=r"(r[1]) : "r"(addr));
}
__device__ __forceinline__ void mma_bf16(float* c, const uint32_t* a, const uint32_t* b) {
    asm volatile("mma.sync.aligned.m16n8k16.row.col.f32.bf16.bf16.f32 "
                 "{%0,%1,%2,%3},{%4,%5,%6,%7},{%8,%9},{%0,%1,%2,%3};"
                 : "+f"(c[0]), "+f"(c[1]), "+f"(c[2]), "+f"(c[3])
                 : "r"(a[0]), "r"(a[1]), "r"(a[2]), "r"(a[3]), "r"(b[0]), "r"(b[1]));
}

// ---------------------------------------------------------------------------
// Conversion kernels
// ---------------------------------------------------------------------------
__global__ void split_fp32(const float* __restrict__ src_or_null,
                           __nv_bfloat16* __restrict__ hi,
                           __nv_bfloat16* __restrict__ lo, size_t n4)
{
    const float* src = src_or_null ? src_or_null : g_y;
    size_t i = (size_t)blockIdx.x * blockDim.x + threadIdx.x;
    if (i >= n4) return;
    float4 v = ((const float4*)src)[i];
    float vv[4] = {v.x, v.y, v.z, v.w};
    __align__(8) __nv_bfloat16 h[4], l[4];
#pragma unroll
    for (int q = 0; q < 4; q++) {
        h[q] = __float2bfloat16(vv[q]);
        l[q] = __float2bfloat16(vv[q] - __bfloat162float(h[q]));
    }
    ((uint2*)hi)[i] = *(uint2*)h;
    ((uint2*)lo)[i] = *(uint2*)l;
}

// src [K][N] fp32 -> dst [N][K] bf16 hi/lo
__global__ void transpose_split(const float* __restrict__ src,
                                __nv_bfloat16* __restrict__ dhi,
                                __nv_bfloat16* __restrict__ dlo, int K, int N)
{
    __shared__ float tile[32][33];
    const int n0 = blockIdx.x * 32, k0 = blockIdx.y * 32;
    const int tx = threadIdx.x & 31, ty0 = threadIdx.x >> 5;
#pragma unroll
    for (int i = 0; i < 4; i++) {
        int ty = ty0 + i * 8;
        tile[ty][tx] = src[(size_t)(k0 + ty) * N + n0 + tx];
    }
    __syncthreads();
#pragma unroll
    for (int i = 0; i < 4; i++) {
        int ty = ty0 + i * 8;
        float v = tile[tx][ty];
        __nv_bfloat16 h = __float2bfloat16(v);
        __nv_bfloat16 l = __float2bfloat16(v - __bfloat162float(h));
        dhi[(size_t)(n0 + ty) * K + k0 + tx] = h;
        dlo[(size_t)(n0 + ty) * K + k0 + tx] = l;
    }
}

// ---------------------------------------------------------------------------
// mma.sync GEMM: out[M,N] = A(hi+lo)[M,GK] @ W(hi+lo)[N,GK]^T + bias[N]
// 128x128 CTA tile, BK=32, 8 warps (2x4), 64x32 warp tiles, double buffer.
// ---------------------------------------------------------------------------
#define BK        32
#define NCHUNK    (GK / BK)
#define LDT       40                         // bf16 elems per smem row (+8 pad)
#define TILE_BYTES (128 * LDT * 2)           // 10240
#define STAGE_BYTES (4 * TILE_BYTES)         // Ah, Al, Bh, Bl
#define GEMM_SMEM  (2 * STAGE_BYTES)         // 81920

// issue cp.async for one 128x32 tile (hi or lo); 2 x 16B per thread
__device__ __forceinline__ void tile_cp(const __nv_bfloat16* __restrict__ src,
                                        int row0, int maxrow, int k0,
                                        uint32_t sdst, int tid)
{
#pragma unroll
    for (int i = 0; i < 2; i++) {
        const int idx = tid + i * 256;       // 0..511
        const int r = idx >> 2, seg = idx & 3;
        const int gr = row0 + r;
        const int ok = (gr < maxrow) ? 16 : 0;
        const __nv_bfloat16* gp = src + (size_t)min(gr, maxrow - 1) * GK + k0 + seg * 8;
        CP_ASYNC16(sdst + r * (LDT * 2) + seg * 16, gp, ok);
    }
}

__global__ void __launch_bounds__(256, 1)
gemm_mma(const float* __restrict__ bias, float* __restrict__ outp,
         int M, int N, int whichB)
{
    extern __shared__ char smem[];
    const uint32_t sbase = smem_u32(smem);
    const int tid = threadIdx.x, wid = tid >> 5, lane = tid & 31;
    const int warpM = wid >> 2, warpN = wid & 3;
    const int n0 = blockIdx.x * 128, m0 = blockIdx.y * 128;

    const __nv_bfloat16* Bh = whichB ? g_wp_hi : g_wq_hi;
    const __nv_bfloat16* Bl = whichB ? g_wp_lo : g_wq_lo;
    float* out = outp ? outp : g_qkv;

    float acc[4][4][4];
#pragma unroll
    for (int i = 0; i < 4; i++)
#pragma unroll
        for (int j = 0; j < 4; j++)
#pragma unroll
            for (int q = 0; q < 4; q++) acc[i][j][q] = 0.f;

    // ldmatrix smem addresses (per-lane, stage-relative)
    // A: row = warpM*64 + mi*16 + (lane&15), col = ks*16 + (lane>>4)*8
    const uint32_t aRowB = (uint32_t)(warpM * 64 + (lane & 15)) * (LDT * 2);
    const uint32_t aColB = (uint32_t)((lane >> 4) * 8) * 2;
    // B: row = warpN*32 + ni*8 + (lane&7), col = ks*16 + ((lane>>3)&1)*8
    const uint32_t bRowB = (uint32_t)(warpN * 32 + (lane & 7)) * (LDT * 2);
    const uint32_t bColB = (uint32_t)(((lane >> 3) & 1) * 8) * 2;

    // prologue: stage 0 loads
    tile_cp(g_a_hi, m0, M, 0, sbase + 0 * TILE_BYTES, tid);
    tile_cp(g_a_lo, m0, M, 0, sbase + 1 * TILE_BYTES, tid);
    tile_cp(Bh,     n0, N, 0, sbase + 2 * TILE_BYTES, tid);
    tile_cp(Bl,     n0, N, 0, sbase + 3 * TILE_BYTES, tid);
    CP_COMMIT();

    for (int c = 0; c < NCHUNK; c++) {
        if (c + 1 < NCHUNK) {
            const uint32_t st = sbase + ((c + 1) & 1) * STAGE_BYTES;
            const int k0 = (c + 1) * BK;
            tile_cp(g_a_hi, m0, M, k0, st + 0 * TILE_BYTES, tid);
            tile_cp(g_a_lo, m0, M, k0, st + 1 * TILE_BYTES, tid);
            tile_cp(Bh,     n0, N, k0, st + 2 * TILE_BYTES, tid);
            tile_cp(Bl,     n0, N, k0, st + 3 * TILE_BYTES, tid);
            CP_COMMIT();
            CP_WAIT(1);
        } else {
            CP_WAIT(0);
        }
        __syncthreads();

        const uint32_t st = sbase + (c & 1) * STAGE_BYTES;
        const uint32_t sAh = st, sAl = st + TILE_BYTES;
        const uint32_t sBh = st + 2 * TILE_BYTES, sBl = st + 3 * TILE_BYTES;

#pragma unroll
        for (int ks = 0; ks < 2; ks++) {
            const uint32_t kOffA = aColB + ks * 32;   // ks*16 elems * 2B
            const uint32_t kOffB = bColB + ks * 32;

            uint32_t bh[4][2], bl[4][2];
#pragma unroll
            for (int ni = 0; ni < 4; ni++) {
                const uint32_t bo = bRowB + (uint32_t)(ni * 8) * (LDT * 2) + kOffB;
                ldmatrix_x2(bh[ni], sBh + bo);
                ldmatrix_x2(bl[ni], sBl + bo);
            }
#pragma unroll
            for (int mi = 0; mi < 4; mi++) {
                const uint32_t ao = aRowB + (uint32_t)(mi * 16) * (LDT * 2) + kOffA;
                uint32_t ah[4], al[4];
                ldmatrix_x4(ah, sAh + ao);
                ldmatrix_x4(al, sAl + ao);
#pragma unroll
                for (int ni = 0; ni < 4; ni++) {
                    mma_bf16(acc[mi][ni], ah, bh[ni]);
                    mma_bf16(acc[mi][ni], ah, bl[ni]);
                    mma_bf16(acc[mi][ni], al, bh[ni]);
                }
            }
        }
        __syncthreads();
    }

    // epilogue
    const int cBase = n0 + warpN * 32 + (lane & 3) * 2;
    const int rBase = m0 + warpM * 64 + (lane >> 2);
#pragma unroll
    for (int mi = 0; mi < 4; mi++) {
#pragma unroll
        for (int ni = 0; ni < 4; ni++) {
            const int col = cBase + ni * 8;
            const float b0 = bias[col], b1 = bias[col + 1];
            const int r0 = rBase + mi * 16;
            if (r0 < M) {
                float2 o = make_float2(acc[mi][ni][0] + b0, acc[mi][ni][1] + b1);
                *(float2*)(out + (size_t)r0 * N + col) = o;
            }
            if (r0 + 8 < M) {
                float2 o = make_float2(acc[mi][ni][2] + b0, acc[mi][ni][3] + b1);
                *(float2*)(out + (size_t)(r0 + 8) * N + col) = o;
            }
        }
    }
}

// ---------------------------------------------------------------------------
// Attention (unchanged)
// ---------------------------------------------------------------------------
#define QR      64
#define SPITCH  472
#define KPITCH  68
#define ATTN_SMEM_FLOATS (QR * SPITCH + QR * KPITCH + 64 * KPITCH + QR)
#define ATTN_SMEM_BYTES  (ATTN_SMEM_FLOATS * 4)

__device__ __forceinline__ float cross_bias(int i, int j)
{
    if (i == 0 || j == 0) return 1.0f;
    const bool i1 = (i <= 234);
    const bool j1 = (j <= 234);
    return (i1 != j1) ? 1.0f : 0.0f;
}

__global__ void __launch_bounds__(256, 1)
attn_kernel()
{
    extern __shared__ float sm[];
    float* S    = sm;
    float* qs   = S + QR * SPITCH;
    float* kv   = qs + QR * KPITCH;
    float* rinv = kv + 64 * KPITCH;

    const int tid = threadIdx.x;
    const int bh  = blockIdx.y;
    const int b   = bh >> 4;
    const int h   = bh & 15;
    const int q0  = blockIdx.x * QR;

    const float* base = g_qkv + (size_t)b * TSEQ * NQKV + h * HD;

    {
        const int r  = tid >> 2;
        const int d0 = (tid & 3) * 16;
        float* dst = qs + r * KPITCH + d0;
        const int t = q0 + r;
        if (t < TSEQ) {
            const float* src = base + (size_t)t * NQKV + d0;
#pragma unroll
            for (int q = 0; q < 4; q++)
                *(float4*)(dst + 4 * q) = *(const float4*)(src + 4 * q);
        } else {
#pragma unroll
            for (int q = 0; q < 16; q++) dst[q] = 0.f;
        }
    }

    const int r0 = tid >> 3;
    const int l8 = tid & 7;
    const float scale = 0.125f;

    for (int j0 = 0; j0 < TSEQ; j0 += 64) {
        const int jn = min(64, TSEQ - j0);
        __syncthreads();
        {
            const int c  = tid >> 2;
            const int d0 = (tid & 3) * 16;
            if (c < jn) {
                const float* src = base + NC + (size_t)(j0 + c) * NQKV + d0;
                float* dst = kv + c * KPITCH + d0;
#pragma unroll
                for (int q = 0; q < 4; q++)
                    *(float4*)(dst + 4 * q) = *(const float4*)(src + 4 * q);
            }
        }
        __syncthreads();

        float acc0[8], acc1[8];
#pragma unroll
        for (int i = 0; i < 8; i++) { acc0[i] = 0.f; acc1[i] = 0.f; }

#pragma unroll 4
        for (int d = 0; d < 64; d++) {
            const float qa = qs[r0 * KPITCH + d];
            const float qb = qs[(r0 + 32) * KPITCH + d];
#pragma unroll
            for (int i = 0; i < 8; i++) {
                const float kvv = kv[(l8 + 8 * i) * KPITCH + d];
                acc0[i] += qa * kvv;
                acc1[i] += qb * kvv;
            }
        }
#pragma unroll
        for (int i = 0; i < 8; i++) {
            const int j = l8 + 8 * i;
            if (j < jn) {
                const int jg = j0 + j;
                S[r0 * SPITCH + jg]        = acc0[i] * scale + cross_bias(q0 + r0, jg);
                S[(r0 + 32) * SPITCH + jg] = acc1[i] * scale + cross_bias(q0 + r0 + 32, jg);
            }
        }
    }
    __syncthreads();

    {
        const int row = tid >> 2;
        const int l4  = tid & 3;
        float m = -1e30f;
        for (int j = l4; j < TSEQ; j += 4) m = fmaxf(m, S[row * SPITCH + j]);
        m = fmaxf(m, __shfl_xor_sync(0xffffffffu, m, 1, 4));
        m = fmaxf(m, __shfl_xor_sync(0xffffffffu, m, 2, 4));
        float s = 0.f;
        for (int j = l4; j < TSEQ; j += 4) {
            const float e = __expf(S[row * SPITCH + j] - m);
            S[row * SPITCH + j] = e;
            s += e;
        }
        s += __shfl_xor_sync(0xffffffffu, s, 1, 4);
        s += __shfl_xor_sync(0xffffffffu, s, 2, 4);
        if (l4 == 0) rinv[row] = 1.0f / s;
    }
    __syncthreads();

    float y0[8], y1[8];
#pragma unroll
    for (int i = 0; i < 8; i++) { y0[i] = 0.f; y1[i] = 0.f; }

    for (int j0 = 0; j0 < TSEQ; j0 += 64) {
        const int jn = min(64, TSEQ - j0);
        __syncthreads();
        {
            const int c  = tid >> 2;
            const int d0 = (tid & 3) * 16;
            if (c < jn) {
                const float* src = base + 2 * NC + (size_t)(j0 + c) * NQKV + d0;
                float* dst = kv + c * KPITCH + d0;
#pragma unroll
                for (int q = 0; q < 4; q++)
                    *(float4*)(dst + 4 * q) = *(const float4*)(src + 4 * q);
            }
        }
        __syncthreads();

        for (int j = 0; j < jn; j++) {
            const float p0 = S[r0 * SPITCH + j0 + j];
            const float p1 = S[(r0 + 32) * SPITCH + j0 + j];
#pragma unroll
            for (int i = 0; i < 8; i++) {
                const float vv = kv[j * KPITCH + l8 + 8 * i];
                y0[i] += p0 * vv;
                y1[i] += p1 * vv;
            }
        }
    }

    {
        const float s0 = rinv[r0];
        const float s1 = rinv[r0 + 32];
        const int t0 = q0 + r0;
        const int t1 = q0 + r0 + 32;
        if (t0 < TSEQ) {
            float* dst = g_y + (size_t)(b * TSEQ + t0) * NC + h * HD;
#pragma unroll
            for (int i = 0; i < 8; i++) dst[l8 + 8 * i] = y0[i] * s0;
        }
        if (t1 < TSEQ) {
            float* dst = g_y + (size_t)(b * TSEQ + t1) * NC + h * HD;
#pragma unroll
            for (int i = 0; i < 8; i++) dst[l8 + 8 * i] = y1[i] * s1;
        }
    }
}

// ---------------------------------------------------------------------------
extern "C" void kernel_launch(void* const* d_in, const int* in_sizes, int n_in,
                              void* d_out, int out_size)
{
    const float* x      = (const float*)d_in[0];
    const float* W_attn = (const float*)d_in[1];
    const float* b_attn = (const float*)d_in[2];
    const float* W_proj = (const float*)d_in[3];
    const float* b_proj = (const float*)d_in[4];
    float* out = (float*)d_out;

    cudaFuncSetAttribute(attn_kernel, cudaFuncAttributeMaxDynamicSharedMemorySize,
                         ATTN_SMEM_BYTES);
    cudaFuncSetAttribute(gemm_mma, cudaFuncAttributeMaxDynamicSharedMemorySize,
                         GEMM_SMEM);

    void *pAhi, *pAlo, *pWqHi, *pWqLo, *pWpHi, *pWpLo;
    cudaGetSymbolAddress(&pAhi,  g_a_hi);
    cudaGetSymbolAddress(&pAlo,  g_a_lo);
    cudaGetSymbolAddress(&pWqHi, g_wq_hi);
    cudaGetSymbolAddress(&pWqLo, g_wq_lo);
    cudaGetSymbolAddress(&pWpHi, g_wp_hi);
    cudaGetSymbolAddress(&pWpLo, g_wp_lo);

    const size_t n4 = (size_t)MROWS * NC / 4;
    const int splitBlocks = (int)((n4 + 255) / 256);

    // 1) split x ; transpose-split weights
    split_fp32<<<splitBlocks, 256>>>(x, (__nv_bfloat16*)pAhi, (__nv_bfloat16*)pAlo, n4);
    transpose_split<<<dim3(NQKV / 32, GK / 32), 256>>>(W_attn, (__nv_bfloat16*)pWqHi,
                                                       (__nv_bfloat16*)pWqLo, GK, NQKV);
    transpose_split<<<dim3(NC / 32, GK / 32), 256>>>(W_proj, (__nv_bfloat16*)pWpHi,
                                                     (__nv_bfloat16*)pWpLo, GK, NC);

    // 2) qkv = x @ W_attn + b_attn
    dim3 g1(NQKV / 128, (MROWS + 127) / 128);
    gemm_mma<<<g1, 256, GEMM_SMEM>>>(b_attn, nullptr, MROWS, NQKV, 0);

    // 3) attention
    dim3 ga((TSEQ + QR - 1) / QR, NB * NH);
    attn_kernel<<<ga, 256, ATTN_SMEM_BYTES>>>();

    // 4) split y ; out = y @ W_proj + b_proj
    split_fp32<<<splitBlocks, 256>>>(nullptr, (__nv_bfloat16*)pAhi, (__nv_bfloat16*)pAlo, n4);
    dim3 g2(NC / 128, (MROWS + 127) / 128);
    gemm_mma<<<g2, 256, GEMM_SMEM>>>(b_proj, out, MROWS, NC, 1);
}

// round 4
// speedup vs baseline: 2.2348x; 1.4252x over previous
#include <cuda_runtime.h>
#include <cuda_bf16.h>
#include <cstdint>

// ---------------------------------------------------------------------------
// CrossOnlyAttention  (B=64, T=469, C=1024, H=16, hd=64)
// Round 4: everything on mma.sync bf16 hi/lo split.
//   - GEMMs: 128x128 tile, 2 CTAs/SM (reg-capped)
//   - GEMM1 writes qkv directly as bf16 hi/lo (no fp32 intermediate)
//   - attention: QK^T and P.V on tensor cores, S fp32 in smem, two-pass softmax
//   - attention writes y directly as bf16 hi/lo for GEMM3
// ---------------------------------------------------------------------------

#define TSEQ   469
#define NB     64
#define NC     1024
#define NH     16
#define HD     64
#define MROWS  (NB * TSEQ)   // 30016
#define NQKV   (3 * NC)      // 3072
#define GK     1024

typedef __nv_bfloat16 bf16;

// scratch (__device__ globals: allocation-free rule)
__device__ bf16 g_a_hi[(size_t)MROWS * NC];     // split activations (x, then y)
__device__ bf16 g_a_lo[(size_t)MROWS * NC];
__device__ bf16 g_qkv_hi[(size_t)MROWS * NQKV]; // split qkv
__device__ bf16 g_qkv_lo[(size_t)MROWS * NQKV];
__device__ bf16 g_wq_hi[(size_t)NQKV * GK];
__device__ bf16 g_wq_lo[(size_t)NQKV * GK];
__device__ bf16 g_wp_hi[(size_t)NC * GK];
__device__ bf16 g_wp_lo[(size_t)NC * GK];

// ---------------------------------------------------------------------------
// helpers
// ---------------------------------------------------------------------------
__device__ __forceinline__ uint32_t smem_u32(const void* p) {
    uint32_t a;
    asm("{ .reg .u64 t; cvta.to.shared.u64 t, %1; cvt.u32.u64 %0, t; }" : "=r"(a) : "l"(p));
    return a;
}

#define CP_ASYNC16(dst, src, sz) \
    asm volatile("cp.async.cg.shared.global [%0], [%1], 16, %2;" \
                 :: "r"(dst), "l"(src), "r"(sz) : "memory")
#define CP_COMMIT() asm volatile("cp.async.commit_group;" ::: "memory")
#define CP_WAIT(N)  asm volatile("cp.async.wait_group %0;" :: "n"(N) : "memory")

__device__ __forceinline__ void ldmatrix_x4(uint32_t* r, uint32_t addr) {
    asm volatile("ldmatrix.sync.aligned.m8n8.x4.shared.b16 {%0,%1,%2,%3}, [%4];"
                 : "=r"(r[0]), "=r"(r[1]), "=r"(r[2]), "=r"(r[3]) : "r"(addr));
}
__device__ __forceinline__ void ldmatrix_x2(uint32_t* r, uint32_t addr) {
    asm volatile("ldmatrix.sync.aligned.m8n8.x2.shared.b16 {%0,%1}, [%2];"
                 : "=r"(r[0]), "=r"(r[1]) : "r"(addr));
}
__device__ __forceinline__ void mma_bf16(float* c, const uint32_t* a, const uint32_t* b) {
    asm volatile("mma.sync.aligned.m16n8k16.row.col.f32.bf16.bf16.f32 "
                 "{%0,%1,%2,%3},{%4,%5,%6,%7},{%8,%9},{%0,%1,%2,%3};"
                 : "+f"(c[0]), "+f"(c[1]), "+f"(c[2]), "+f"(c[3])
                 : "r"(a[0]), "r"(a[1]), "r"(a[2]), "r"(a[3]), "r"(b[0]), "r"(b[1]));
}

__device__ __forceinline__ void split2(float v, bf16& h, bf16& l) {
    h = __float2bfloat16(v);
    l = __float2bfloat16(v - __bfloat162float(h));
}

// ---------------------------------------------------------------------------
// conversion kernels
// ---------------------------------------------------------------------------
__global__ void split_fp32(const float* __restrict__ src,
                           bf16* __restrict__ hi, bf16* __restrict__ lo, size_t n4)
{
    size_t i = (size_t)blockIdx.x * blockDim.x + threadIdx.x;
    if (i >= n4) return;
    float4 v = ((const float4*)src)[i];
    float vv[4] = {v.x, v.y, v.z, v.w};
    __align__(8) bf16 h[4], l[4];
#pragma unroll
    for (int q = 0; q < 4; q++) split2(vv[q], h[q], l[q]);
    ((uint2*)hi)[i] = *(uint2*)h;
    ((uint2*)lo)[i] = *(uint2*)l;
}

__global__ void transpose_split(const float* __restrict__ src,
                                bf16* __restrict__ dhi, bf16* __restrict__ dlo,
                                int K, int N)
{
    __shared__ float tile[32][33];
    const int n0 = blockIdx.x * 32, k0 = blockIdx.y * 32;
    const int tx = threadIdx.x & 31, ty0 = threadIdx.x >> 5;
#pragma unroll
    for (int i = 0; i < 4; i++) {
        int ty = ty0 + i * 8;
        tile[ty][tx] = src[(size_t)(k0 + ty) * N + n0 + tx];
    }
    __syncthreads();
#pragma unroll
    for (int i = 0; i < 4; i++) {
        int ty = ty0 + i * 8;
        float v = tile[tx][ty];
        bf16 h, l; split2(v, h, l);
        dhi[(size_t)(n0 + ty) * K + k0 + tx] = h;
        dlo[(size_t)(n0 + ty) * K + k0 + tx] = l;
    }
}

// ---------------------------------------------------------------------------
// mma.sync GEMM: 128x128 CTA tile, BK=32, 8 warps 2x4, 2 CTAs/SM
// ---------------------------------------------------------------------------
#define BK        32
#define NCHUNK    (GK / BK)
#define LDT       40
#define TILE_BYTES (128 * LDT * 2)
#define STAGE_BYTES (4 * TILE_BYTES)
#define GEMM_SMEM  (2 * STAGE_BYTES)         // 81920

__device__ __forceinline__ void tile_cp(const bf16* __restrict__ src,
                                        int row0, int maxrow, int k0,
                                        uint32_t sdst, int tid)
{
#pragma unroll
    for (int i = 0; i < 2; i++) {
        const int idx = tid + i * 256;
        const int r = idx >> 2, seg = idx & 3;
        const int gr = row0 + r;
        const int ok = (gr < maxrow) ? 16 : 0;
        const bf16* gp = src + (size_t)min(gr, maxrow - 1) * GK + k0 + seg * 8;
        CP_ASYNC16(sdst + r * (LDT * 2) + seg * 16, gp, ok);
    }
}

__global__ void __launch_bounds__(256, 2)
gemm_mma(const bf16* __restrict__ Ah, const bf16* __restrict__ Al,
         const bf16* __restrict__ Bh, const bf16* __restrict__ Bl,
         const float* __restrict__ bias,
         float* __restrict__ outF, bf16* __restrict__ outHi, bf16* __restrict__ outLo,
         int M, int N, int splitOut)
{
    extern __shared__ char smem[];
    const uint32_t sbase = smem_u32(smem);
    const int tid = threadIdx.x, wid = tid >> 5, lane = tid & 31;
    const int warpM = wid >> 2, warpN = wid & 3;
    const int n0 = blockIdx.x * 128, m0 = blockIdx.y * 128;

    float acc[4][4][4];
#pragma unroll
    for (int i = 0; i < 4; i++)
#pragma unroll
        for (int j = 0; j < 4; j++)
#pragma unroll
            for (int q = 0; q < 4; q++) acc[i][j][q] = 0.f;

    const uint32_t aRowB = (uint32_t)(warpM * 64 + (lane & 15)) * (LDT * 2);
    const uint32_t aColB = (uint32_t)((lane >> 4) * 8) * 2;
    const uint32_t bRowB = (uint32_t)(warpN * 32 + (lane & 7)) * (LDT * 2);
    const uint32_t bColB = (uint32_t)(((lane >> 3) & 1) * 8) * 2;

    tile_cp(Ah, m0, M, 0, sbase + 0 * TILE_BYTES, tid);
    tile_cp(Al, m0, M, 0, sbase + 1 * TILE_BYTES, tid);
    tile_cp(Bh, n0, N, 0, sbase + 2 * TILE_BYTES, tid);
    tile_cp(Bl, n0, N, 0, sbase + 3 * TILE_BYTES, tid);
    CP_COMMIT();

    for (int c = 0; c < NCHUNK; c++) {
        if (c + 1 < NCHUNK) {
            const uint32_t st = sbase + ((c + 1) & 1) * STAGE_BYTES;
            const int k0 = (c + 1) * BK;
            tile_cp(Ah, m0, M, k0, st + 0 * TILE_BYTES, tid);
            tile_cp(Al, m0, M, k0, st + 1 * TILE_BYTES, tid);
            tile_cp(Bh, n0, N, k0, st + 2 * TILE_BYTES, tid);
            tile_cp(Bl, n0, N, k0, st + 3 * TILE_BYTES, tid);
            CP_COMMIT();
            CP_WAIT(1);
        } else {
            CP_WAIT(0);
        }
        __syncthreads();

        const uint32_t st = sbase + (c & 1) * STAGE_BYTES;
        const uint32_t sAh = st, sAl = st + TILE_BYTES;
        const uint32_t sBh = st + 2 * TILE_BYTES, sBl = st + 3 * TILE_BYTES;

#pragma unroll
        for (int ks = 0; ks < 2; ks++) {
            const uint32_t kOffA = aColB + ks * 32;
            const uint32_t kOffB = bColB + ks * 32;

            uint32_t bh[4][2], bl[4][2];
#pragma unroll
            for (int ni = 0; ni < 4; ni++) {
                const uint32_t bo = bRowB + (uint32_t)(ni * 8) * (LDT * 2) + kOffB;
                ldmatrix_x2(bh[ni], sBh + bo);
                ldmatrix_x2(bl[ni], sBl + bo);
            }
#pragma unroll
            for (int mi = 0; mi < 4; mi++) {
                const uint32_t ao = aRowB + (uint32_t)(mi * 16) * (LDT * 2) + kOffA;
                uint32_t ah[4], al[4];
                ldmatrix_x4(ah, sAh + ao);
                ldmatrix_x4(al, sAl + ao);
#pragma unroll
                for (int ni = 0; ni < 4; ni++) {
                    mma_bf16(acc[mi][ni], ah, bh[ni]);
                    mma_bf16(acc[mi][ni], ah, bl[ni]);
                    mma_bf16(acc[mi][ni], al, bh[ni]);
                }
            }
        }
        __syncthreads();
    }

    const int cBase = n0 + warpN * 32 + (lane & 3) * 2;
    const int rBase = m0 + warpM * 64 + (lane >> 2);
#pragma unroll
    for (int mi = 0; mi < 4; mi++) {
#pragma unroll
        for (int ni = 0; ni < 4; ni++) {
            const int col = cBase + ni * 8;
            const float b0 = bias[col], b1 = bias[col + 1];
#pragma unroll
            for (int half = 0; half < 2; half++) {
                const int r = rBase + mi * 16 + half * 8;
                if (r >= M) continue;
                const float v0 = acc[mi][ni][half * 2 + 0] + b0;
                const float v1 = acc[mi][ni][half * 2 + 1] + b1;
                const size_t o = (size_t)r * N + col;
                if (splitOut) {
                    bf16 h0, l0, h1, l1;
                    split2(v0, h0, l0); split2(v1, h1, l1);
                    __nv_bfloat162 hh; hh.x = h0; hh.y = h1;
                    __nv_bfloat162 ll; ll.x = l0; ll.y = l1;
                    *(__nv_bfloat162*)(outHi + o) = hh;
                    *(__nv_bfloat162*)(outLo + o) = ll;
                } else {
                    *(float2*)(outF + o) = make_float2(v0, v1);
                }
            }
        }
    }
}

// ---------------------------------------------------------------------------
// attention: tensor-core QK^T and P.V, S fp32 in smem, per (b,h,64 q-rows)
// ---------------------------------------------------------------------------
#define AQR    64
#define ASP    472                 // S fp32 pitch (elems)
#define APITCH 72                  // bf16 tile pitch (elems) -> 144B rows
#define NKB    8                   // ceil(469/64)

// smem byte offsets
#define OFF_S    0
#define OFF_QH   (64 * ASP * 4)                    // 120832
#define OFF_QL   (OFF_QH + 64 * APITCH * 2)        // +9216
#define OFF_KV   (OFF_QL + 64 * APITCH * 2)        // 139264; 2 bufs x (hi+lo)
#define KVBUF    (2 * 64 * APITCH * 2)             // 18432 per buffer
#define OFF_PH   (OFF_KV + 2 * KVBUF)              // 176128
#define OFF_PL   (OFF_PH + 64 * APITCH * 2)
#define OFF_RINV (OFF_PL + 64 * APITCH * 2)        // 194560
#define ATTN_SMEM (OFF_RINV + 64 * 4)              // 194816

__device__ __forceinline__ float cross_bias(int i, int j)
{
    if (i == 0 || j == 0) return 1.0f;
    return ((i <= 234) != (j <= 234)) ? 1.0f : 0.0f;
}

__global__ void __launch_bounds__(256, 1)
attn_mma()
{
    extern __shared__ char smem[];
    const uint32_t sbase = smem_u32(smem);
    float* S    = (float*)(smem + OFF_S);
    float* rinv = (float*)(smem + OFF_RINV);

    const int tid = threadIdx.x, wid = tid >> 5, lane = tid & 31;
    const int warpM = wid >> 2, warpN = wid & 3;
    const int bh = blockIdx.y;
    const int b  = bh >> 4, h = bh & 15;
    const int q0 = blockIdx.x * AQR;

    const size_t rowb = (size_t)b * TSEQ * NQKV + h * HD;
    const bf16* qhg = g_qkv_hi + rowb;
    const bf16* qlg = g_qkv_lo + rowb;
    const bf16* khg = qhg + NC;
    const bf16* klg = qlg + NC;
    const bf16* vhg = qhg + 2 * NC;
    const bf16* vlg = qlg + 2 * NC;

    // ---- stage Q tile (cp.async, zero-fill OOB rows) ----
    {
#pragma unroll
        for (int i = 0; i < 2; i++) {
            const int idx = tid + i * 256;
            const int r = idx >> 3, seg = idx & 7;
            const int ok = (q0 + r < TSEQ) ? 16 : 0;
            const bf16* s1 = qhg + (size_t)(q0 + r) * NQKV + seg * 8;
            const bf16* s2 = qlg + (size_t)(q0 + r) * NQKV + seg * 8;
            CP_ASYNC16(sbase + OFF_QH + r * 144 + seg * 16, s1, ok);
            CP_ASYNC16(sbase + OFF_QL + r * 144 + seg * 16, s2, ok);
        }
    }
    // ---- stage K block 0 ----
#pragma unroll
    for (int i = 0; i < 2; i++) {
        const int idx = tid + i * 256;
        const int r = idx >> 3, seg = idx & 7;
        const int ok = (r < TSEQ) ? 16 : 0;
        CP_ASYNC16(sbase + OFF_KV + r * 144 + seg * 16,
                   khg + (size_t)r * NQKV + seg * 8, ok);
        CP_ASYNC16(sbase + OFF_KV + 9216 + r * 144 + seg * 16,
                   klg + (size_t)r * NQKV + seg * 8, ok);
    }
    CP_COMMIT();

    const uint32_t aRow = (uint32_t)(warpM * 32 + (lane & 15)) * 144;
    const uint32_t aCol = (uint32_t)((lane >> 4) * 8) * 2;
    const uint32_t bRow = (uint32_t)(warpN * 16 + (lane & 7)) * 144;
    const uint32_t bCol = (uint32_t)(((lane >> 3) & 1) * 8) * 2;

    // ================= phase 1: S = scale * Q K^T + bias =================
    for (int c = 0; c < NKB; c++) {
        if (c + 1 < NKB) {
            const uint32_t kb = sbase + OFF_KV + ((c + 1) & 1) * KVBUF;
            const int j0n = (c + 1) * 64;
#pragma unroll
            for (int i = 0; i < 2; i++) {
                const int idx = tid + i * 256;
                const int r = idx >> 3, seg = idx & 7;
                const int ok = (j0n + r < TSEQ) ? 16 : 0;
                CP_ASYNC16(kb + r * 144 + seg * 16,
                           khg + (size_t)(j0n + r) * NQKV + seg * 8, ok);
                CP_ASYNC16(kb + 9216 + r * 144 + seg * 16,
                           klg + (size_t)(j0n + r) * NQKV + seg * 8, ok);
            }
            CP_COMMIT();
            CP_WAIT(1);
        } else {
            CP_WAIT(0);
        }
        __syncthreads();

        const uint32_t kvh = sbase + OFF_KV + (c & 1) * KVBUF;
        const uint32_t kvl = kvh + 9216;

        float sc[2][2][4];
#pragma unroll
        for (int mi = 0; mi < 2; mi++)
#pragma unroll
            for (int ni = 0; ni < 2; ni++)
#pragma unroll
                for (int q = 0; q < 4; q++) sc[mi][ni][q] = 0.f;

#pragma unroll
        for (int ks = 0; ks < 4; ks++) {
            uint32_t bhf[2][2], blf[2][2];
#pragma unroll
            for (int ni = 0; ni < 2; ni++) {
                const uint32_t bo = bRow + (uint32_t)(ni * 8) * 144 + bCol + ks * 32;
                ldmatrix_x2(bhf[ni], kvh + bo);
                ldmatrix_x2(blf[ni], kvl + bo);
            }
#pragma unroll
            for (int mi = 0; mi < 2; mi++) {
                const uint32_t ao = aRow + (uint32_t)(mi * 16) * 144 + aCol + ks * 32;
                uint32_t ah[4], al[4];
                ldmatrix_x4(ah, sbase + OFF_QH + ao);
                ldmatrix_x4(al, sbase + OFF_QL + ao);
#pragma unroll
                for (int ni = 0; ni < 2; ni++) {
                    mma_bf16(sc[mi][ni], ah, bhf[ni]);
                    mma_bf16(sc[mi][ni], ah, blf[ni]);
                    mma_bf16(sc[mi][ni], al, bhf[ni]);
                }
            }
        }

        const int j0 = c * 64;
        const int jn = min(64, TSEQ - j0);
#pragma unroll
        for (int mi = 0; mi < 2; mi++) {
#pragma unroll
            for (int ni = 0; ni < 2; ni++) {
                const int c0 = warpN * 16 + ni * 8 + (lane & 3) * 2;
#pragma unroll
                for (int half = 0; half < 2; half++) {
                    const int r = warpM * 32 + mi * 16 + (lane >> 2) + half * 8;
                    const int qi = q0 + r;
                    if (c0 < jn)
                        S[r * ASP + j0 + c0] =
                            sc[mi][ni][half * 2] * 0.125f + cross_bias(qi, j0 + c0);
                    if (c0 + 1 < jn)
                        S[r * ASP + j0 + c0 + 1] =
                            sc[mi][ni][half * 2 + 1] * 0.125f + cross_bias(qi, j0 + c0 + 1);
                }
            }
        }
        __syncthreads();
    }

    // ================= phase 2: softmax =================
    {
        const int row = tid >> 2, l4 = tid & 3;
        float m = -1e30f;
        for (int j = l4; j < TSEQ; j += 4) m = fmaxf(m, S[row * ASP + j]);
        m = fmaxf(m, __shfl_xor_sync(0xffffffffu, m, 1, 4));
        m = fmaxf(m, __shfl_xor_sync(0xffffffffu, m, 2, 4));
        float s = 0.f;
        for (int j = l4; j < TSEQ; j += 4) {
            const float e = __expf(S[row * ASP + j] - m);
            S[row * ASP + j] = e;
            s += e;
        }
        s += __shfl_xor_sync(0xffffffffu, s, 1, 4);
        s += __shfl_xor_sync(0xffffffffu, s, 2, 4);
        if (l4 == 0) rinv[row] = 1.0f / s;
    }

    // ================= phase 3: Y = P V =================
    float yc[2][2][4];
#pragma unroll
    for (int mi = 0; mi < 2; mi++)
#pragma unroll
        for (int ni = 0; ni < 2; ni++)
#pragma unroll
            for (int q = 0; q < 4; q++) yc[mi][ni][q] = 0.f;

    bf16* phS = (bf16*)(smem + OFF_PH);
    bf16* plS = (bf16*)(smem + OFF_PL);
    bf16* vtH = (bf16*)(smem + OFF_KV);          // reuse kv buffer 0: V^T hi
    bf16* vtL = (bf16*)(smem + OFF_KV + 9216);   // V^T lo

    for (int c = 0; c < NKB; c++) {
        const int j0 = c * 64;
        __syncthreads();   // previous mma done reading vt/p

        // stage V^T (transpose during store) -- thread: key r, 16 d values
        {
            const int r = tid >> 2, d0 = (tid & 3) * 16;
            const bool ok = (j0 + r) < TSEQ;
            uint4 zero = make_uint4(0, 0, 0, 0);
            const bf16* sh = vhg + (size_t)(j0 + r) * NQKV + d0;
            const bf16* sl = vlg + (size_t)(j0 + r) * NQKV + d0;
            uint4 h0 = ok ? *(const uint4*)(sh) : zero;
            uint4 h1 = ok ? *(const uint4*)(sh + 8) : zero;
            uint4 l0 = ok ? *(const uint4*)(sl) : zero;
            uint4 l1 = ok ? *(const uint4*)(sl + 8) : zero;
            const ushort* ph0 = (const ushort*)&h0;
            const ushort* ph1 = (const ushort*)&h1;
            const ushort* pl0 = (const ushort*)&l0;
            const ushort* pl1 = (const ushort*)&l1;
#pragma unroll
            for (int q = 0; q < 8; q++) {
                ((ushort*)vtH)[(d0 + q) * APITCH + r]     = ph0[q];
                ((ushort*)vtH)[(d0 + 8 + q) * APITCH + r] = ph1[q];
                ((ushort*)vtL)[(d0 + q) * APITCH + r]     = pl0[q];
                ((ushort*)vtL)[(d0 + 8 + q) * APITCH + r] = pl1[q];
            }
        }
        // convert P block to bf16 hi/lo with rinv folded in
        {
            const int row = tid >> 2, jj0 = (tid & 3) * 16;
            const float ri = rinv[row];
#pragma unroll
            for (int q = 0; q < 16; q++) {
                const int j = jj0 + q;
                const int jg = j0 + j;
                float p = (jg < TSEQ) ? S[row * ASP + jg] * ri : 0.f;
                bf16 hh, ll; split2(p, hh, ll);
                phS[row * APITCH + j] = hh;
                plS[row * APITCH + j] = ll;
            }
        }
        __syncthreads();

#pragma unroll
        for (int ks = 0; ks < 4; ks++) {
            uint32_t bhf[2][2], blf[2][2];
#pragma unroll
            for (int ni = 0; ni < 2; ni++) {
                const uint32_t bo = bRow + (uint32_t)(ni * 8) * 144 + bCol + ks * 32;
                ldmatrix_x2(bhf[ni], sbase + OFF_KV + bo);
                ldmatrix_x2(blf[ni], sbase + OFF_KV + 9216 + bo);
            }
#pragma unroll
            for (int mi = 0; mi < 2; mi++) {
                const uint32_t ao = aRow + (uint32_t)(mi * 16) * 144 + aCol + ks * 32;
                uint32_t ah[4], al[4];
                ldmatrix_x4(ah, sbase + OFF_PH + ao);
                ldmatrix_x4(al, sbase + OFF_PL + ao);
#pragma unroll
                for (int ni = 0; ni < 2; ni++) {
                    mma_bf16(yc[mi][ni], ah, bhf[ni]);
                    mma_bf16(yc[mi][ni], ah, blf[ni]);
                    mma_bf16(yc[mi][ni], al, bhf[ni]);
                }
            }
        }
    }

    // write y as bf16 hi/lo into g_a_hi/lo
#pragma unroll
    for (int mi = 0; mi < 2; mi++) {
#pragma unroll
        for (int ni = 0; ni < 2; ni++) {
            const int d = warpN * 16 + ni * 8 + (lane & 3) * 2;
#pragma unroll
            for (int half = 0; half < 2; half++) {
                const int r = warpM * 32 + mi * 16 + (lane >> 2) + half * 8;
                const int t = q0 + r;
                if (t >= TSEQ) continue;
                const size_t o = ((size_t)b * TSEQ + t) * NC + h * HD + d;
                bf16 h0, l0, h1, l1;
                split2(yc[mi][ni][half * 2],     h0, l0);
                split2(yc[mi][ni][half * 2 + 1], h1, l1);
                __nv_bfloat162 hh; hh.x = h0; hh.y = h1;
                __nv_bfloat162 ll; ll.x = l0; ll.y = l1;
                *(__nv_bfloat162*)(g_a_hi + o) = hh;
                *(__nv_bfloat162*)(g_a_lo + o) = ll;
            }
        }
    }
}

// ---------------------------------------------------------------------------
extern "C" void kernel_launch(void* const* d_in, const int* in_sizes, int n_in,
                              void* d_out, int out_size)
{
    const float* x      = (const float*)d_in[0];
    const float* W_attn = (const float*)d_in[1];
    const float* b_attn = (const float*)d_in[2];
    const float* W_proj = (const float*)d_in[3];
    const float* b_proj = (const float*)d_in[4];
    float* out = (float*)d_out;

    cudaFuncSetAttribute(gemm_mma, cudaFuncAttributeMaxDynamicSharedMemorySize, GEMM_SMEM);
    cudaFuncSetAttribute(attn_mma, cudaFuncAttributeMaxDynamicSharedMemorySize, ATTN_SMEM);

    void *pAhi, *pAlo, *pQhi, *pQlo, *pWqHi, *pWqLo, *pWpHi, *pWpLo;
    cudaGetSymbolAddress(&pAhi,  g_a_hi);
    cudaGetSymbolAddress(&pAlo,  g_a_lo);
    cudaGetSymbolAddress(&pQhi,  g_qkv_hi);
    cudaGetSymbolAddress(&pQlo,  g_qkv_lo);
    cudaGetSymbolAddress(&pWqHi, g_wq_hi);
    cudaGetSymbolAddress(&pWqLo, g_wq_lo);
    cudaGetSymbolAddress(&pWpHi, g_wp_hi);
    cudaGetSymbolAddress(&pWpLo, g_wp_lo);

    const size_t n4 = (size_t)MROWS * NC / 4;
    split_fp32<<<(int)((n4 + 255) / 256), 256>>>(x, (bf16*)pAhi, (bf16*)pAlo, n4);
    transpose_split<<<dim3(NQKV / 32, GK / 32), 256>>>(W_attn, (bf16*)pWqHi, (bf16*)pWqLo, GK, NQKV);
    transpose_split<<<dim3(NC / 32, GK / 32), 256>>>(W_proj, (bf16*)pWpHi, (bf16*)pWpLo, GK, NC);

    // qkv (split output)
    dim3 g1(NQKV / 128, (MROWS + 127) / 128);
    gemm_mma<<<g1, 256, GEMM_SMEM>>>((bf16*)pAhi, (bf16*)pAlo, (bf16*)pWqHi, (bf16*)pWqLo,
                                     b_attn, nullptr, (bf16*)pQhi, (bf16*)pQlo,
                                     MROWS, NQKV, 1);

    // attention (writes y split into g_a_hi/lo)
    dim3 ga((TSEQ + AQR - 1) / AQR, NB * NH);
    attn_mma<<<ga, 256, ATTN_SMEM>>>();

    // out = y @ W_proj + b_proj (fp32 output)
    dim3 g2(NC / 128, (MROWS + 127) / 128);
    gemm_mma<<<g2, 256, GEMM_SMEM>>>((bf16*)pAhi, (bf16*)pAlo, (bf16*)pWpHi, (bf16*)pWpLo,
                                     b_proj, out, nullptr, nullptr,
                                     MROWS, NC, 0);
}

// round 5
// speedup vs baseline: 2.5483x; 1.1403x over previous
#include <cuda_runtime.h>
#include <cuda_bf16.h>
#include <cstdint>

// ---------------------------------------------------------------------------
// CrossOnlyAttention  (B=64, T=469, C=1024, H=16, hd=64)
// Round 5: attention phase-3 rework — V stays row-major (cp.async double
// buffer) and is fed to mma via ldmatrix.x4.trans; scalar V transpose gone.
// B-operand ldmatrix widened x2->x4 in GEMM and attention phase 1.
// ---------------------------------------------------------------------------

#define TSEQ   469
#define NB     64
#define NC     1024
#define NH     16
#define HD     64
#define MROWS  (NB * TSEQ)   // 30016
#define NQKV   (3 * NC)      // 3072
#define GK     1024

typedef __nv_bfloat16 bf16;

// scratch (__device__ globals: allocation-free rule)
__device__ bf16 g_a_hi[(size_t)MROWS * NC];
__device__ bf16 g_a_lo[(size_t)MROWS * NC];
__device__ bf16 g_qkv_hi[(size_t)MROWS * NQKV];
__device__ bf16 g_qkv_lo[(size_t)MROWS * NQKV];
__device__ bf16 g_wq_hi[(size_t)NQKV * GK];
__device__ bf16 g_wq_lo[(size_t)NQKV * GK];
__device__ bf16 g_wp_hi[(size_t)NC * GK];
__device__ bf16 g_wp_lo[(size_t)NC * GK];

// ---------------------------------------------------------------------------
// helpers
// ---------------------------------------------------------------------------
__device__ __forceinline__ uint32_t smem_u32(const void* p) {
    uint32_t a;
    asm("{ .reg .u64 t; cvta.to.shared.u64 t, %1; cvt.u32.u64 %0, t; }" : "=r"(a) : "l"(p));
    return a;
}

#define CP_ASYNC16(dst, src, sz) \
    asm volatile("cp.async.cg.shared.global [%0], [%1], 16, %2;" \
                 :: "r"(dst), "l"(src), "r"(sz) : "memory")
#define CP_COMMIT() asm volatile("cp.async.commit_group;" ::: "memory")
#define CP_WAIT(N)  asm volatile("cp.async.wait_group %0;" :: "n"(N) : "memory")

__device__ __forceinline__ void ldmatrix_x4(uint32_t* r, uint32_t addr) {
    asm volatile("ldmatrix.sync.aligned.m8n8.x4.shared.b16 {%0,%1,%2,%3}, [%4];"
                 : "=r"(r[0]), "=r"(r[1]), "=r"(r[2]), "=r"(r[3]) : "r"(addr));
}
__device__ __forceinline__ void ldmatrix_x4_trans(uint32_t* r, uint32_t addr) {
    asm volatile("ldmatrix.sync.aligned.m8n8.x4.trans.shared.b16 {%0,%1,%2,%3}, [%4];"
                 : "=r"(r[0]), "=r"(r[1]), "=r"(r[2]), "=r"(r[3]) : "r"(addr));
}
__device__ __forceinline__ void mma_bf16(float* c, const uint32_t* a, const uint32_t* b) {
    asm volatile("mma.sync.aligned.m16n8k16.row.col.f32.bf16.bf16.f32 "
                 "{%0,%1,%2,%3},{%4,%5,%6,%7},{%8,%9},{%0,%1,%2,%3};"
                 : "+f"(c[0]), "+f"(c[1]), "+f"(c[2]), "+f"(c[3])
                 : "r"(a[0]), "r"(a[1]), "r"(a[2]), "r"(a[3]), "r"(b[0]), "r"(b[1]));
}

__device__ __forceinline__ void split2(float v, bf16& h, bf16& l) {
    h = __float2bfloat16(v);
    l = __float2bfloat16(v - __bfloat162float(h));
}

// ---------------------------------------------------------------------------
// conversion kernels
// ---------------------------------------------------------------------------
__global__ void split_fp32(const float* __restrict__ src,
                           bf16* __restrict__ hi, bf16* __restrict__ lo, size_t n4)
{
    size_t i = (size_t)blockIdx.x * blockDim.x + threadIdx.x;
    if (i >= n4) return;
    float4 v = ((const float4*)src)[i];
    float vv[4] = {v.x, v.y, v.z, v.w};
    __align__(8) bf16 h[4], l[4];
#pragma unroll
    for (int q = 0; q < 4; q++) split2(vv[q], h[q], l[q]);
    ((uint2*)hi)[i] = *(uint2*)h;
    ((uint2*)lo)[i] = *(uint2*)l;
}

__global__ void transpose_split(const float* __restrict__ src,
                                bf16* __restrict__ dhi, bf16* __restrict__ dlo,
                                int K, int N)
{
    __shared__ float tile[32][33];
    const int n0 = blockIdx.x * 32, k0 = blockIdx.y * 32;
    const int tx = threadIdx.x & 31, ty0 = threadIdx.x >> 5;
#pragma unroll
    for (int i = 0; i < 4; i++) {
        int ty = ty0 + i * 8;
        tile[ty][tx] = src[(size_t)(k0 + ty) * N + n0 + tx];
    }
    __syncthreads();
#pragma unroll
    for (int i = 0; i < 4; i++) {
        int ty = ty0 + i * 8;
        float v = tile[tx][ty];
        bf16 h, l; split2(v, h, l);
        dhi[(size_t)(n0 + ty) * K + k0 + tx] = h;
        dlo[(size_t)(n0 + ty) * K + k0 + tx] = l;
    }
}

// ---------------------------------------------------------------------------
// mma.sync GEMM: 128x128 CTA tile, BK=32, 8 warps 2x4, 2 CTAs/SM
// ---------------------------------------------------------------------------
#define BK        32
#define NCHUNK    (GK / BK)
#define LDT       40
#define TILE_BYTES (128 * LDT * 2)
#define STAGE_BYTES (4 * TILE_BYTES)
#define GEMM_SMEM  (2 * STAGE_BYTES)         // 81920

__device__ __forceinline__ void tile_cp(const bf16* __restrict__ src,
                                        int row0, int maxrow, int k0,
                                        uint32_t sdst, int tid)
{
#pragma unroll
    for (int i = 0; i < 2; i++) {
        const int idx = tid + i * 256;
        const int r = idx >> 2, seg = idx & 3;
        const int gr = row0 + r;
        const int ok = (gr < maxrow) ? 16 : 0;
        const bf16* gp = src + (size_t)min(gr, maxrow - 1) * GK + k0 + seg * 8;
        CP_ASYNC16(sdst + r * (LDT * 2) + seg * 16, gp, ok);
    }
}

__global__ void __launch_bounds__(256, 2)
gemm_mma(const bf16* __restrict__ Ah, const bf16* __restrict__ Al,
         const bf16* __restrict__ Bh, const bf16* __restrict__ Bl,
         const float* __restrict__ bias,
         float* __restrict__ outF, bf16* __restrict__ outHi, bf16* __restrict__ outLo,
         int M, int N, int splitOut)
{
    extern __shared__ char smem[];
    const uint32_t sbase = smem_u32(smem);
    const int tid = threadIdx.x, wid = tid >> 5, lane = tid & 31;
    const int warpM = wid >> 2, warpN = wid & 3;
    const int n0 = blockIdx.x * 128, m0 = blockIdx.y * 128;

    float acc[4][4][4];
#pragma unroll
    for (int i = 0; i < 4; i++)
#pragma unroll
        for (int j = 0; j < 4; j++)
#pragma unroll
            for (int q = 0; q < 4; q++) acc[i][j][q] = 0.f;

    const uint32_t aRowB = (uint32_t)(warpM * 64 + (lane & 15)) * (LDT * 2);
    const uint32_t aColB = (uint32_t)((lane >> 4) * 8) * 2;
    // x4-merged B: lanes 0-7 -> n rows +0-7 (k half 0), 8-15 -> same rows k half 1,
    //              16-23 -> n rows +8-15 k half 0, 24-31 -> k half 1
    const uint32_t bRow4 = (uint32_t)(warpN * 32 + (lane & 7) + ((lane >> 4) << 3)) * (LDT * 2);
    const uint32_t bColB = (uint32_t)(((lane >> 3) & 1) * 8) * 2;

    tile_cp(Ah, m0, M, 0, sbase + 0 * TILE_BYTES, tid);
    tile_cp(Al, m0, M, 0, sbase + 1 * TILE_BYTES, tid);
    tile_cp(Bh, n0, N, 0, sbase + 2 * TILE_BYTES, tid);
    tile_cp(Bl, n0, N, 0, sbase + 3 * TILE_BYTES, tid);
    CP_COMMIT();

    for (int c = 0; c < NCHUNK; c++) {
        if (c + 1 < NCHUNK) {
            const uint32_t st = sbase + ((c + 1) & 1) * STAGE_BYTES;
            const int k0 = (c + 1) * BK;
            tile_cp(Ah, m0, M, k0, st + 0 * TILE_BYTES, tid);
            tile_cp(Al, m0, M, k0, st + 1 * TILE_BYTES, tid);
            tile_cp(Bh, n0, N, k0, st + 2 * TILE_BYTES, tid);
            tile_cp(Bl, n0, N, k0, st + 3 * TILE_BYTES, tid);
            CP_COMMIT();
            CP_WAIT(1);
        } else {
            CP_WAIT(0);
        }
        __syncthreads();

        const uint32_t st = sbase + (c & 1) * STAGE_BYTES;
        const uint32_t sAh = st, sAl = st + TILE_BYTES;
        const uint32_t sBh = st + 2 * TILE_BYTES, sBl = st + 3 * TILE_BYTES;

#pragma unroll
        for (int ks = 0; ks < 2; ks++) {
            const uint32_t kOffA = aColB + ks * 32;
            const uint32_t kOffB = bColB + ks * 32;

            uint32_t bh4[2][4], bl4[2][4];
#pragma unroll
            for (int np = 0; np < 2; np++) {
                const uint32_t bo = bRow4 + (uint32_t)(np * 16) * (LDT * 2) + kOffB;
                ldmatrix_x4(bh4[np], sBh + bo);
                ldmatrix_x4(bl4[np], sBl + bo);
            }
#pragma unroll
            for (int mi = 0; mi < 4; mi++) {
                const uint32_t ao = aRowB + (uint32_t)(mi * 16) * (LDT * 2) + kOffA;
                uint32_t ah[4], al[4];
                ldmatrix_x4(ah, sAh + ao);
                ldmatrix_x4(al, sAl + ao);
#pragma unroll
                for (int ni = 0; ni < 4; ni++) {
                    const uint32_t* pbh = &bh4[ni >> 1][(ni & 1) * 2];
                    const uint32_t* pbl = &bl4[ni >> 1][(ni & 1) * 2];
                    mma_bf16(acc[mi][ni], ah, pbh);
                    mma_bf16(acc[mi][ni], ah, pbl);
                    mma_bf16(acc[mi][ni], al, pbh);
                }
            }
        }
        __syncthreads();
    }

    const int cBase = n0 + warpN * 32 + (lane & 3) * 2;
    const int rBase = m0 + warpM * 64 + (lane >> 2);
#pragma unroll
    for (int mi = 0; mi < 4; mi++) {
#pragma unroll
        for (int ni = 0; ni < 4; ni++) {
            const int col = cBase + ni * 8;
            const float b0 = bias[col], b1 = bias[col + 1];
#pragma unroll
            for (int half = 0; half < 2; half++) {
                const int r = rBase + mi * 16 + half * 8;
                if (r >= M) continue;
                const float v0 = acc[mi][ni][half * 2 + 0] + b0;
                const float v1 = acc[mi][ni][half * 2 + 1] + b1;
                const size_t o = (size_t)r * N + col;
                if (splitOut) {
                    bf16 h0, l0, h1, l1;
                    split2(v0, h0, l0); split2(v1, h1, l1);
                    __nv_bfloat162 hh; hh.x = h0; hh.y = h1;
                    __nv_bfloat162 ll; ll.x = l0; ll.y = l1;
                    *(__nv_bfloat162*)(outHi + o) = hh;
                    *(__nv_bfloat162*)(outLo + o) = ll;
                } else {
                    *(float2*)(outF + o) = make_float2(v0, v1);
                }
            }
        }
    }
}

// ---------------------------------------------------------------------------
// attention
// ---------------------------------------------------------------------------
#define AQR    64
#define ASP    472
#define APITCH 72                  // 144B rows
#define NKB    8

#define OFF_S    0
#define OFF_QH   (64 * ASP * 4)
#define OFF_QL   (OFF_QH + 64 * APITCH * 2)
#define OFF_KV   (OFF_QL + 64 * APITCH * 2)
#define KVBUF    (2 * 64 * APITCH * 2)             // hi at +0, lo at +9216
#define OFF_PH   (OFF_KV + 2 * KVBUF)
#define OFF_PL   (OFF_PH + 64 * APITCH * 2)
#define OFF_RINV (OFF_PL + 64 * APITCH * 2)
#define ATTN_SMEM (OFF_RINV + 64 * 4)              // 194816

__device__ __forceinline__ float cross_bias(int i, int j)
{
    if (i == 0 || j == 0) return 1.0f;
    return ((i <= 234) != (j <= 234)) ? 1.0f : 0.0f;
}

__global__ void __launch_bounds__(256, 1)
attn_mma()
{
    extern __shared__ char smem[];
    const uint32_t sbase = smem_u32(smem);
    float* S    = (float*)(smem + OFF_S);
    float* rinv = (float*)(smem + OFF_RINV);

    const int tid = threadIdx.x, wid = tid >> 5, lane = tid & 31;
    const int warpM = wid >> 2, warpN = wid & 3;
    const int bh = blockIdx.y;
    const int b  = bh >> 4, h = bh & 15;
    const int q0 = blockIdx.x * AQR;

    const size_t rowb = (size_t)b * TSEQ * NQKV + h * HD;
    const bf16* qhg = g_qkv_hi + rowb;
    const bf16* qlg = g_qkv_lo + rowb;
    const bf16* khg = qhg + NC;
    const bf16* klg = qlg + NC;
    const bf16* vhg = qhg + 2 * NC;
    const bf16* vlg = qlg + 2 * NC;

    // ---- stage Q tile ----
#pragma unroll
    for (int i = 0; i < 2; i++) {
        const int idx = tid + i * 256;
        const int r = idx >> 3, seg = idx & 7;
        const int ok = (q0 + r < TSEQ) ? 16 : 0;
        CP_ASYNC16(sbase + OFF_QH + r * 144 + seg * 16,
                   qhg + (size_t)(q0 + r) * NQKV + seg * 8, ok);
        CP_ASYNC16(sbase + OFF_QL + r * 144 + seg * 16,
                   qlg + (size_t)(q0 + r) * NQKV + seg * 8, ok);
    }
    // ---- stage K block 0 ----
#pragma unroll
    for (int i = 0; i < 2; i++) {
        const int idx = tid + i * 256;
        const int r = idx >> 3, seg = idx & 7;
        const int ok = (r < TSEQ) ? 16 : 0;
        CP_ASYNC16(sbase + OFF_KV + r * 144 + seg * 16,
                   khg + (size_t)r * NQKV + seg * 8, ok);
        CP_ASYNC16(sbase + OFF_KV + 9216 + r * 144 + seg * 16,
                   klg + (size_t)r * NQKV + seg * 8, ok);
    }
    CP_COMMIT();

    const uint32_t aRow = (uint32_t)(warpM * 32 + (lane & 15)) * 144;
    const uint32_t aCol = (uint32_t)((lane >> 4) * 8) * 2;
    // phase-1 B (K tile, non-trans x4): lanes 0-7 n+0-7 k0, 8-15 n+0-7 k1,
    //                                   16-23 n+8-15 k0, 24-31 n+8-15 k1
    const uint32_t bRow4 = (uint32_t)(warpN * 16 + (lane & 7) + ((lane >> 4) << 3)) * 144;
    const uint32_t bColB = (uint32_t)(((lane >> 3) & 1) * 8) * 2;
    // phase-3 V (trans x4): lanes 0-7 k rows 0-7, 8-15 k rows 8-15 (col d+0),
    //                       16-23 k rows 0-7, 24-31 k rows 8-15 (col d+8)
    const uint32_t vRow4 = (uint32_t)((lane & 7) + ((lane >> 3) & 1) * 8) * 144;
    const uint32_t vCol4 = (uint32_t)(warpN * 16 + ((lane >> 4) << 3)) * 2;

    // ================= phase 1: S = scale * Q K^T + bias =================
    for (int c = 0; c < NKB; c++) {
        if (c + 1 < NKB) {
            const uint32_t kb = sbase + OFF_KV + ((c + 1) & 1) * KVBUF;
            const int j0n = (c + 1) * 64;
#pragma unroll
            for (int i = 0; i < 2; i++) {
                const int idx = tid + i * 256;
                const int r = idx >> 3, seg = idx & 7;
                const int ok = (j0n + r < TSEQ) ? 16 : 0;
                CP_ASYNC16(kb + r * 144 + seg * 16,
                           khg + (size_t)(j0n + r) * NQKV + seg * 8, ok);
                CP_ASYNC16(kb + 9216 + r * 144 + seg * 16,
                           klg + (size_t)(j0n + r) * NQKV + seg * 8, ok);
            }
            CP_COMMIT();
            CP_WAIT(1);
        } else {
            CP_WAIT(0);
        }
        __syncthreads();

        const uint32_t kvh = sbase + OFF_KV + (c & 1) * KVBUF;
        const uint32_t kvl = kvh + 9216;

        float sc[2][2][4];
#pragma unroll
        for (int mi = 0; mi < 2; mi++)
#pragma unroll
            for (int ni = 0; ni < 2; ni++)
#pragma unroll
                for (int q = 0; q < 4; q++) sc[mi][ni][q] = 0.f;

#pragma unroll
        for (int ks = 0; ks < 4; ks++) {
            uint32_t bh4[4], bl4[4];
            const uint32_t bo = bRow4 + bColB + ks * 32;
            ldmatrix_x4(bh4, kvh + bo);
            ldmatrix_x4(bl4, kvl + bo);
#pragma unroll
            for (int mi = 0; mi < 2; mi++) {
                const uint32_t ao = aRow + (uint32_t)(mi * 16) * 144 + aCol + ks * 32;
                uint32_t ah[4], al[4];
                ldmatrix_x4(ah, sbase + OFF_QH + ao);
                ldmatrix_x4(al, sbase + OFF_QL + ao);
#pragma unroll
                for (int ni = 0; ni < 2; ni++) {
                    mma_bf16(sc[mi][ni], ah, &bh4[ni * 2]);
                    mma_bf16(sc[mi][ni], ah, &bl4[ni * 2]);
                    mma_bf16(sc[mi][ni], al, &bh4[ni * 2]);
                }
            }
        }

        const int j0 = c * 64;
        const int jn = min(64, TSEQ - j0);
#pragma unroll
        for (int mi = 0; mi < 2; mi++) {
#pragma unroll
            for (int ni = 0; ni < 2; ni++) {
                const int c0 = warpN * 16 + ni * 8 + (lane & 3) * 2;
#pragma unroll
                for (int half = 0; half < 2; half++) {
                    const int r = warpM * 32 + mi * 16 + (lane >> 2) + half * 8;
                    const int qi = q0 + r;
                    if (c0 < jn)
                        S[r * ASP + j0 + c0] =
                            sc[mi][ni][half * 2] * 0.125f + cross_bias(qi, j0 + c0);
                    if (c0 + 1 < jn)
                        S[r * ASP + j0 + c0 + 1] =
                            sc[mi][ni][half * 2 + 1] * 0.125f + cross_bias(qi, j0 + c0 + 1);
                }
            }
        }
        __syncthreads();
    }

    // ---- prefetch V block 0 (overlaps softmax) ----
#pragma unroll
    for (int i = 0; i < 2; i++) {
        const int idx = tid + i * 256;
        const int r = idx >> 3, seg = idx & 7;
        const int ok = (r < TSEQ) ? 16 : 0;
        CP_ASYNC16(sbase + OFF_KV + r * 144 + seg * 16,
                   vhg + (size_t)r * NQKV + seg * 8, ok);
        CP_ASYNC16(sbase + OFF_KV + 9216 + r * 144 + seg * 16,
                   vlg + (size_t)r * NQKV + seg * 8, ok);
    }
    CP_COMMIT();

    // ================= phase 2: softmax =================
    {
        const int row = tid >> 2, l4 = tid & 3;
        float m = -1e30f;
        for (int j = l4; j < TSEQ; j += 4) m = fmaxf(m, S[row * ASP + j]);
        m = fmaxf(m, __shfl_xor_sync(0xffffffffu, m, 1, 4));
        m = fmaxf(m, __shfl_xor_sync(0xffffffffu, m, 2, 4));
        float s = 0.f;
        for (int j = l4; j < TSEQ; j += 4) {
            const float e = __expf(S[row * ASP + j] - m);
            S[row * ASP + j] = e;
            s += e;
        }
        s += __shfl_xor_sync(0xffffffffu, s, 1, 4);
        s += __shfl_xor_sync(0xffffffffu, s, 2, 4);
        if (l4 == 0) rinv[row] = 1.0f / s;
    }

    // ================= phase 3: Y = P V =================
    float yc[2][2][4];
#pragma unroll
    for (int mi = 0; mi < 2; mi++)
#pragma unroll
        for (int ni = 0; ni < 2; ni++)
#pragma unroll
            for (int q = 0; q < 4; q++) yc[mi][ni][q] = 0.f;

    bf16* phS = (bf16*)(smem + OFF_PH);
    bf16* plS = (bf16*)(smem + OFF_PL);

    for (int c = 0; c < NKB; c++) {
        const int j0 = c * 64;
        __syncthreads();   // mma(c-1) done everywhere; softmax done (c==0)

        if (c + 1 < NKB) {         // stage V(c+1) into the other buffer
            const uint32_t vb = sbase + OFF_KV + ((c + 1) & 1) * KVBUF;
            const int j0n = (c + 1) * 64;
#pragma unroll
            for (int i = 0; i < 2; i++) {
                const int idx = tid + i * 256;
                const int r = idx >> 3, seg = idx & 7;
                const int ok = (j0n + r < TSEQ) ? 16 : 0;
                CP_ASYNC16(vb + r * 144 + seg * 16,
                           vhg + (size_t)(j0n + r) * NQKV + seg * 8, ok);
                CP_ASYNC16(vb + 9216 + r * 144 + seg * 16,
                           vlg + (size_t)(j0n + r) * NQKV + seg * 8, ok);
            }
            CP_COMMIT();
        }

        // convert P block c -> bf16 hi/lo (rinv folded)
        {
            const int row = tid >> 2, jj0 = (tid & 3) * 16;
            const float ri = rinv[row];
#pragma unroll
            for (int q = 0; q < 16; q++) {
                const int j = jj0 + q;
                const int jg = j0 + j;
                float p = (jg < TSEQ) ? S[row * ASP + jg] * ri : 0.f;
                bf16 hh, ll; split2(p, hh, ll);
                phS[row * APITCH + j] = hh;
                plS[row * APITCH + j] = ll;
            }
        }

        if (c + 1 < NKB) { CP_WAIT(1); } else { CP_WAIT(0); }
        __syncthreads();   // P ready, V(c) ready

        const uint32_t vvh = sbase + OFF_KV + (c & 1) * KVBUF;
        const uint32_t vvl = vvh + 9216;

#pragma unroll
        for (int ks = 0; ks < 4; ks++) {
            uint32_t vh4[4], vl4[4];
            const uint32_t vo = vRow4 + (uint32_t)(ks * 16) * 144 + vCol4;
            ldmatrix_x4_trans(vh4, vvh + vo);
            ldmatrix_x4_trans(vl4, vvl + vo);
#pragma unroll
            for (int mi = 0; mi < 2; mi++) {
                const uint32_t ao = aRow + (uint32_t)(mi * 16) * 144 + aCol + ks * 32;
                uint32_t ph[4], pl[4];
                ldmatrix_x4(ph, sbase + OFF_PH + ao);
                ldmatrix_x4(pl, sbase + OFF_PL + ao);
#pragma unroll
                for (int ni = 0; ni < 2; ni++) {
                    mma_bf16(yc[mi][ni], ph, &vh4[ni * 2]);
                    mma_bf16(yc[mi][ni], ph, &vl4[ni * 2]);
                    mma_bf16(yc[mi][ni], pl, &vh4[ni * 2]);
                }
            }
        }
    }

    // write y as bf16 hi/lo into g_a_hi/lo
#pragma unroll
    for (int mi = 0; mi < 2; mi++) {
#pragma unroll
        for (int ni = 0; ni < 2; ni++) {
            const int d = warpN * 16 + ni * 8 + (lane & 3) * 2;
#pragma unroll
            for (int half = 0; half < 2; half++) {
                const int r = warpM * 32 + mi * 16 + (lane >> 2) + half * 8;
                const int t = q0 + r;
                if (t >= TSEQ) continue;
                const size_t o = ((size_t)b * TSEQ + t) * NC + h * HD + d;
                bf16 h0, l0, h1, l1;
                split2(yc[mi][ni][half * 2],     h0, l0);
                split2(yc[mi][ni][half * 2 + 1], h1, l1);
                __nv_bfloat162 hh; hh.x = h0; hh.y = h1;
                __nv_bfloat162 ll; ll.x = l0; ll.y = l1;
                *(__nv_bfloat162*)(g_a_hi + o) = hh;
                *(__nv_bfloat162*)(g_a_lo + o) = ll;
            }
        }
    }
}

// ---------------------------------------------------------------------------
extern "C" void kernel_launch(void* const* d_in, const int* in_sizes, int n_in,
                              void* d_out, int out_size)
{
    const float* x      = (const float*)d_in[0];
    const float* W_attn = (const float*)d_in[1];
    const float* b_attn = (const float*)d_in[2];
    const float* W_proj = (const float*)d_in[3];
    const float* b_proj = (const float*)d_in[4];
    float* out = (float*)d_out;

    cudaFuncSetAttribute(gemm_mma, cudaFuncAttributeMaxDynamicSharedMemorySize, GEMM_SMEM);
    cudaFuncSetAttribute(attn_mma, cudaFuncAttributeMaxDynamicSharedMemorySize, ATTN_SMEM);

    void *pAhi, *pAlo, *pQhi, *pQlo, *pWqHi, *pWqLo, *pWpHi, *pWpLo;
    cudaGetSymbolAddress(&pAhi,  g_a_hi);
    cudaGetSymbolAddress(&pAlo,  g_a_lo);
    cudaGetSymbolAddress(&pQhi,  g_qkv_hi);
    cudaGetSymbolAddress(&pQlo,  g_qkv_lo);
    cudaGetSymbolAddress(&pWqHi, g_wq_hi);
    cudaGetSymbolAddress(&pWqLo, g_wq_lo);
    cudaGetSymbolAddress(&pWpHi, g_wp_hi);
    cudaGetSymbolAddress(&pWpLo, g_wp_lo);

    const size_t n4 = (size_t)MROWS * NC / 4;
    split_fp32<<<(int)((n4 + 255) / 256), 256>>>(x, (bf16*)pAhi, (bf16*)pAlo, n4);
    transpose_split<<<dim3(NQKV / 32, GK / 32), 256>>>(W_attn, (bf16*)pWqHi, (bf16*)pWqLo, GK, NQKV);
    transpose_split<<<dim3(NC / 32, GK / 32), 256>>>(W_proj, (bf16*)pWpHi, (bf16*)pWpLo, GK, NC);

    dim3 g1(NQKV / 128, (MROWS + 127) / 128);
    gemm_mma<<<g1, 256, GEMM_SMEM>>>((bf16*)pAhi, (bf16*)pAlo, (bf16*)pWqHi, (bf16*)pWqLo,
                                     b_attn, nullptr, (bf16*)pQhi, (bf16*)pQlo,
                                     MROWS, NQKV, 1);

    dim3 ga((TSEQ + AQR - 1) / AQR, NB * NH);
    attn_mma<<<ga, 256, ATTN_SMEM>>>();

    dim3 g2(NC / 128, (MROWS + 127) / 128);
    gemm_mma<<<g2, 256, GEMM_SMEM>>>((bf16*)pAhi, (bf16*)pAlo, (bf16*)pWpHi, (bf16*)pWpLo,
                                     b_proj, out, nullptr, nullptr,
                                     MROWS, NC, 0);
}

// round 6
// speedup vs baseline: 3.2769x; 1.2859x over previous
#include <cuda_runtime.h>
#include <cuda_bf16.h>
#include <cstdint>

// ---------------------------------------------------------------------------
// CrossOnlyAttention  (B=64, T=469, C=1024, H=16, hd=64)
// Round 6: flash-style attention — online softmax, S/P register-resident
// (accumulator->A-operand fragment reuse), K/V double-buffered cp.async.
// GEMMs unchanged from round 5.
// ---------------------------------------------------------------------------

#define TSEQ   469
#define NB     64
#define NC     1024
#define NH     16
#define HD     64
#define MROWS  (NB * TSEQ)   // 30016
#define NQKV   (3 * NC)      // 3072
#define GK     1024

typedef __nv_bfloat16 bf16;

__device__ bf16 g_a_hi[(size_t)MROWS * NC];
__device__ bf16 g_a_lo[(size_t)MROWS * NC];
__device__ bf16 g_qkv_hi[(size_t)MROWS * NQKV];
__device__ bf16 g_qkv_lo[(size_t)MROWS * NQKV];
__device__ bf16 g_wq_hi[(size_t)NQKV * GK];
__device__ bf16 g_wq_lo[(size_t)NQKV * GK];
__device__ bf16 g_wp_hi[(size_t)NC * GK];
__device__ bf16 g_wp_lo[(size_t)NC * GK];

// ---------------------------------------------------------------------------
// helpers
// ---------------------------------------------------------------------------
__device__ __forceinline__ uint32_t smem_u32(const void* p) {
    uint32_t a;
    asm("{ .reg .u64 t; cvta.to.shared.u64 t, %1; cvt.u32.u64 %0, t; }" : "=r"(a) : "l"(p));
    return a;
}

#define CP_ASYNC16(dst, src, sz) \
    asm volatile("cp.async.cg.shared.global [%0], [%1], 16, %2;" \
                 :: "r"(dst), "l"(src), "r"(sz) : "memory")
#define CP_COMMIT() asm volatile("cp.async.commit_group;" ::: "memory")
#define CP_WAIT(N)  asm volatile("cp.async.wait_group %0;" :: "n"(N) : "memory")

__device__ __forceinline__ void ldmatrix_x4(uint32_t* r, uint32_t addr) {
    asm volatile("ldmatrix.sync.aligned.m8n8.x4.shared.b16 {%0,%1,%2,%3}, [%4];"
                 : "=r"(r[0]), "=r"(r[1]), "=r"(r[2]), "=r"(r[3]) : "r"(addr));
}
__device__ __forceinline__ void ldmatrix_x4_trans(uint32_t* r, uint32_t addr) {
    asm volatile("ldmatrix.sync.aligned.m8n8.x4.trans.shared.b16 {%0,%1,%2,%3}, [%4];"
                 : "=r"(r[0]), "=r"(r[1]), "=r"(r[2]), "=r"(r[3]) : "r"(addr));
}
__device__ __forceinline__ void mma_bf16(float* c, const uint32_t* a, const uint32_t* b) {
    asm volatile("mma.sync.aligned.m16n8k16.row.col.f32.bf16.bf16.f32 "
                 "{%0,%1,%2,%3},{%4,%5,%6,%7},{%8,%9},{%0,%1,%2,%3};"
                 : "+f"(c[0]), "+f"(c[1]), "+f"(c[2]), "+f"(c[3])
                 : "r"(a[0]), "r"(a[1]), "r"(a[2]), "r"(a[3]), "r"(b[0]), "r"(b[1]));
}

__device__ __forceinline__ void split2(float v, bf16& h, bf16& l) {
    h = __float2bfloat16(v);
    l = __float2bfloat16(v - __bfloat162float(h));
}
// pack two fp32 into bf16x2 hi-word and lo-word (elem a in low 16 bits)
__device__ __forceinline__ void pack_split(float a, float b, uint32_t& hi, uint32_t& lo) {
    bf16 ha, la, hb, lb;
    split2(a, ha, la); split2(b, hb, lb);
    hi = ((uint32_t)__bfloat16_as_ushort(hb) << 16) | __bfloat16_as_ushort(ha);
    lo = ((uint32_t)__bfloat16_as_ushort(lb) << 16) | __bfloat16_as_ushort(la);
}

// ---------------------------------------------------------------------------
// conversion kernels (unchanged)
// ---------------------------------------------------------------------------
__global__ void split_fp32(const float* __restrict__ src,
                           bf16* __restrict__ hi, bf16* __restrict__ lo, size_t n4)
{
    size_t i = (size_t)blockIdx.x * blockDim.x + threadIdx.x;
    if (i >= n4) return;
    float4 v = ((const float4*)src)[i];
    float vv[4] = {v.x, v.y, v.z, v.w};
    __align__(8) bf16 h[4], l[4];
#pragma unroll
    for (int q = 0; q < 4; q++) split2(vv[q], h[q], l[q]);
    ((uint2*)hi)[i] = *(uint2*)h;
    ((uint2*)lo)[i] = *(uint2*)l;
}

__global__ void transpose_split(const float* __restrict__ src,
                                bf16* __restrict__ dhi, bf16* __restrict__ dlo,
                                int K, int N)
{
    __shared__ float tile[32][33];
    const int n0 = blockIdx.x * 32, k0 = blockIdx.y * 32;
    const int tx = threadIdx.x & 31, ty0 = threadIdx.x >> 5;
#pragma unroll
    for (int i = 0; i < 4; i++) {
        int ty = ty0 + i * 8;
        tile[ty][tx] = src[(size_t)(k0 + ty) * N + n0 + tx];
    }
    __syncthreads();
#pragma unroll
    for (int i = 0; i < 4; i++) {
        int ty = ty0 + i * 8;
        float v = tile[tx][ty];
        bf16 h, l; split2(v, h, l);
        dhi[(size_t)(n0 + ty) * K + k0 + tx] = h;
        dlo[(size_t)(n0 + ty) * K + k0 + tx] = l;
    }
}

// ---------------------------------------------------------------------------
// mma.sync GEMM (unchanged from round 5)
// ---------------------------------------------------------------------------
#define BK        32
#define NCHUNK    (GK / BK)
#define LDT       40
#define TILE_BYTES (128 * LDT * 2)
#define STAGE_BYTES (4 * TILE_BYTES)
#define GEMM_SMEM  (2 * STAGE_BYTES)

__device__ __forceinline__ void tile_cp(const bf16* __restrict__ src,
                                        int row0, int maxrow, int k0,
                                        uint32_t sdst, int tid)
{
#pragma unroll
    for (int i = 0; i < 2; i++) {
        const int idx = tid + i * 256;
        const int r = idx >> 2, seg = idx & 3;
        const int gr = row0 + r;
        const int ok = (gr < maxrow) ? 16 : 0;
        const bf16* gp = src + (size_t)min(gr, maxrow - 1) * GK + k0 + seg * 8;
        CP_ASYNC16(sdst + r * (LDT * 2) + seg * 16, gp, ok);
    }
}

__global__ void __launch_bounds__(256, 2)
gemm_mma(const bf16* __restrict__ Ah, const bf16* __restrict__ Al,
         const bf16* __restrict__ Bh, const bf16* __restrict__ Bl,
         const float* __restrict__ bias,
         float* __restrict__ outF, bf16* __restrict__ outHi, bf16* __restrict__ outLo,
         int M, int N, int splitOut)
{
    extern __shared__ char smem[];
    const uint32_t sbase = smem_u32(smem);
    const int tid = threadIdx.x, wid = tid >> 5, lane = tid & 31;
    const int warpM = wid >> 2, warpN = wid & 3;
    const int n0 = blockIdx.x * 128, m0 = blockIdx.y * 128;

    float acc[4][4][4];
#pragma unroll
    for (int i = 0; i < 4; i++)
#pragma unroll
        for (int j = 0; j < 4; j++)
#pragma unroll
            for (int q = 0; q < 4; q++) acc[i][j][q] = 0.f;

    const uint32_t aRowB = (uint32_t)(warpM * 64 + (lane & 15)) * (LDT * 2);
    const uint32_t aColB = (uint32_t)((lane >> 4) * 8) * 2;
    const uint32_t bRow4 = (uint32_t)(warpN * 32 + (lane & 7) + ((lane >> 4) << 3)) * (LDT * 2);
    const uint32_t bColB = (uint32_t)(((lane >> 3) & 1) * 8) * 2;

    tile_cp(Ah, m0, M, 0, sbase + 0 * TILE_BYTES, tid);
    tile_cp(Al, m0, M, 0, sbase + 1 * TILE_BYTES, tid);
    tile_cp(Bh, n0, N, 0, sbase + 2 * TILE_BYTES, tid);
    tile_cp(Bl, n0, N, 0, sbase + 3 * TILE_BYTES, tid);
    CP_COMMIT();

    for (int c = 0; c < NCHUNK; c++) {
        if (c + 1 < NCHUNK) {
            const uint32_t st = sbase + ((c + 1) & 1) * STAGE_BYTES;
            const int k0 = (c + 1) * BK;
            tile_cp(Ah, m0, M, k0, st + 0 * TILE_BYTES, tid);
            tile_cp(Al, m0, M, k0, st + 1 * TILE_BYTES, tid);
            tile_cp(Bh, n0, N, k0, st + 2 * TILE_BYTES, tid);
            tile_cp(Bl, n0, N, k0, st + 3 * TILE_BYTES, tid);
            CP_COMMIT();
            CP_WAIT(1);
        } else {
            CP_WAIT(0);
        }
        __syncthreads();

        const uint32_t st = sbase + (c & 1) * STAGE_BYTES;
        const uint32_t sAh = st, sAl = st + TILE_BYTES;
        const uint32_t sBh = st + 2 * TILE_BYTES, sBl = st + 3 * TILE_BYTES;

#pragma unroll
        for (int ks = 0; ks < 2; ks++) {
            const uint32_t kOffA = aColB + ks * 32;
            const uint32_t kOffB = bColB + ks * 32;

            uint32_t bh4[2][4], bl4[2][4];
#pragma unroll
            for (int np = 0; np < 2; np++) {
                const uint32_t bo = bRow4 + (uint32_t)(np * 16) * (LDT * 2) + kOffB;
                ldmatrix_x4(bh4[np], sBh + bo);
                ldmatrix_x4(bl4[np], sBl + bo);
            }
#pragma unroll
            for (int mi = 0; mi < 4; mi++) {
                const uint32_t ao = aRowB + (uint32_t)(mi * 16) * (LDT * 2) + kOffA;
                uint32_t ah[4], al[4];
                ldmatrix_x4(ah, sAh + ao);
                ldmatrix_x4(al, sAl + ao);
#pragma unroll
                for (int ni = 0; ni < 4; ni++) {
                    const uint32_t* pbh = &bh4[ni >> 1][(ni & 1) * 2];
                    const uint32_t* pbl = &bl4[ni >> 1][(ni & 1) * 2];
                    mma_bf16(acc[mi][ni], ah, pbh);
                    mma_bf16(acc[mi][ni], ah, pbl);
                    mma_bf16(acc[mi][ni], al, pbh);
                }
            }
        }
        __syncthreads();
    }

    const int cBase = n0 + warpN * 32 + (lane & 3) * 2;
    const int rBase = m0 + warpM * 64 + (lane >> 2);
#pragma unroll
    for (int mi = 0; mi < 4; mi++) {
#pragma unroll
        for (int ni = 0; ni < 4; ni++) {
            const int col = cBase + ni * 8;
            const float b0 = bias[col], b1 = bias[col + 1];
#pragma unroll
            for (int half = 0; half < 2; half++) {
                const int r = rBase + mi * 16 + half * 8;
                if (r >= M) continue;
                const float v0 = acc[mi][ni][half * 2 + 0] + b0;
                const float v1 = acc[mi][ni][half * 2 + 1] + b1;
                const size_t o = (size_t)r * N + col;
                if (splitOut) {
                    bf16 h0, l0, h1, l1;
                    split2(v0, h0, l0); split2(v1, h1, l1);
                    __nv_bfloat162 hh; hh.x = h0; hh.y = h1;
                    __nv_bfloat162 ll; ll.x = l0; ll.y = l1;
                    *(__nv_bfloat162*)(outHi + o) = hh;
                    *(__nv_bfloat162*)(outLo + o) = ll;
                } else {
                    *(float2*)(outF + o) = make_float2(v0, v1);
                }
            }
        }
    }
}

// ---------------------------------------------------------------------------
// flash attention: 128 q-rows/CTA, 8 warps x 16 rows, online softmax,
// S/P register-resident, K/V double-buffered.
// ---------------------------------------------------------------------------
#define AQR    128
#define NKB    8
#define APB    144                 // smem row pitch bytes (72 bf16)

#define OFF_QH   0
#define OFF_QL   (128 * APB)                 // 18432
#define OFF_KV   (2 * 128 * APB)             // 36864
#define KVSTG    (4 * 64 * APB)              // 36864: Kh,Kl,Vh,Vl
#define ATTN_SMEM (OFF_KV + 2 * KVSTG)       // 110592

__device__ __forceinline__ float cross_bias(int i, int j)
{
    if (i == 0 || j == 0) return 1.0f;
    return ((i <= 234) != (j <= 234)) ? 1.0f : 0.0f;
}

// stage one 64-key K/V block (hi+lo each) into buffer
__device__ __forceinline__ void kv_stage(const bf16* khg, const bf16* klg,
                                         const bf16* vhg, const bf16* vlg,
                                         int j0, uint32_t buf, int tid)
{
#pragma unroll
    for (int i = 0; i < 2; i++) {
        const int idx = tid + i * 256;       // 0..511
        const int r = idx >> 3, seg = idx & 7;
        const int ok = (j0 + r < TSEQ) ? 16 : 0;
        const size_t g = (size_t)(j0 + r) * NQKV + seg * 8;
        const uint32_t s = buf + r * APB + seg * 16;
        CP_ASYNC16(s,                khg + g, ok);
        CP_ASYNC16(s + 64 * APB,     klg + g, ok);
        CP_ASYNC16(s + 2 * 64 * APB, vhg + g, ok);
        CP_ASYNC16(s + 3 * 64 * APB, vlg + g, ok);
    }
}

__global__ void __launch_bounds__(256, 1)
attn_flash()
{
    extern __shared__ char smem[];
    const uint32_t sbase = smem_u32(smem);

    const int tid = threadIdx.x, wid = tid >> 5, lane = tid & 31;
    const int bh = blockIdx.y;
    const int b  = bh >> 4, h = bh & 15;
    const int q0 = blockIdx.x * AQR;

    const size_t rowb = (size_t)b * TSEQ * NQKV + h * HD;
    const bf16* qhg = g_qkv_hi + rowb;
    const bf16* qlg = g_qkv_lo + rowb;
    const bf16* khg = qhg + NC;
    const bf16* klg = qlg + NC;
    const bf16* vhg = qhg + 2 * NC;
    const bf16* vlg = qlg + 2 * NC;

    // ---- stage Q tile (128 rows x 64 d, hi+lo) ----
#pragma unroll
    for (int i = 0; i < 4; i++) {
        const int idx = tid + i * 256;       // 0..1023
        const int r = idx >> 3, seg = idx & 7;
        const int ok = (q0 + r < TSEQ) ? 16 : 0;
        const size_t g = (size_t)(q0 + r) * NQKV + seg * 8;
        CP_ASYNC16(sbase + OFF_QH + r * APB + seg * 16, qhg + g, ok);
        CP_ASYNC16(sbase + OFF_QL + r * APB + seg * 16, qlg + g, ok);
    }
    kv_stage(khg, klg, vhg, vlg, 0, sbase + OFF_KV, tid);
    CP_COMMIT();

    // per-lane fragment addresses
    const uint32_t aRowQ = (uint32_t)(wid * 16 + (lane & 15)) * APB;
    const uint32_t aColQ = (uint32_t)((lane >> 4) * 8) * 2;
    const uint32_t kRow4 = (uint32_t)((lane & 7) + ((lane >> 4) << 3)) * APB;
    const uint32_t kColB = (uint32_t)(((lane >> 3) & 1) * 8) * 2;
    const uint32_t vRow4 = (uint32_t)((lane & 7) + ((lane >> 3) & 1) * 8) * APB;
    const uint32_t vCol4 = (uint32_t)((lane >> 4) << 3) * 2;

    uint32_t qh[4][4], ql[4][4];   // Q frags, persistent
    float yc[8][4];
    float m_run[2] = {-1e30f, -1e30f};
    float s_run[2] = {0.f, 0.f};
#pragma unroll
    for (int ni = 0; ni < 8; ni++)
#pragma unroll
        for (int q = 0; q < 4; q++) yc[ni][q] = 0.f;

    for (int c = 0; c < NKB; c++) {
        if (c + 1 < NKB) {
            kv_stage(khg, klg, vhg, vlg, (c + 1) * 64,
                     sbase + OFF_KV + ((c + 1) & 1) * KVSTG, tid);
            CP_COMMIT();
            CP_WAIT(1);
        } else {
            CP_WAIT(0);
        }
        __syncthreads();

        if (c == 0) {   // load Q frags once
#pragma unroll
            for (int ks = 0; ks < 4; ks++) {
                const uint32_t ao = aRowQ + aColQ + ks * 32;
                ldmatrix_x4(qh[ks], sbase + OFF_QH + ao);
                ldmatrix_x4(ql[ks], sbase + OFF_QL + ao);
            }
        }

        const uint32_t stg = sbase + OFF_KV + (c & 1) * KVSTG;
        const uint32_t skh = stg, skl = stg + 64 * APB;
        const uint32_t svh = stg + 2 * 64 * APB, svl = stg + 3 * 64 * APB;

        // ---- S = Q K^T ----
        float sc[8][4];
#pragma unroll
        for (int ni = 0; ni < 8; ni++)
#pragma unroll
            for (int q = 0; q < 4; q++) sc[ni][q] = 0.f;

#pragma unroll
        for (int ks = 0; ks < 4; ks++) {
#pragma unroll
            for (int np = 0; np < 4; np++) {
                uint32_t kh4[4], kl4[4];
                const uint32_t bo = kRow4 + (uint32_t)(np * 16) * APB + kColB + ks * 32;
                ldmatrix_x4(kh4, skh + bo);
                ldmatrix_x4(kl4, skl + bo);
#pragma unroll
                for (int t = 0; t < 2; t++) {
                    mma_bf16(sc[np * 2 + t], qh[ks], &kh4[t * 2]);
                    mma_bf16(sc[np * 2 + t], qh[ks], &kl4[t * 2]);
                    mma_bf16(sc[np * 2 + t], ql[ks], &kh4[t * 2]);
                }
            }
        }

        // ---- scale + bias + OOB mask ----
        const int j0 = c * 64;
#pragma unroll
        for (int ni = 0; ni < 8; ni++) {
#pragma unroll
            for (int q = 0; q < 4; q++) {
                const int e = q & 1, hh = q >> 1;
                const int jg = j0 + ni * 8 + (lane & 3) * 2 + e;
                const int qi = q0 + wid * 16 + (lane >> 2) + hh * 8;
                const float v = sc[ni][q] * 0.125f + cross_bias(qi, jg);
                sc[ni][q] = (jg < TSEQ) ? v : -1e30f;
            }
        }

        // ---- online softmax update (per row-half) ----
#pragma unroll
        for (int hh = 0; hh < 2; hh++) {
            float mb = -1e30f;
#pragma unroll
            for (int ni = 0; ni < 8; ni++)
                mb = fmaxf(mb, fmaxf(sc[ni][hh * 2], sc[ni][hh * 2 + 1]));
            mb = fmaxf(mb, __shfl_xor_sync(0xffffffffu, mb, 1));
            mb = fmaxf(mb, __shfl_xor_sync(0xffffffffu, mb, 2));
            const float mn = fmaxf(m_run[hh], mb);
            const float f = __expf(m_run[hh] - mn);
            m_run[hh] = mn;
            float sb = 0.f;
#pragma unroll
            for (int ni = 0; ni < 8; ni++) {
                const float p0 = __expf(sc[ni][hh * 2] - mn);
                const float p1 = __expf(sc[ni][hh * 2 + 1] - mn);
                sc[ni][hh * 2] = p0; sc[ni][hh * 2 + 1] = p1;
                sb += p0 + p1;
            }
            sb += __shfl_xor_sync(0xffffffffu, sb, 1);
            sb += __shfl_xor_sync(0xffffffffu, sb, 2);
            s_run[hh] = s_run[hh] * f + sb;
#pragma unroll
            for (int ni = 0; ni < 8; ni++) {
                yc[ni][hh * 2]     *= f;
                yc[ni][hh * 2 + 1] *= f;
            }
        }

        // ---- Y += P V  (P frags straight from registers) ----
#pragma unroll
        for (int kk = 0; kk < 4; kk++) {
            uint32_t pah[4], pal[4];
#pragma unroll
            for (int t = 0; t < 2; t++) {
                const float* s0 = sc[kk * 2 + t];
                pack_split(s0[0], s0[1], pah[t * 2 + 0], pal[t * 2 + 0]); // wrong slot? see below
                pack_split(s0[2], s0[3], pah[t * 2 + 1], pal[t * 2 + 1]);
            }
            // frag layout check: a0 = (row r,  k lo) = tile 2kk  c0c1 -> pah[0]
            //                    a1 = (row r+8,k lo) = tile 2kk  c2c3 -> pah[1]
            //                    a2 = (row r,  k hi) = tile 2kk+1 c0c1 -> pah[2]
            //                    a3 = (row r+8,k hi) = tile 2kk+1 c2c3 -> pah[3]
#pragma unroll
            for (int np = 0; np < 4; np++) {
                uint32_t vh4[4], vl4[4];
                const uint32_t vo = vRow4 + (uint32_t)(kk * 16) * APB
                                  + (uint32_t)(np * 16) * 2 + vCol4;
                ldmatrix_x4_trans(vh4, svh + vo);
                ldmatrix_x4_trans(vl4, svl + vo);
#pragma unroll
                for (int t = 0; t < 2; t++) {
                    mma_bf16(yc[np * 2 + t], pah, &vh4[t * 2]);
                    mma_bf16(yc[np * 2 + t], pah, &vl4[t * 2]);
                    mma_bf16(yc[np * 2 + t], pal, &vh4[t * 2]);
                }
            }
        }
        __syncthreads();
    }

    // ---- epilogue: normalize, split, store ----
#pragma unroll
    for (int hh = 0; hh < 2; hh++) {
        const float ri = 1.0f / s_run[hh];
        const int r = wid * 16 + (lane >> 2) + hh * 8;
        const int t = q0 + r;
        if (t >= TSEQ) continue;
        const size_t base = ((size_t)b * TSEQ + t) * NC + h * HD;
#pragma unroll
        for (int ni = 0; ni < 8; ni++) {
            const int d = ni * 8 + (lane & 3) * 2;
            const float v0 = yc[ni][hh * 2] * ri;
            const float v1 = yc[ni][hh * 2 + 1] * ri;
            bf16 h0, l0, h1, l1;
            split2(v0, h0, l0); split2(v1, h1, l1);
            __nv_bfloat162 hv; hv.x = h0; hv.y = h1;
            __nv_bfloat162 lv; lv.x = l0; lv.y = l1;
            *(__nv_bfloat162*)(g_a_hi + base + d) = hv;
            *(__nv_bfloat162*)(g_a_lo + base + d) = lv;
        }
    }
}

// ---------------------------------------------------------------------------
extern "C" void kernel_launch(void* const* d_in, const int* in_sizes, int n_in,
                              void* d_out, int out_size)
{
    const float* x      = (const float*)d_in[0];
    const float* W_attn = (const float*)d_in[1];
    const float* b_attn = (const float*)d_in[2];
    const float* W_proj = (const float*)d_in[3];
    const float* b_proj = (const float*)d_in[4];
    float* out = (float*)d_out;

    cudaFuncSetAttribute(gemm_mma, cudaFuncAttributeMaxDynamicSharedMemorySize, GEMM_SMEM);
    cudaFuncSetAttribute(attn_flash, cudaFuncAttributeMaxDynamicSharedMemorySize, ATTN_SMEM);

    void *pAhi, *pAlo, *pQhi, *pQlo, *pWqHi, *pWqLo, *pWpHi, *pWpLo;
    cudaGetSymbolAddress(&pAhi,  g_a_hi);
    cudaGetSymbolAddress(&pAlo,  g_a_lo);
    cudaGetSymbolAddress(&pQhi,  g_qkv_hi);
    cudaGetSymbolAddress(&pQlo,  g_qkv_lo);
    cudaGetSymbolAddress(&pWqHi, g_wq_hi);
    cudaGetSymbolAddress(&pWqLo, g_wq_lo);
    cudaGetSymbolAddress(&pWpHi, g_wp_hi);
    cudaGetSymbolAddress(&pWpLo, g_wp_lo);

    const size_t n4 = (size_t)MROWS * NC / 4;
    split_fp32<<<(int)((n4 + 255) / 256), 256>>>(x, (bf16*)pAhi, (bf16*)pAlo, n4);
    transpose_split<<<dim3(NQKV / 32, GK / 32), 256>>>(W_attn, (bf16*)pWqHi, (bf16*)pWqLo, GK, NQKV);
    transpose_split<<<dim3(NC / 32, GK / 32), 256>>>(W_proj, (bf16*)pWpHi, (bf16*)pWpLo, GK, NC);

    dim3 g1(NQKV / 128, (MROWS + 127) / 128);
    gemm_mma<<<g1, 256, GEMM_SMEM>>>((bf16*)pAhi, (bf16*)pAlo, (bf16*)pWqHi, (bf16*)pWqLo,
                                     b_attn, nullptr, (bf16*)pQhi, (bf16*)pQlo,
                                     MROWS, NQKV, 1);

    dim3 ga((TSEQ + AQR - 1) / AQR, NB * NH);
    attn_flash<<<ga, 256, ATTN_SMEM>>>();

    dim3 g2(NC / 128, (MROWS + 127) / 128);
    gemm_mma<<<g2, 256, GEMM_SMEM>>>((bf16*)pAhi, (bf16*)pAlo, (bf16*)pWpHi, (bf16*)pWpLo,
                                     b_proj, out, nullptr, nullptr,
                                     MROWS, NC, 0);
}

// round 7
// speedup vs baseline: 3.6610x; 1.1172x over previous
#include <cuda_runtime.h>
#include <cuda_bf16.h>
#include <cstdint>

// ---------------------------------------------------------------------------
// CrossOnlyAttention  (B=64, T=469, C=1024, H=16, hd=64)
// Round 7: 3-stage cp.async rings (1 sync/chunk) in GEMM and attention.
// GEMM smem tiles: unpadded 64B rows + XOR swizzle (chunk ^= (row>>1)&3).
// ---------------------------------------------------------------------------

#define TSEQ   469
#define NB     64
#define NC     1024
#define NH     16
#define HD     64
#define MROWS  (NB * TSEQ)   // 30016
#define NQKV   (3 * NC)      // 3072
#define GK     1024

typedef __nv_bfloat16 bf16;

__device__ bf16 g_a_hi[(size_t)MROWS * NC];
__device__ bf16 g_a_lo[(size_t)MROWS * NC];
__device__ bf16 g_qkv_hi[(size_t)MROWS * NQKV];
__device__ bf16 g_qkv_lo[(size_t)MROWS * NQKV];
__device__ bf16 g_wq_hi[(size_t)NQKV * GK];
__device__ bf16 g_wq_lo[(size_t)NQKV * GK];
__device__ bf16 g_wp_hi[(size_t)NC * GK];
__device__ bf16 g_wp_lo[(size_t)NC * GK];

// ---------------------------------------------------------------------------
// helpers
// ---------------------------------------------------------------------------
__device__ __forceinline__ uint32_t smem_u32(const void* p) {
    uint32_t a;
    asm("{ .reg .u64 t; cvta.to.shared.u64 t, %1; cvt.u32.u64 %0, t; }" : "=r"(a) : "l"(p));
    return a;
}

#define CP_ASYNC16(dst, src, sz) \
    asm volatile("cp.async.cg.shared.global [%0], [%1], 16, %2;" \
                 :: "r"(dst), "l"(src), "r"(sz) : "memory")
#define CP_COMMIT() asm volatile("cp.async.commit_group;" ::: "memory")
#define CP_WAIT(N)  asm volatile("cp.async.wait_group %0;" :: "n"(N) : "memory")

__device__ __forceinline__ void ldmatrix_x4(uint32_t* r, uint32_t addr) {
    asm volatile("ldmatrix.sync.aligned.m8n8.x4.shared.b16 {%0,%1,%2,%3}, [%4];"
                 : "=r"(r[0]), "=r"(r[1]), "=r"(r[2]), "=r"(r[3]) : "r"(addr));
}
__device__ __forceinline__ void ldmatrix_x4_trans(uint32_t* r, uint32_t addr) {
    asm volatile("ldmatrix.sync.aligned.m8n8.x4.trans.shared.b16 {%0,%1,%2,%3}, [%4];"
                 : "=r"(r[0]), "=r"(r[1]), "=r"(r[2]), "=r"(r[3]) : "r"(addr));
}
__device__ __forceinline__ void mma_bf16(float* c, const uint32_t* a, const uint32_t* b) {
    asm volatile("mma.sync.aligned.m16n8k16.row.col.f32.bf16.bf16.f32 "
                 "{%0,%1,%2,%3},{%4,%5,%6,%7},{%8,%9},{%0,%1,%2,%3};"
                 : "+f"(c[0]), "+f"(c[1]), "+f"(c[2]), "+f"(c[3])
                 : "r"(a[0]), "r"(a[1]), "r"(a[2]), "r"(a[3]), "r"(b[0]), "r"(b[1]));
}

__device__ __forceinline__ void split2(float v, bf16& h, bf16& l) {
    h = __float2bfloat16(v);
    l = __float2bfloat16(v - __bfloat162float(h));
}
__device__ __forceinline__ void pack_split(float a, float b, uint32_t& hi, uint32_t& lo) {
    bf16 ha, la, hb, lb;
    split2(a, ha, la); split2(b, hb, lb);
    hi = ((uint32_t)__bfloat16_as_ushort(hb) << 16) | __bfloat16_as_ushort(ha);
    lo = ((uint32_t)__bfloat16_as_ushort(lb) << 16) | __bfloat16_as_ushort(la);
}

// ---------------------------------------------------------------------------
// conversion kernels (unchanged)
// ---------------------------------------------------------------------------
__global__ void split_fp32(const float* __restrict__ src,
                           bf16* __restrict__ hi, bf16* __restrict__ lo, size_t n4)
{
    size_t i = (size_t)blockIdx.x * blockDim.x + threadIdx.x;
    if (i >= n4) return;
    float4 v = ((const float4*)src)[i];
    float vv[4] = {v.x, v.y, v.z, v.w};
    __align__(8) bf16 h[4], l[4];
#pragma unroll
    for (int q = 0; q < 4; q++) split2(vv[q], h[q], l[q]);
    ((uint2*)hi)[i] = *(uint2*)h;
    ((uint2*)lo)[i] = *(uint2*)l;
}

__global__ void transpose_split(const float* __restrict__ src,
                                bf16* __restrict__ dhi, bf16* __restrict__ dlo,
                                int K, int N)
{
    __shared__ float tile[32][33];
    const int n0 = blockIdx.x * 32, k0 = blockIdx.y * 32;
    const int tx = threadIdx.x & 31, ty0 = threadIdx.x >> 5;
#pragma unroll
    for (int i = 0; i < 4; i++) {
        int ty = ty0 + i * 8;
        tile[ty][tx] = src[(size_t)(k0 + ty) * N + n0 + tx];
    }
    __syncthreads();
#pragma unroll
    for (int i = 0; i < 4; i++) {
        int ty = ty0 + i * 8;
        float v = tile[tx][ty];
        bf16 h, l; split2(v, h, l);
        dhi[(size_t)(n0 + ty) * K + k0 + tx] = h;
        dlo[(size_t)(n0 + ty) * K + k0 + tx] = l;
    }
}

// ---------------------------------------------------------------------------
// mma.sync GEMM: 128x128 CTA tile, BK=32, 8 warps 2x4, 2 CTAs/SM,
// 3-stage cp.async ring, XOR-swizzled 64B-row smem tiles.
// ---------------------------------------------------------------------------
#define BK        32
#define NCHUNK    (GK / BK)
#define TILE_BYTES 8192                  // 128 rows x 64 B
#define STAGE_BYTES (4 * TILE_BYTES)     // 32768
#define GEMM_SMEM  (3 * STAGE_BYTES)     // 98304

// swizzled store: element (r, chunk seg) -> r*64 + ((seg ^ ((r>>1)&3))*16)
__device__ __forceinline__ void tile_cp(const bf16* __restrict__ src,
                                        int row0, int maxrow, int k0,
                                        uint32_t sdst, int tid)
{
#pragma unroll
    for (int i = 0; i < 2; i++) {
        const int idx = tid + i * 256;       // 0..511
        const int r = idx >> 2, seg = idx & 3;
        const int gr = row0 + r;
        const int ok = (gr < maxrow) ? 16 : 0;
        const bf16* gp = src + (size_t)min(gr, maxrow - 1) * GK + k0 + seg * 8;
        CP_ASYNC16(sdst + r * 64 + ((seg ^ ((r >> 1) & 3)) << 4), gp, ok);
    }
}

__global__ void __launch_bounds__(256, 2)
gemm_mma(const bf16* __restrict__ Ah, const bf16* __restrict__ Al,
         const bf16* __restrict__ Bh, const bf16* __restrict__ Bl,
         const float* __restrict__ bias,
         float* __restrict__ outF, bf16* __restrict__ outHi, bf16* __restrict__ outLo,
         int M, int N, int splitOut)
{
    extern __shared__ char smem[];
    const uint32_t sbase = smem_u32(smem);
    const int tid = threadIdx.x, wid = tid >> 5, lane = tid & 31;
    const int warpM = wid >> 2, warpN = wid & 3;
    const int n0 = blockIdx.x * 128, m0 = blockIdx.y * 128;

    float acc[4][4][4];
#pragma unroll
    for (int i = 0; i < 4; i++)
#pragma unroll
        for (int j = 0; j < 4; j++)
#pragma unroll
            for (int q = 0; q < 4; q++) acc[i][j][q] = 0.f;

    // per-lane swizzled addressing (swizzle term invariant across mi/np/ks)
    const uint32_t swzA = ((lane & 15) >> 1) & 3;
    const uint32_t swzB = ((lane & 7) >> 1) & 3;
    const uint32_t aBase = (uint32_t)(warpM * 64 + (lane & 15)) * 64;
    const uint32_t bBase = (uint32_t)(warpN * 32 + (lane & 7) + ((lane >> 4) << 3)) * 64;
    uint32_t aChunk[2], bChunk[2];
#pragma unroll
    for (int ks = 0; ks < 2; ks++) {
        aChunk[ks] = (((lane >> 4) + ks * 2) ^ swzA) << 4;
        bChunk[ks] = ((((lane >> 3) & 1) + ks * 2) ^ swzB) << 4;
    }

    // prologue: stages 0 and 1
    tile_cp(Ah, m0, M, 0, sbase + 0 * TILE_BYTES, tid);
    tile_cp(Al, m0, M, 0, sbase + 1 * TILE_BYTES, tid);
    tile_cp(Bh, n0, N, 0, sbase + 2 * TILE_BYTES, tid);
    tile_cp(Bl, n0, N, 0, sbase + 3 * TILE_BYTES, tid);
    CP_COMMIT();
    {
        const uint32_t st = sbase + STAGE_BYTES;
        tile_cp(Ah, m0, M, BK, st + 0 * TILE_BYTES, tid);
        tile_cp(Al, m0, M, BK, st + 1 * TILE_BYTES, tid);
        tile_cp(Bh, n0, N, BK, st + 2 * TILE_BYTES, tid);
        tile_cp(Bl, n0, N, BK, st + 3 * TILE_BYTES, tid);
        CP_COMMIT();
    }

    for (int c = 0; c < NCHUNK; c++) {
        if (c + 1 < NCHUNK) { CP_WAIT(1); } else { CP_WAIT(0); }
        __syncthreads();           // stage c ready; all warps done with stage c-1

        if (c + 2 < NCHUNK) {      // refill stage (c+2)%3 (was c-1's buffer)
            const uint32_t st = sbase + ((c + 2) % 3) * STAGE_BYTES;
            const int k0 = (c + 2) * BK;
            tile_cp(Ah, m0, M, k0, st + 0 * TILE_BYTES, tid);
            tile_cp(Al, m0, M, k0, st + 1 * TILE_BYTES, tid);
            tile_cp(Bh, n0, N, k0, st + 2 * TILE_BYTES, tid);
            tile_cp(Bl, n0, N, k0, st + 3 * TILE_BYTES, tid);
            CP_COMMIT();
        }

        const uint32_t st = sbase + (c % 3) * STAGE_BYTES;
        const uint32_t sAh = st, sAl = st + TILE_BYTES;
        const uint32_t sBh = st + 2 * TILE_BYTES, sBl = st + 3 * TILE_BYTES;

#pragma unroll
        for (int ks = 0; ks < 2; ks++) {
            uint32_t bh4[2][4], bl4[2][4];
#pragma unroll
            for (int np = 0; np < 2; np++) {
                const uint32_t bo = bBase + (uint32_t)(np * 16) * 64 + bChunk[ks];
                ldmatrix_x4(bh4[np], sBh + bo);
                ldmatrix_x4(bl4[np], sBl + bo);
            }
#pragma unroll
            for (int mi = 0; mi < 4; mi++) {
                const uint32_t ao = aBase + (uint32_t)(mi * 16) * 64 + aChunk[ks];
                uint32_t ah[4], al[4];
                ldmatrix_x4(ah, sAh + ao);
                ldmatrix_x4(al, sAl + ao);
#pragma unroll
                for (int ni = 0; ni < 4; ni++) {
                    const uint32_t* pbh = &bh4[ni >> 1][(ni & 1) * 2];
                    const uint32_t* pbl = &bl4[ni >> 1][(ni & 1) * 2];
                    mma_bf16(acc[mi][ni], ah, pbh);
                    mma_bf16(acc[mi][ni], ah, pbl);
                    mma_bf16(acc[mi][ni], al, pbh);
                }
            }
        }
    }

    const int cBase = n0 + warpN * 32 + (lane & 3) * 2;
    const int rBase = m0 + warpM * 64 + (lane >> 2);
#pragma unroll
    for (int mi = 0; mi < 4; mi++) {
#pragma unroll
        for (int ni = 0; ni < 4; ni++) {
            const int col = cBase + ni * 8;
            const float b0 = bias[col], b1 = bias[col + 1];
#pragma unroll
            for (int half = 0; half < 2; half++) {
                const int r = rBase + mi * 16 + half * 8;
                if (r >= M) continue;
                const float v0 = acc[mi][ni][half * 2 + 0] + b0;
                const float v1 = acc[mi][ni][half * 2 + 1] + b1;
                const size_t o = (size_t)r * N + col;
                if (splitOut) {
                    bf16 h0, l0, h1, l1;
                    split2(v0, h0, l0); split2(v1, h1, l1);
                    __nv_bfloat162 hh; hh.x = h0; hh.y = h1;
                    __nv_bfloat162 ll; ll.x = l0; ll.y = l1;
                    *(__nv_bfloat162*)(outHi + o) = hh;
                    *(__nv_bfloat162*)(outLo + o) = ll;
                } else {
                    *(float2*)(outF + o) = make_float2(v0, v1);
                }
            }
        }
    }
}

// ---------------------------------------------------------------------------
// flash attention: 128 q-rows/CTA, online softmax, 3-stage K/V ring.
// ---------------------------------------------------------------------------
#define AQR    128
#define NKB    8
#define APB    144                 // smem row pitch bytes (conflict-free)

#define OFF_QH   0
#define OFF_QL   (128 * APB)                 // 18432
#define OFF_KV   (2 * 128 * APB)             // 36864
#define KVSTG    (4 * 64 * APB)              // 36864: Kh,Kl,Vh,Vl
#define ATTN_SMEM (OFF_KV + 3 * KVSTG)       // 147456

__device__ __forceinline__ float cross_bias(int i, int j)
{
    if (i == 0 || j == 0) return 1.0f;
    return ((i <= 234) != (j <= 234)) ? 1.0f : 0.0f;
}

__device__ __forceinline__ void kv_stage(const bf16* khg, const bf16* klg,
                                         const bf16* vhg, const bf16* vlg,
                                         int j0, uint32_t buf, int tid)
{
#pragma unroll
    for (int i = 0; i < 2; i++) {
        const int idx = tid + i * 256;
        const int r = idx >> 3, seg = idx & 7;
        const int ok = (j0 + r < TSEQ) ? 16 : 0;
        const size_t g = (size_t)(j0 + r) * NQKV + seg * 8;
        const uint32_t s = buf + r * APB + seg * 16;
        CP_ASYNC16(s,                khg + g, ok);
        CP_ASYNC16(s + 64 * APB,     klg + g, ok);
        CP_ASYNC16(s + 2 * 64 * APB, vhg + g, ok);
        CP_ASYNC16(s + 3 * 64 * APB, vlg + g, ok);
    }
}

__global__ void __launch_bounds__(256, 1)
attn_flash()
{
    extern __shared__ char smem[];
    const uint32_t sbase = smem_u32(smem);

    const int tid = threadIdx.x, wid = tid >> 5, lane = tid & 31;
    const int bh = blockIdx.y;
    const int b  = bh >> 4, h = bh & 15;
    const int q0 = blockIdx.x * AQR;

    const size_t rowb = (size_t)b * TSEQ * NQKV + h * HD;
    const bf16* qhg = g_qkv_hi + rowb;
    const bf16* qlg = g_qkv_lo + rowb;
    const bf16* khg = qhg + NC;
    const bf16* klg = qlg + NC;
    const bf16* vhg = qhg + 2 * NC;
    const bf16* vlg = qlg + 2 * NC;

    // prologue: Q + KV0 (group 0), KV1 (group 1)
#pragma unroll
    for (int i = 0; i < 4; i++) {
        const int idx = tid + i * 256;
        const int r = idx >> 3, seg = idx & 7;
        const int ok = (q0 + r < TSEQ) ? 16 : 0;
        const size_t g = (size_t)(q0 + r) * NQKV + seg * 8;
        CP_ASYNC16(sbase + OFF_QH + r * APB + seg * 16, qhg + g, ok);
        CP_ASYNC16(sbase + OFF_QL + r * APB + seg * 16, qlg + g, ok);
    }
    kv_stage(khg, klg, vhg, vlg, 0, sbase + OFF_KV, tid);
    CP_COMMIT();
    kv_stage(khg, klg, vhg, vlg, 64, sbase + OFF_KV + KVSTG, tid);
    CP_COMMIT();

    const uint32_t aRowQ = (uint32_t)(wid * 16 + (lane & 15)) * APB;
    const uint32_t aColQ = (uint32_t)((lane >> 4) * 8) * 2;
    const uint32_t kRow4 = (uint32_t)((lane & 7) + ((lane >> 4) << 3)) * APB;
    const uint32_t kColB = (uint32_t)(((lane >> 3) & 1) * 8) * 2;
    const uint32_t vRow4 = (uint32_t)((lane & 7) + ((lane >> 3) & 1) * 8) * APB;
    const uint32_t vCol4 = (uint32_t)((lane >> 4) << 3) * 2;

    uint32_t qh[4][4], ql[4][4];
    float yc[8][4];
    float m_run[2] = {-1e30f, -1e30f};
    float s_run[2] = {0.f, 0.f};
#pragma unroll
    for (int ni = 0; ni < 8; ni++)
#pragma unroll
        for (int q = 0; q < 4; q++) yc[ni][q] = 0.f;

    for (int c = 0; c < NKB; c++) {
        if (c + 1 < NKB) { CP_WAIT(1); } else { CP_WAIT(0); }
        __syncthreads();

        if (c + 2 < NKB) {
            kv_stage(khg, klg, vhg, vlg, (c + 2) * 64,
                     sbase + OFF_KV + ((c + 2) % 3) * KVSTG, tid);
            CP_COMMIT();
        }

        if (c == 0) {
#pragma unroll
            for (int ks = 0; ks < 4; ks++) {
                const uint32_t ao = aRowQ + aColQ + ks * 32;
                ldmatrix_x4(qh[ks], sbase + OFF_QH + ao);
                ldmatrix_x4(ql[ks], sbase + OFF_QL + ao);
            }
        }

        const uint32_t stg = sbase + OFF_KV + (c % 3) * KVSTG;
        const uint32_t skh = stg, skl = stg + 64 * APB;
        const uint32_t svh = stg + 2 * 64 * APB, svl = stg + 3 * 64 * APB;

        // ---- S = Q K^T ----
        float sc[8][4];
#pragma unroll
        for (int ni = 0; ni < 8; ni++)
#pragma unroll
            for (int q = 0; q < 4; q++) sc[ni][q] = 0.f;

#pragma unroll
        for (int ks = 0; ks < 4; ks++) {
#pragma unroll
            for (int np = 0; np < 4; np++) {
                uint32_t kh4[4], kl4[4];
                const uint32_t bo = kRow4 + (uint32_t)(np * 16) * APB + kColB + ks * 32;
                ldmatrix_x4(kh4, skh + bo);
                ldmatrix_x4(kl4, skl + bo);
#pragma unroll
                for (int t = 0; t < 2; t++) {
                    mma_bf16(sc[np * 2 + t], qh[ks], &kh4[t * 2]);
                    mma_bf16(sc[np * 2 + t], qh[ks], &kl4[t * 2]);
                    mma_bf16(sc[np * 2 + t], ql[ks], &kh4[t * 2]);
                }
            }
        }

        // ---- scale + bias + OOB mask ----
        const int j0 = c * 64;
#pragma unroll
        for (int ni = 0; ni < 8; ni++) {
#pragma unroll
            for (int q = 0; q < 4; q++) {
                const int e = q & 1, hh = q >> 1;
                const int jg = j0 + ni * 8 + (lane & 3) * 2 + e;
                const int qi = q0 + wid * 16 + (lane >> 2) + hh * 8;
                const float v = sc[ni][q] * 0.125f + cross_bias(qi, jg);
                sc[ni][q] = (jg < TSEQ) ? v : -1e30f;
            }
        }

        // ---- online softmax ----
#pragma unroll
        for (int hh = 0; hh < 2; hh++) {
            float mb = -1e30f;
#pragma unroll
            for (int ni = 0; ni < 8; ni++)
                mb = fmaxf(mb, fmaxf(sc[ni][hh * 2], sc[ni][hh * 2 + 1]));
            mb = fmaxf(mb, __shfl_xor_sync(0xffffffffu, mb, 1));
            mb = fmaxf(mb, __shfl_xor_sync(0xffffffffu, mb, 2));
            const float mn = fmaxf(m_run[hh], mb);
            const float f = __expf(m_run[hh] - mn);
            m_run[hh] = mn;
            float sb = 0.f;
#pragma unroll
            for (int ni = 0; ni < 8; ni++) {
                const float p0 = __expf(sc[ni][hh * 2] - mn);
                const float p1 = __expf(sc[ni][hh * 2 + 1] - mn);
                sc[ni][hh * 2] = p0; sc[ni][hh * 2 + 1] = p1;
                sb += p0 + p1;
            }
            sb += __shfl_xor_sync(0xffffffffu, sb, 1);
            sb += __shfl_xor_sync(0xffffffffu, sb, 2);
            s_run[hh] = s_run[hh] * f + sb;
#pragma unroll
            for (int ni = 0; ni < 8; ni++) {
                yc[ni][hh * 2]     *= f;
                yc[ni][hh * 2 + 1] *= f;
            }
        }

        // ---- Y += P V ----
#pragma unroll
        for (int kk = 0; kk < 4; kk++) {
            uint32_t pah[4], pal[4];
#pragma unroll
            for (int t = 0; t < 2; t++) {
                const float* s0 = sc[kk * 2 + t];
                pack_split(s0[0], s0[1], pah[t * 2 + 0], pal[t * 2 + 0]);
                pack_split(s0[2], s0[3], pah[t * 2 + 1], pal[t * 2 + 1]);
            }
#pragma unroll
            for (int np = 0; np < 4; np++) {
                uint32_t vh4[4], vl4[4];
                const uint32_t vo = vRow4 + (uint32_t)(kk * 16) * APB
                                  + (uint32_t)(np * 16) * 2 + vCol4;
                ldmatrix_x4_trans(vh4, svh + vo);
                ldmatrix_x4_trans(vl4, svl + vo);
#pragma unroll
                for (int t = 0; t < 2; t++) {
                    mma_bf16(yc[np * 2 + t], pah, &vh4[t * 2]);
                    mma_bf16(yc[np * 2 + t], pah, &vl4[t * 2]);
                    mma_bf16(yc[np * 2 + t], pal, &vh4[t * 2]);
                }
            }
        }
    }

    // ---- epilogue ----
#pragma unroll
    for (int hh = 0; hh < 2; hh++) {
        const float ri = 1.0f / s_run[hh];
        const int r = wid * 16 + (lane >> 2) + hh * 8;
        const int t = q0 + r;
        if (t >= TSEQ) continue;
        const size_t base = ((size_t)b * TSEQ + t) * NC + h * HD;
#pragma unroll
        for (int ni = 0; ni < 8; ni++) {
            const int d = ni * 8 + (lane & 3) * 2;
            const float v0 = yc[ni][hh * 2] * ri;
            const float v1 = yc[ni][hh * 2 + 1] * ri;
            bf16 h0, l0, h1, l1;
            split2(v0, h0, l0); split2(v1, h1, l1);
            __nv_bfloat162 hv; hv.x = h0; hv.y = h1;
            __nv_bfloat162 lv; lv.x = l0; lv.y = l1;
            *(__nv_bfloat162*)(g_a_hi + base + d) = hv;
            *(__nv_bfloat162*)(g_a_lo + base + d) = lv;
        }
    }
}

// ---------------------------------------------------------------------------
extern "C" void kernel_launch(void* const* d_in, const int* in_sizes, int n_in,
                              void* d_out, int out_size)
{
    const float* x      = (const float*)d_in[0];
    const float* W_attn = (const float*)d_in[1];
    const float* b_attn = (const float*)d_in[2];
    const float* W_proj = (const float*)d_in[3];
    const float* b_proj = (const float*)d_in[4];
    float* out = (float*)d_out;

    cudaFuncSetAttribute(gemm_mma, cudaFuncAttributeMaxDynamicSharedMemorySize, GEMM_SMEM);
    cudaFuncSetAttribute(attn_flash, cudaFuncAttributeMaxDynamicSharedMemorySize, ATTN_SMEM);

    void *pAhi, *pAlo, *pQhi, *pQlo, *pWqHi, *pWqLo, *pWpHi, *pWpLo;
    cudaGetSymbolAddress(&pAhi,  g_a_hi);
    cudaGetSymbolAddress(&pAlo,  g_a_lo);
    cudaGetSymbolAddress(&pQhi,  g_qkv_hi);
    cudaGetSymbolAddress(&pQlo,  g_qkv_lo);
    cudaGetSymbolAddress(&pWqHi, g_wq_hi);
    cudaGetSymbolAddress(&pWqLo, g_wq_lo);
    cudaGetSymbolAddress(&pWpHi, g_wp_hi);
    cudaGetSymbolAddress(&pWpLo, g_wp_lo);

    const size_t n4 = (size_t)MROWS * NC / 4;
    split_fp32<<<(int)((n4 + 255) / 256), 256>>>(x, (bf16*)pAhi, (bf16*)pAlo, n4);
    transpose_split<<<dim3(NQKV / 32, GK / 32), 256>>>(W_attn, (bf16*)pWqHi, (bf16*)pWqLo, GK, NQKV);
    transpose_split<<<dim3(NC / 32, GK / 32), 256>>>(W_proj, (bf16*)pWpHi, (bf16*)pWpLo, GK, NC);

    dim3 g1(NQKV / 128, (MROWS + 127) / 128);
    gemm_mma<<<g1, 256, GEMM_SMEM>>>((bf16*)pAhi, (bf16*)pAlo, (bf16*)pWqHi, (bf16*)pWqLo,
                                     b_attn, nullptr, (bf16*)pQhi, (bf16*)pQlo,
                                     MROWS, NQKV, 1);

    dim3 ga((TSEQ + AQR - 1) / AQR, NB * NH);
    attn_flash<<<ga, 256, ATTN_SMEM>>>();

    dim3 g2(NC / 128, (MROWS + 127) / 128);
    gemm_mma<<<g2, 256, GEMM_SMEM>>>((bf16*)pAhi, (bf16*)pAlo, (bf16*)pWpHi, (bf16*)pWpLo,
                                     b_proj, out, nullptr, nullptr,
                                     MROWS, NC, 0);
}

// round 8
// speedup vs baseline: 5.0181x; 1.3707x over previous
#include <cuda_runtime.h>
#include <cuda_bf16.h>
#include <cuda_fp16.h>
#include <cstdint>

// ---------------------------------------------------------------------------
// CrossOnlyAttention  (B=64, T=469, C=1024, H=16, hd=64)
// Round 8: fp16 2-product arithmetic. Activations single fp16; weights / K / V
// split fp16 hi/lo. C = A*Bh + A*Bl (2 MMAs per product, was 3).
// 3-stage cp.async rings retained.
// ---------------------------------------------------------------------------

#define TSEQ   469
#define NB     64
#define NC     1024
#define NH     16
#define HD     64
#define MROWS  (NB * TSEQ)   // 30016
#define NQKV   (3 * NC)      // 3072
#define GK     1024

typedef __half f16;

__device__ f16 g_a_h[(size_t)MROWS * NC];        // activations (x, then y), single
__device__ f16 g_qkv_h[(size_t)MROWS * NQKV];    // qkv hi
__device__ f16 g_qkv_l[(size_t)MROWS * NQKV];    // qkv lo (k/v corrections)
__device__ f16 g_wq_h[(size_t)NQKV * GK];
__device__ f16 g_wq_l[(size_t)NQKV * GK];
__device__ f16 g_wp_h[(size_t)NC * GK];
__device__ f16 g_wp_l[(size_t)NC * GK];

// ---------------------------------------------------------------------------
// helpers
// ---------------------------------------------------------------------------
__device__ __forceinline__ uint32_t smem_u32(const void* p) {
    uint32_t a;
    asm("{ .reg .u64 t; cvta.to.shared.u64 t, %1; cvt.u32.u64 %0, t; }" : "=r"(a) : "l"(p));
    return a;
}

#define CP_ASYNC16(dst, src, sz) \
    asm volatile("cp.async.cg.shared.global [%0], [%1], 16, %2;" \
                 :: "r"(dst), "l"(src), "r"(sz) : "memory")
#define CP_COMMIT() asm volatile("cp.async.commit_group;" ::: "memory")
#define CP_WAIT(N)  asm volatile("cp.async.wait_group %0;" :: "n"(N) : "memory")

__device__ __forceinline__ void ldmatrix_x4(uint32_t* r, uint32_t addr) {
    asm volatile("ldmatrix.sync.aligned.m8n8.x4.shared.b16 {%0,%1,%2,%3}, [%4];"
                 : "=r"(r[0]), "=r"(r[1]), "=r"(r[2]), "=r"(r[3]) : "r"(addr));
}
__device__ __forceinline__ void ldmatrix_x4_trans(uint32_t* r, uint32_t addr) {
    asm volatile("ldmatrix.sync.aligned.m8n8.x4.trans.shared.b16 {%0,%1,%2,%3}, [%4];"
                 : "=r"(r[0]), "=r"(r[1]), "=r"(r[2]), "=r"(r[3]) : "r"(addr));
}
__device__ __forceinline__ void mma_f16(float* c, const uint32_t* a, const uint32_t* b) {
    asm volatile("mma.sync.aligned.m16n8k16.row.col.f32.f16.f16.f32 "
                 "{%0,%1,%2,%3},{%4,%5,%6,%7},{%8,%9},{%0,%1,%2,%3};"
                 : "+f"(c[0]), "+f"(c[1]), "+f"(c[2]), "+f"(c[3])
                 : "r"(a[0]), "r"(a[1]), "r"(a[2]), "r"(a[3]), "r"(b[0]), "r"(b[1]));
}

__device__ __forceinline__ void split2h(float v, f16& h, f16& l) {
    h = __float2half_rn(v);
    l = __float2half_rn(v - __half2float(h));
}
__device__ __forceinline__ uint32_t pack_f16(float a, float b) {
    __half2 h = __floats2half2_rn(a, b);
    return *(uint32_t*)&h;
}

// ---------------------------------------------------------------------------
// conversion kernels
// ---------------------------------------------------------------------------
__global__ void cvt_f16(const float* __restrict__ src, f16* __restrict__ dst, size_t n4)
{
    size_t i = (size_t)blockIdx.x * blockDim.x + threadIdx.x;
    if (i >= n4) return;
    float4 v = ((const float4*)src)[i];
    __half2 a = __floats2half2_rn(v.x, v.y);
    __half2 b = __floats2half2_rn(v.z, v.w);
    uint2 o; o.x = *(uint32_t*)&a; o.y = *(uint32_t*)&b;
    ((uint2*)dst)[i] = o;
}

// src [K][N] fp32 -> dst [N][K] f16 hi/lo
__global__ void transpose_split_f16(const float* __restrict__ src,
                                    f16* __restrict__ dhi, f16* __restrict__ dlo,
                                    int K, int N)
{
    __shared__ float tile[32][33];
    const int n0 = blockIdx.x * 32, k0 = blockIdx.y * 32;
    const int tx = threadIdx.x & 31, ty0 = threadIdx.x >> 5;
#pragma unroll
    for (int i = 0; i < 4; i++) {
        int ty = ty0 + i * 8;
        tile[ty][tx] = src[(size_t)(k0 + ty) * N + n0 + tx];
    }
    __syncthreads();
#pragma unroll
    for (int i = 0; i < 4; i++) {
        int ty = ty0 + i * 8;
        float v = tile[tx][ty];
        f16 h, l; split2h(v, h, l);
        dhi[(size_t)(n0 + ty) * K + k0 + tx] = h;
        dlo[(size_t)(n0 + ty) * K + k0 + tx] = l;
    }
}

// ---------------------------------------------------------------------------
// fp16 2-product GEMM: out[M,N] = A[M,GK] @ (Bh+Bl)[N,GK]^T + bias
// 128x128 tile, BK=32, 3-stage ring, XOR-swizzled 64B-row tiles, 2 CTAs/SM.
// ---------------------------------------------------------------------------
#define BK        32
#define NCHUNK    (GK / BK)
#define TILE_BYTES 8192                  // 128 rows x 64 B
#define STAGE_BYTES (3 * TILE_BYTES)     // A, Bh, Bl = 24576
#define GEMM_SMEM  (3 * STAGE_BYTES)     // 73728

__device__ __forceinline__ void tile_cp(const f16* __restrict__ src,
                                        int row0, int maxrow, int k0,
                                        uint32_t sdst, int tid)
{
#pragma unroll
    for (int i = 0; i < 2; i++) {
        const int idx = tid + i * 256;       // 0..511
        const int r = idx >> 2, seg = idx & 3;
        const int gr = row0 + r;
        const int ok = (gr < maxrow) ? 16 : 0;
        const f16* gp = src + (size_t)min(gr, maxrow - 1) * GK + k0 + seg * 8;
        CP_ASYNC16(sdst + r * 64 + ((seg ^ ((r >> 1) & 3)) << 4), gp, ok);
    }
}

__global__ void __launch_bounds__(256, 2)
gemm_f16(const f16* __restrict__ A,
         const f16* __restrict__ Bh, const f16* __restrict__ Bl,
         const float* __restrict__ bias,
         float* __restrict__ outF, f16* __restrict__ outHi, f16* __restrict__ outLo,
         int M, int N, int splitOut)
{
    extern __shared__ char smem[];
    const uint32_t sbase = smem_u32(smem);
    const int tid = threadIdx.x, wid = tid >> 5, lane = tid & 31;
    const int warpM = wid >> 2, warpN = wid & 3;
    const int n0 = blockIdx.x * 128, m0 = blockIdx.y * 128;

    float acc[4][4][4];
#pragma unroll
    for (int i = 0; i < 4; i++)
#pragma unroll
        for (int j = 0; j < 4; j++)
#pragma unroll
            for (int q = 0; q < 4; q++) acc[i][j][q] = 0.f;

    const uint32_t swzA = ((lane & 15) >> 1) & 3;
    const uint32_t swzB = ((lane & 7) >> 1) & 3;
    const uint32_t aBase = (uint32_t)(warpM * 64 + (lane & 15)) * 64;
    const uint32_t bBase = (uint32_t)(warpN * 32 + (lane & 7) + ((lane >> 4) << 3)) * 64;
    uint32_t aChunk[2], bChunk[2];
#pragma unroll
    for (int ks = 0; ks < 2; ks++) {
        aChunk[ks] = (((lane >> 4) + ks * 2) ^ swzA) << 4;
        bChunk[ks] = ((((lane >> 3) & 1) + ks * 2) ^ swzB) << 4;
    }

    tile_cp(A,  m0, M, 0, sbase + 0 * TILE_BYTES, tid);
    tile_cp(Bh, n0, N, 0, sbase + 1 * TILE_BYTES, tid);
    tile_cp(Bl, n0, N, 0, sbase + 2 * TILE_BYTES, tid);
    CP_COMMIT();
    {
        const uint32_t st = sbase + STAGE_BYTES;
        tile_cp(A,  m0, M, BK, st + 0 * TILE_BYTES, tid);
        tile_cp(Bh, n0, N, BK, st + 1 * TILE_BYTES, tid);
        tile_cp(Bl, n0, N, BK, st + 2 * TILE_BYTES, tid);
        CP_COMMIT();
    }

    for (int c = 0; c < NCHUNK; c++) {
        if (c + 1 < NCHUNK) { CP_WAIT(1); } else { CP_WAIT(0); }
        __syncthreads();

        if (c + 2 < NCHUNK) {
            const uint32_t st = sbase + ((c + 2) % 3) * STAGE_BYTES;
            const int k0 = (c + 2) * BK;
            tile_cp(A,  m0, M, k0, st + 0 * TILE_BYTES, tid);
            tile_cp(Bh, n0, N, k0, st + 1 * TILE_BYTES, tid);
            tile_cp(Bl, n0, N, k0, st + 2 * TILE_BYTES, tid);
            CP_COMMIT();
        }

        const uint32_t st = sbase + (c % 3) * STAGE_BYTES;
        const uint32_t sA = st, sBh = st + TILE_BYTES, sBl = st + 2 * TILE_BYTES;

#pragma unroll
        for (int ks = 0; ks < 2; ks++) {
            uint32_t bh4[2][4], bl4[2][4];
#pragma unroll
            for (int np = 0; np < 2; np++) {
                const uint32_t bo = bBase + (uint32_t)(np * 16) * 64 + bChunk[ks];
                ldmatrix_x4(bh4[np], sBh + bo);
                ldmatrix_x4(bl4[np], sBl + bo);
            }
#pragma unroll
            for (int mi = 0; mi < 4; mi++) {
                const uint32_t ao = aBase + (uint32_t)(mi * 16) * 64 + aChunk[ks];
                uint32_t av[4];
                ldmatrix_x4(av, sA + ao);
#pragma unroll
                for (int ni = 0; ni < 4; ni++) {
                    mma_f16(acc[mi][ni], av, &bh4[ni >> 1][(ni & 1) * 2]);
                    mma_f16(acc[mi][ni], av, &bl4[ni >> 1][(ni & 1) * 2]);
                }
            }
        }
    }

    const int cBase = n0 + warpN * 32 + (lane & 3) * 2;
    const int rBase = m0 + warpM * 64 + (lane >> 2);
#pragma unroll
    for (int mi = 0; mi < 4; mi++) {
#pragma unroll
        for (int ni = 0; ni < 4; ni++) {
            const int col = cBase + ni * 8;
            const float b0 = bias[col], b1 = bias[col + 1];
#pragma unroll
            for (int half = 0; half < 2; half++) {
                const int r = rBase + mi * 16 + half * 8;
                if (r >= M) continue;
                const float v0 = acc[mi][ni][half * 2 + 0] + b0;
                const float v1 = acc[mi][ni][half * 2 + 1] + b1;
                const size_t o = (size_t)r * N + col;
                if (splitOut) {
                    f16 h0, l0, h1, l1;
                    split2h(v0, h0, l0); split2h(v1, h1, l1);
                    __half2 hh; hh.x = h0; hh.y = h1;
                    __half2 ll; ll.x = l0; ll.y = l1;
                    *(__half2*)(outHi + o) = hh;
                    *(__half2*)(outLo + o) = ll;
                } else {
                    *(float2*)(outF + o) = make_float2(v0, v1);
                }
            }
        }
    }
}

// ---------------------------------------------------------------------------
// flash attention: Q single fp16, K/V split fp16 hi/lo, P single fp16.
// 128 q-rows/CTA, online softmax, 3-stage K/V ring.
// ---------------------------------------------------------------------------
#define AQR    128
#define NKB    8
#define APB    144

#define OFF_QH   0
#define OFF_KV   (128 * APB)                 // 18432
#define KVSTG    (4 * 64 * APB)              // 36864: Kh,Kl,Vh,Vl
#define ATTN_SMEM (OFF_KV + 3 * KVSTG)       // 129024

__device__ __forceinline__ float cross_bias(int i, int j)
{
    if (i == 0 || j == 0) return 1.0f;
    return ((i <= 234) != (j <= 234)) ? 1.0f : 0.0f;
}

__device__ __forceinline__ void kv_stage(const f16* khg, const f16* klg,
                                         const f16* vhg, const f16* vlg,
                                         int j0, uint32_t buf, int tid)
{
#pragma unroll
    for (int i = 0; i < 2; i++) {
        const int idx = tid + i * 256;
        const int r = idx >> 3, seg = idx & 7;
        const int ok = (j0 + r < TSEQ) ? 16 : 0;
        const size_t g = (size_t)(j0 + r) * NQKV + seg * 8;
        const uint32_t s = buf + r * APB + seg * 16;
        CP_ASYNC16(s,                khg + g, ok);
        CP_ASYNC16(s + 64 * APB,     klg + g, ok);
        CP_ASYNC16(s + 2 * 64 * APB, vhg + g, ok);
        CP_ASYNC16(s + 3 * 64 * APB, vlg + g, ok);
    }
}

__global__ void __launch_bounds__(256, 1)
attn_flash()
{
    extern __shared__ char smem[];
    const uint32_t sbase = smem_u32(smem);

    const int tid = threadIdx.x, wid = tid >> 5, lane = tid & 31;
    const int bh = blockIdx.y;
    const int b  = bh >> 4, h = bh & 15;
    const int q0 = blockIdx.x * AQR;

    const size_t rowb = (size_t)b * TSEQ * NQKV + h * HD;
    const f16* qhg = g_qkv_h + rowb;
    const f16* khg = qhg + NC;
    const f16* klg = g_qkv_l + rowb + NC;
    const f16* vhg = qhg + 2 * NC;
    const f16* vlg = g_qkv_l + rowb + 2 * NC;

    // prologue: Q (single) + KV0, KV1
#pragma unroll
    for (int i = 0; i < 2; i++) {
        const int idx = tid + i * 256;
        const int r = idx >> 1, seg = idx & 1;          // 2 x 16B per row... 64 f16 = 128B
        // 128 rows x 8 segs of 16B: need 1024 cp; use 4 iters of 256 below instead
    }
#pragma unroll
    for (int i = 0; i < 4; i++) {
        const int idx = tid + i * 256;                  // 0..1023
        const int r = idx >> 3, seg = idx & 7;
        const int ok = (q0 + r < TSEQ) ? 16 : 0;
        CP_ASYNC16(sbase + OFF_QH + r * APB + seg * 16,
                   qhg + (size_t)(q0 + r) * NQKV + seg * 8, ok);
    }
    kv_stage(khg, klg, vhg, vlg, 0, sbase + OFF_KV, tid);
    CP_COMMIT();
    kv_stage(khg, klg, vhg, vlg, 64, sbase + OFF_KV + KVSTG, tid);
    CP_COMMIT();

    const uint32_t aRowQ = (uint32_t)(wid * 16 + (lane & 15)) * APB;
    const uint32_t aColQ = (uint32_t)((lane >> 4) * 8) * 2;
    const uint32_t kRow4 = (uint32_t)((lane & 7) + ((lane >> 4) << 3)) * APB;
    const uint32_t kColB = (uint32_t)(((lane >> 3) & 1) * 8) * 2;
    const uint32_t vRow4 = (uint32_t)((lane & 7) + ((lane >> 3) & 1) * 8) * APB;
    const uint32_t vCol4 = (uint32_t)((lane >> 4) << 3) * 2;

    uint32_t qf[4][4];
    float yc[8][4];
    float m_run[2] = {-1e30f, -1e30f};
    float s_run[2] = {0.f, 0.f};
#pragma unroll
    for (int ni = 0; ni < 8; ni++)
#pragma unroll
        for (int q = 0; q < 4; q++) yc[ni][q] = 0.f;

    for (int c = 0; c < NKB; c++) {
        if (c + 1 < NKB) { CP_WAIT(1); } else { CP_WAIT(0); }
        __syncthreads();

        if (c + 2 < NKB) {
            kv_stage(khg, klg, vhg, vlg, (c + 2) * 64,
                     sbase + OFF_KV + ((c + 2) % 3) * KVSTG, tid);
            CP_COMMIT();
        }

        if (c == 0) {
#pragma unroll
            for (int ks = 0; ks < 4; ks++)
                ldmatrix_x4(qf[ks], sbase + OFF_QH + aRowQ + aColQ + ks * 32);
        }

        const uint32_t stg = sbase + OFF_KV + (c % 3) * KVSTG;
        const uint32_t skh = stg, skl = stg + 64 * APB;
        const uint32_t svh = stg + 2 * 64 * APB, svl = stg + 3 * 64 * APB;

        // ---- S = Q K^T ----
        float sc[8][4];
#pragma unroll
        for (int ni = 0; ni < 8; ni++)
#pragma unroll
            for (int q = 0; q < 4; q++) sc[ni][q] = 0.f;

#pragma unroll
        for (int ks = 0; ks < 4; ks++) {
#pragma unroll
            for (int np = 0; np < 4; np++) {
                uint32_t kh4[4], kl4[4];
                const uint32_t bo = kRow4 + (uint32_t)(np * 16) * APB + kColB + ks * 32;
                ldmatrix_x4(kh4, skh + bo);
                ldmatrix_x4(kl4, skl + bo);
#pragma unroll
                for (int t = 0; t < 2; t++) {
                    mma_f16(sc[np * 2 + t], qf[ks], &kh4[t * 2]);
                    mma_f16(sc[np * 2 + t], qf[ks], &kl4[t * 2]);
                }
            }
        }

        // ---- scale + bias + OOB mask ----
        const int j0 = c * 64;
#pragma unroll
        for (int ni = 0; ni < 8; ni++) {
#pragma unroll
            for (int q = 0; q < 4; q++) {
                const int e = q & 1, hh = q >> 1;
                const int jg = j0 + ni * 8 + (lane & 3) * 2 + e;
                const int qi = q0 + wid * 16 + (lane >> 2) + hh * 8;
                const float v = sc[ni][q] * 0.125f + cross_bias(qi, jg);
                sc[ni][q] = (jg < TSEQ) ? v : -1e30f;
            }
        }

        // ---- online softmax ----
#pragma unroll
        for (int hh = 0; hh < 2; hh++) {
            float mb = -1e30f;
#pragma unroll
            for (int ni = 0; ni < 8; ni++)
                mb = fmaxf(mb, fmaxf(sc[ni][hh * 2], sc[ni][hh * 2 + 1]));
            mb = fmaxf(mb, __shfl_xor_sync(0xffffffffu, mb, 1));
            mb = fmaxf(mb, __shfl_xor_sync(0xffffffffu, mb, 2));
            const float mn = fmaxf(m_run[hh], mb);
            const float f = __expf(m_run[hh] - mn);
            m_run[hh] = mn;
            float sb = 0.f;
#pragma unroll
            for (int ni = 0; ni < 8; ni++) {
                const float p0 = __expf(sc[ni][hh * 2] - mn);
                const float p1 = __expf(sc[ni][hh * 2 + 1] - mn);
                sc[ni][hh * 2] = p0; sc[ni][hh * 2 + 1] = p1;
                sb += p0 + p1;
            }
            sb += __shfl_xor_sync(0xffffffffu, sb, 1);
            sb += __shfl_xor_sync(0xffffffffu, sb, 2);
            s_run[hh] = s_run[hh] * f + sb;
#pragma unroll
            for (int ni = 0; ni < 8; ni++) {
                yc[ni][hh * 2]     *= f;
                yc[ni][hh * 2 + 1] *= f;
            }
        }

        // ---- Y += P V (P single fp16 from registers) ----
#pragma unroll
        for (int kk = 0; kk < 4; kk++) {
            uint32_t pa[4];
#pragma unroll
            for (int t = 0; t < 2; t++) {
                const float* s0 = sc[kk * 2 + t];
                pa[t * 2 + 0] = pack_f16(s0[0], s0[1]);
                pa[t * 2 + 1] = pack_f16(s0[2], s0[3]);
            }
#pragma unroll
            for (int np = 0; np < 4; np++) {
                uint32_t vh4[4], vl4[4];
                const uint32_t vo = vRow4 + (uint32_t)(kk * 16) * APB
                                  + (uint32_t)(np * 16) * 2 + vCol4;
                ldmatrix_x4_trans(vh4, svh + vo);
                ldmatrix_x4_trans(vl4, svl + vo);
#pragma unroll
                for (int t = 0; t < 2; t++) {
                    mma_f16(yc[np * 2 + t], pa, &vh4[t * 2]);
                    mma_f16(yc[np * 2 + t], pa, &vl4[t * 2]);
                }
            }
        }
    }

    // ---- epilogue: normalize, store y as single fp16 ----
#pragma unroll
    for (int hh = 0; hh < 2; hh++) {
        const float ri = 1.0f / s_run[hh];
        const int r = wid * 16 + (lane >> 2) + hh * 8;
        const int t = q0 + r;
        if (t >= TSEQ) continue;
        const size_t base = ((size_t)b * TSEQ + t) * NC + h * HD;
#pragma unroll
        for (int ni = 0; ni < 8; ni++) {
            const int d = ni * 8 + (lane & 3) * 2;
            __half2 hv = __floats2half2_rn(yc[ni][hh * 2] * ri, yc[ni][hh * 2 + 1] * ri);
            *(__half2*)(g_a_h + base + d) = hv;
        }
    }
}

// ---------------------------------------------------------------------------
extern "C" void kernel_launch(void* const* d_in, const int* in_sizes, int n_in,
                              void* d_out, int out_size)
{
    const float* x      = (const float*)d_in[0];
    const float* W_attn = (const float*)d_in[1];
    const float* b_attn = (const float*)d_in[2];
    const float* W_proj = (const float*)d_in[3];
    const float* b_proj = (const float*)d_in[4];
    float* out = (float*)d_out;

    cudaFuncSetAttribute(gemm_f16, cudaFuncAttributeMaxDynamicSharedMemorySize, GEMM_SMEM);
    cudaFuncSetAttribute(attn_flash, cudaFuncAttributeMaxDynamicSharedMemorySize, ATTN_SMEM);

    void *pAh, *pQh, *pQl, *pWqH, *pWqL, *pWpH, *pWpL;
    cudaGetSymbolAddress(&pAh,  g_a_h);
    cudaGetSymbolAddress(&pQh,  g_qkv_h);
    cudaGetSymbolAddress(&pQl,  g_qkv_l);
    cudaGetSymbolAddress(&pWqH, g_wq_h);
    cudaGetSymbolAddress(&pWqL, g_wq_l);
    cudaGetSymbolAddress(&pWpH, g_wp_h);
    cudaGetSymbolAddress(&pWpL, g_wp_l);

    const size_t n4 = (size_t)MROWS * NC / 4;
    cvt_f16<<<(int)((n4 + 255) / 256), 256>>>(x, (f16*)pAh, n4);
    transpose_split_f16<<<dim3(NQKV / 32, GK / 32), 256>>>(W_attn, (f16*)pWqH, (f16*)pWqL, GK, NQKV);
    transpose_split_f16<<<dim3(NC / 32, GK / 32), 256>>>(W_proj, (f16*)pWpH, (f16*)pWpL, GK, NC);

    // qkv = x @ W_attn + b_attn  (split fp16 output)
    dim3 g1(NQKV / 128, (MROWS + 127) / 128);
    gemm_f16<<<g1, 256, GEMM_SMEM>>>((f16*)pAh, (f16*)pWqH, (f16*)pWqL,
                                     b_attn, nullptr, (f16*)pQh, (f16*)pQl,
                                     MROWS, NQKV, 1);

    // attention (writes y single fp16 into g_a_h)
    dim3 ga((TSEQ + AQR - 1) / AQR, NB * NH);
    attn_flash<<<ga, 256, ATTN_SMEM>>>();

    // out = y @ W_proj + b_proj (fp32 output)
    dim3 g2(NC / 128, (MROWS + 127) / 128);
    gemm_f16<<<g2, 256, GEMM_SMEM>>>((f16*)pAh, (f16*)pWpH, (f16*)pWpL,
                                     b_proj, out, nullptr, nullptr,
                                     MROWS, NC, 0);
}

// round 9
// speedup vs baseline: 8.8690x; 1.7674x over previous
#include <cuda_runtime.h>
#include <cuda_fp16.h>
#include <cstdint>

// ---------------------------------------------------------------------------
// CrossOnlyAttention  (B=64, T=469, C=1024, H=16, hd=64)
// Round 9: pure fp16 arithmetic (1 MMA per product). GEMM: 4-stage ring.
// Attention: single-fp16 K/V, 2 CTAs/SM.
// ---------------------------------------------------------------------------

#define TSEQ   469
#define NB     64
#define NC     1024
#define NH     16
#define HD     64
#define MROWS  (NB * TSEQ)   // 30016
#define NQKV   (3 * NC)      // 3072
#define GK     1024

typedef __half f16;

__device__ f16 g_a_h[(size_t)MROWS * NC];        // activations (x, then y)
__device__ f16 g_qkv_h[(size_t)MROWS * NQKV];    // qkv
__device__ f16 g_wq_h[(size_t)NQKV * GK];        // W_attn^T
__device__ f16 g_wp_h[(size_t)NC * GK];          // W_proj^T

// ---------------------------------------------------------------------------
// helpers
// ---------------------------------------------------------------------------
__device__ __forceinline__ uint32_t smem_u32(const void* p) {
    uint32_t a;
    asm("{ .reg .u64 t; cvta.to.shared.u64 t, %1; cvt.u32.u64 %0, t; }" : "=r"(a) : "l"(p));
    return a;
}

#define CP_ASYNC16(dst, src, sz) \
    asm volatile("cp.async.cg.shared.global [%0], [%1], 16, %2;" \
                 :: "r"(dst), "l"(src), "r"(sz) : "memory")
#define CP_COMMIT() asm volatile("cp.async.commit_group;" ::: "memory")
#define CP_WAIT(N)  asm volatile("cp.async.wait_group %0;" :: "n"(N) : "memory")

__device__ __forceinline__ void ldmatrix_x4(uint32_t* r, uint32_t addr) {
    asm volatile("ldmatrix.sync.aligned.m8n8.x4.shared.b16 {%0,%1,%2,%3}, [%4];"
                 : "=r"(r[0]), "=r"(r[1]), "=r"(r[2]), "=r"(r[3]) : "r"(addr));
}
__device__ __forceinline__ void ldmatrix_x4_trans(uint32_t* r, uint32_t addr) {
    asm volatile("ldmatrix.sync.aligned.m8n8.x4.trans.shared.b16 {%0,%1,%2,%3}, [%4];"
                 : "=r"(r[0]), "=r"(r[1]), "=r"(r[2]), "=r"(r[3]) : "r"(addr));
}
__device__ __forceinline__ void mma_f16(float* c, const uint32_t* a, const uint32_t* b) {
    asm volatile("mma.sync.aligned.m16n8k16.row.col.f32.f16.f16.f32 "
                 "{%0,%1,%2,%3},{%4,%5,%6,%7},{%8,%9},{%0,%1,%2,%3};"
                 : "+f"(c[0]), "+f"(c[1]), "+f"(c[2]), "+f"(c[3])
                 : "r"(a[0]), "r"(a[1]), "r"(a[2]), "r"(a[3]), "r"(b[0]), "r"(b[1]));
}
__device__ __forceinline__ uint32_t pack_f16(float a, float b) {
    __half2 h = __floats2half2_rn(a, b);
    return *(uint32_t*)&h;
}

// ---------------------------------------------------------------------------
// conversion kernels
// ---------------------------------------------------------------------------
__global__ void cvt_f16(const float* __restrict__ src, f16* __restrict__ dst, size_t n4)
{
    size_t i = (size_t)blockIdx.x * blockDim.x + threadIdx.x;
    if (i >= n4) return;
    float4 v = ((const float4*)src)[i];
    __half2 a = __floats2half2_rn(v.x, v.y);
    __half2 b = __floats2half2_rn(v.z, v.w);
    uint2 o; o.x = *(uint32_t*)&a; o.y = *(uint32_t*)&b;
    ((uint2*)dst)[i] = o;
}

// src [K][N] fp32 -> dst [N][K] f16
__global__ void transpose_f16(const float* __restrict__ src,
                              f16* __restrict__ dst, int K, int N)
{
    __shared__ float tile[32][33];
    const int n0 = blockIdx.x * 32, k0 = blockIdx.y * 32;
    const int tx = threadIdx.x & 31, ty0 = threadIdx.x >> 5;
#pragma unroll
    for (int i = 0; i < 4; i++) {
        int ty = ty0 + i * 8;
        tile[ty][tx] = src[(size_t)(k0 + ty) * N + n0 + tx];
    }
    __syncthreads();
#pragma unroll
    for (int i = 0; i < 4; i++) {
        int ty = ty0 + i * 8;
        dst[(size_t)(n0 + ty) * K + k0 + tx] = __float2half_rn(tile[tx][ty]);
    }
}

// ---------------------------------------------------------------------------
// fp16 GEMM: out[M,N] = A[M,GK] @ B[N,GK]^T + bias
// 128x128 tile, BK=32, 4-stage cp.async ring, XOR-swizzled 64B rows, 2 CTAs/SM.
// ---------------------------------------------------------------------------
#define BK        32
#define NCHUNK    (GK / BK)
#define TILE_BYTES 8192                  // 128 rows x 64 B
#define STAGE_BYTES (2 * TILE_BYTES)     // A, B = 16384
#define GEMM_SMEM  (4 * STAGE_BYTES)     // 65536

__device__ __forceinline__ void tile_cp(const f16* __restrict__ src,
                                        int row0, int maxrow, int k0,
                                        uint32_t sdst, int tid)
{
#pragma unroll
    for (int i = 0; i < 2; i++) {
        const int idx = tid + i * 256;       // 0..511
        const int r = idx >> 2, seg = idx & 3;
        const int gr = row0 + r;
        const int ok = (gr < maxrow) ? 16 : 0;
        const f16* gp = src + (size_t)min(gr, maxrow - 1) * GK + k0 + seg * 8;
        CP_ASYNC16(sdst + r * 64 + ((seg ^ ((r >> 1) & 3)) << 4), gp, ok);
    }
}

__global__ void __launch_bounds__(256, 2)
gemm_f16(const f16* __restrict__ A, const f16* __restrict__ B,
         const float* __restrict__ bias,
         float* __restrict__ outF, f16* __restrict__ outH,
         int M, int N)
{
    extern __shared__ char smem[];
    const uint32_t sbase = smem_u32(smem);
    const int tid = threadIdx.x, wid = tid >> 5, lane = tid & 31;
    const int warpM = wid >> 2, warpN = wid & 3;
    const int n0 = blockIdx.x * 128, m0 = blockIdx.y * 128;

    float acc[4][4][4];
#pragma unroll
    for (int i = 0; i < 4; i++)
#pragma unroll
        for (int j = 0; j < 4; j++)
#pragma unroll
            for (int q = 0; q < 4; q++) acc[i][j][q] = 0.f;

    const uint32_t swzA = ((lane & 15) >> 1) & 3;
    const uint32_t swzB = ((lane & 7) >> 1) & 3;
    const uint32_t aBase = (uint32_t)(warpM * 64 + (lane & 15)) * 64;
    const uint32_t bBase = (uint32_t)(warpN * 32 + (lane & 7) + ((lane >> 4) << 3)) * 64;
    uint32_t aChunk[2], bChunk[2];
#pragma unroll
    for (int ks = 0; ks < 2; ks++) {
        aChunk[ks] = (((lane >> 4) + ks * 2) ^ swzA) << 4;
        bChunk[ks] = ((((lane >> 3) & 1) + ks * 2) ^ swzB) << 4;
    }

    // prologue: stages 0,1,2
#pragma unroll
    for (int s = 0; s < 3; s++) {
        const uint32_t st = sbase + s * STAGE_BYTES;
        tile_cp(A, m0, M, s * BK, st, tid);
        tile_cp(B, n0, N, s * BK, st + TILE_BYTES, tid);
        CP_COMMIT();
    }

    for (int c = 0; c < NCHUNK; c++) {
        if (c + 2 < NCHUNK)      { CP_WAIT(2); }
        else if (c + 1 < NCHUNK) { CP_WAIT(1); }
        else                     { CP_WAIT(0); }
        __syncthreads();

        if (c + 3 < NCHUNK) {
            const uint32_t st = sbase + ((c + 3) & 3) * STAGE_BYTES;
            const int k0 = (c + 3) * BK;
            tile_cp(A, m0, M, k0, st, tid);
            tile_cp(B, n0, N, k0, st + TILE_BYTES, tid);
            CP_COMMIT();
        }

        const uint32_t st = sbase + (c & 3) * STAGE_BYTES;
        const uint32_t sA = st, sB = st + TILE_BYTES;

#pragma unroll
        for (int ks = 0; ks < 2; ks++) {
            uint32_t b4[2][4];
#pragma unroll
            for (int np = 0; np < 2; np++) {
                const uint32_t bo = bBase + (uint32_t)(np * 16) * 64 + bChunk[ks];
                ldmatrix_x4(b4[np], sB + bo);
            }
#pragma unroll
            for (int mi = 0; mi < 4; mi++) {
                const uint32_t ao = aBase + (uint32_t)(mi * 16) * 64 + aChunk[ks];
                uint32_t av[4];
                ldmatrix_x4(av, sA + ao);
#pragma unroll
                for (int ni = 0; ni < 4; ni++)
                    mma_f16(acc[mi][ni], av, &b4[ni >> 1][(ni & 1) * 2]);
            }
        }
    }

    const int cBase = n0 + warpN * 32 + (lane & 3) * 2;
    const int rBase = m0 + warpM * 64 + (lane >> 2);
#pragma unroll
    for (int mi = 0; mi < 4; mi++) {
#pragma unroll
        for (int ni = 0; ni < 4; ni++) {
            const int col = cBase + ni * 8;
            const float b0 = bias[col], b1 = bias[col + 1];
#pragma unroll
            for (int half = 0; half < 2; half++) {
                const int r = rBase + mi * 16 + half * 8;
                if (r >= M) continue;
                const float v0 = acc[mi][ni][half * 2 + 0] + b0;
                const float v1 = acc[mi][ni][half * 2 + 1] + b1;
                const size_t o = (size_t)r * N + col;
                if (outH) {
                    __half2 hh = __floats2half2_rn(v0, v1);
                    *(__half2*)(outH + o) = hh;
                } else {
                    *(float2*)(outF + o) = make_float2(v0, v1);
                }
            }
        }
    }
}

// ---------------------------------------------------------------------------
// flash attention: all fp16 single, 128 q-rows/CTA, online softmax,
// 3-stage K/V ring, 2 CTAs/SM.
// ---------------------------------------------------------------------------
#define AQR    128
#define NKB    8
#define APB    144

#define OFF_QH   0
#define OFF_KV   (128 * APB)                 // 18432
#define KVSTG    (2 * 64 * APB)              // 18432: K, V
#define ATTN_SMEM (OFF_KV + 3 * KVSTG)       // 73728

__device__ __forceinline__ float cross_bias(int i, int j)
{
    if (i == 0 || j == 0) return 1.0f;
    return ((i <= 234) != (j <= 234)) ? 1.0f : 0.0f;
}

__device__ __forceinline__ void kv_stage(const f16* khg, const f16* vhg,
                                         int j0, uint32_t buf, int tid)
{
#pragma unroll
    for (int i = 0; i < 2; i++) {
        const int idx = tid + i * 256;
        const int r = idx >> 3, seg = idx & 7;
        const int ok = (j0 + r < TSEQ) ? 16 : 0;
        const size_t g = (size_t)(j0 + r) * NQKV + seg * 8;
        const uint32_t s = buf + r * APB + seg * 16;
        CP_ASYNC16(s,            khg + g, ok);
        CP_ASYNC16(s + 64 * APB, vhg + g, ok);
    }
}

__global__ void __launch_bounds__(256, 2)
attn_flash()
{
    extern __shared__ char smem[];
    const uint32_t sbase = smem_u32(smem);

    const int tid = threadIdx.x, wid = tid >> 5, lane = tid & 31;
    const int bh = blockIdx.y;
    const int b  = bh >> 4, h = bh & 15;
    const int q0 = blockIdx.x * AQR;

    const size_t rowb = (size_t)b * TSEQ * NQKV + h * HD;
    const f16* qhg = g_qkv_h + rowb;
    const f16* khg = qhg + NC;
    const f16* vhg = qhg + 2 * NC;

    // prologue: Q + KV0, KV1
#pragma unroll
    for (int i = 0; i < 4; i++) {
        const int idx = tid + i * 256;
        const int r = idx >> 3, seg = idx & 7;
        const int ok = (q0 + r < TSEQ) ? 16 : 0;
        CP_ASYNC16(sbase + OFF_QH + r * APB + seg * 16,
                   qhg + (size_t)(q0 + r) * NQKV + seg * 8, ok);
    }
    kv_stage(khg, vhg, 0, sbase + OFF_KV, tid);
    CP_COMMIT();
    kv_stage(khg, vhg, 64, sbase + OFF_KV + KVSTG, tid);
    CP_COMMIT();

    const uint32_t aRowQ = (uint32_t)(wid * 16 + (lane & 15)) * APB;
    const uint32_t aColQ = (uint32_t)((lane >> 4) * 8) * 2;
    const uint32_t kRow4 = (uint32_t)((lane & 7) + ((lane >> 4) << 3)) * APB;
    const uint32_t kColB = (uint32_t)(((lane >> 3) & 1) * 8) * 2;
    const uint32_t vRow4 = (uint32_t)((lane & 7) + ((lane >> 3) & 1) * 8) * APB;
    const uint32_t vCol4 = (uint32_t)((lane >> 4) << 3) * 2;

    uint32_t qf[4][4];
    float yc[8][4];
    float m_run[2] = {-1e30f, -1e30f};
    float s_run[2] = {0.f, 0.f};
#pragma unroll
    for (int ni = 0; ni < 8; ni++)
#pragma unroll
        for (int q = 0; q < 4; q++) yc[ni][q] = 0.f;

    for (int c = 0; c < NKB; c++) {
        if (c + 1 < NKB) { CP_WAIT(1); } else { CP_WAIT(0); }
        __syncthreads();

        if (c + 2 < NKB) {
            kv_stage(khg, vhg, (c + 2) * 64,
                     sbase + OFF_KV + ((c + 2) % 3) * KVSTG, tid);
            CP_COMMIT();
        }

        if (c == 0) {
#pragma unroll
            for (int ks = 0; ks < 4; ks++)
                ldmatrix_x4(qf[ks], sbase + OFF_QH + aRowQ + aColQ + ks * 32);
        }

        const uint32_t stg = sbase + OFF_KV + (c % 3) * KVSTG;
        const uint32_t skh = stg, svh = stg + 64 * APB;

        // ---- S = Q K^T ----
        float sc[8][4];
#pragma unroll
        for (int ni = 0; ni < 8; ni++)
#pragma unroll
            for (int q = 0; q < 4; q++) sc[ni][q] = 0.f;

#pragma unroll
        for (int ks = 0; ks < 4; ks++) {
#pragma unroll
            for (int np = 0; np < 4; np++) {
                uint32_t k4[4];
                const uint32_t bo = kRow4 + (uint32_t)(np * 16) * APB + kColB + ks * 32;
                ldmatrix_x4(k4, skh + bo);
                mma_f16(sc[np * 2 + 0], qf[ks], &k4[0]);
                mma_f16(sc[np * 2 + 1], qf[ks], &k4[2]);
            }
        }

        // ---- scale + bias + OOB mask ----
        const int j0 = c * 64;
#pragma unroll
        for (int ni = 0; ni < 8; ni++) {
#pragma unroll
            for (int q = 0; q < 4; q++) {
                const int e = q & 1, hh = q >> 1;
                const int jg = j0 + ni * 8 + (lane & 3) * 2 + e;
                const int qi = q0 + wid * 16 + (lane >> 2) + hh * 8;
                const float v = sc[ni][q] * 0.125f + cross_bias(qi, jg);
                sc[ni][q] = (jg < TSEQ) ? v : -1e30f;
            }
        }

        // ---- online softmax ----
#pragma unroll
        for (int hh = 0; hh < 2; hh++) {
            float mb = -1e30f;
#pragma unroll
            for (int ni = 0; ni < 8; ni++)
                mb = fmaxf(mb, fmaxf(sc[ni][hh * 2], sc[ni][hh * 2 + 1]));
            mb = fmaxf(mb, __shfl_xor_sync(0xffffffffu, mb, 1));
            mb = fmaxf(mb, __shfl_xor_sync(0xffffffffu, mb, 2));
            const float mn = fmaxf(m_run[hh], mb);
            const float f = __expf(m_run[hh] - mn);
            m_run[hh] = mn;
            float sb = 0.f;
#pragma unroll
            for (int ni = 0; ni < 8; ni++) {
                const float p0 = __expf(sc[ni][hh * 2] - mn);
                const float p1 = __expf(sc[ni][hh * 2 + 1] - mn);
                sc[ni][hh * 2] = p0; sc[ni][hh * 2 + 1] = p1;
                sb += p0 + p1;
            }
            sb += __shfl_xor_sync(0xffffffffu, sb, 1);
            sb += __shfl_xor_sync(0xffffffffu, sb, 2);
            s_run[hh] = s_run[hh] * f + sb;
#pragma unroll
            for (int ni = 0; ni < 8; ni++) {
                yc[ni][hh * 2]     *= f;
                yc[ni][hh * 2 + 1] *= f;
            }
        }

        // ---- Y += P V ----
#pragma unroll
        for (int kk = 0; kk < 4; kk++) {
            uint32_t pa[4];
#pragma unroll
            for (int t = 0; t < 2; t++) {
                const float* s0 = sc[kk * 2 + t];
                pa[t * 2 + 0] = pack_f16(s0[0], s0[1]);
                pa[t * 2 + 1] = pack_f16(s0[2], s0[3]);
            }
#pragma unroll
            for (int np = 0; np < 4; np++) {
                uint32_t v4[4];
                const uint32_t vo = vRow4 + (uint32_t)(kk * 16) * APB
                                  + (uint32_t)(np * 16) * 2 + vCol4;
                ldmatrix_x4_trans(v4, svh + vo);
                mma_f16(yc[np * 2 + 0], pa, &v4[0]);
                mma_f16(yc[np * 2 + 1], pa, &v4[2]);
            }
        }
    }

    // ---- epilogue ----
#pragma unroll
    for (int hh = 0; hh < 2; hh++) {
        const float ri = 1.0f / s_run[hh];
        const int r = wid * 16 + (lane >> 2) + hh * 8;
        const int t = q0 + r;
        if (t >= TSEQ) continue;
        const size_t base = ((size_t)b * TSEQ + t) * NC + h * HD;
#pragma unroll
        for (int ni = 0; ni < 8; ni++) {
            const int d = ni * 8 + (lane & 3) * 2;
            __half2 hv = __floats2half2_rn(yc[ni][hh * 2] * ri, yc[ni][hh * 2 + 1] * ri);
            *(__half2*)(g_a_h + base + d) = hv;
        }
    }
}

// ---------------------------------------------------------------------------
extern "C" void kernel_launch(void* const* d_in, const int* in_sizes, int n_in,
                              void* d_out, int out_size)
{
    const float* x      = (const float*)d_in[0];
    const float* W_attn = (const float*)d_in[1];
    const float* b_attn = (const float*)d_in[2];
    const float* W_proj = (const float*)d_in[3];
    const float* b_proj = (const float*)d_in[4];
    float* out = (float*)d_out;

    cudaFuncSetAttribute(gemm_f16, cudaFuncAttributeMaxDynamicSharedMemorySize, GEMM_SMEM);
    cudaFuncSetAttribute(attn_flash, cudaFuncAttributeMaxDynamicSharedMemorySize, ATTN_SMEM);

    void *pAh, *pQh, *pWqH, *pWpH;
    cudaGetSymbolAddress(&pAh,  g_a_h);
    cudaGetSymbolAddress(&pQh,  g_qkv_h);
    cudaGetSymbolAddress(&pWqH, g_wq_h);
    cudaGetSymbolAddress(&pWpH, g_wp_h);

    const size_t n4 = (size_t)MROWS * NC / 4;
    cvt_f16<<<(int)((n4 + 255) / 256), 256>>>(x, (f16*)pAh, n4);
    transpose_f16<<<dim3(NQKV / 32, GK / 32), 256>>>(W_attn, (f16*)pWqH, GK, NQKV);
    transpose_f16<<<dim3(NC / 32, GK / 32), 256>>>(W_proj, (f16*)pWpH, GK, NC);

    // qkv = x @ W_attn + b_attn
    dim3 g1(NQKV / 128, (MROWS + 127) / 128);
    gemm_f16<<<g1, 256, GEMM_SMEM>>>((f16*)pAh, (f16*)pWqH, b_attn,
                                     nullptr, (f16*)pQh, MROWS, NQKV);

    // attention (writes y into g_a_h)
    dim3 ga((TSEQ + AQR - 1) / AQR, NB * NH);
    attn_flash<<<ga, 256, ATTN_SMEM>>>();

    // out = y @ W_proj + b_proj
    dim3 g2(NC / 128, (MROWS + 127) / 128);
    gemm_f16<<<g2, 256, GEMM_SMEM>>>((f16*)pAh, (f16*)pWpH, b_proj,
                                     out, nullptr, MROWS, NC);
}

// round 10
// speedup vs baseline: 9.2243x; 1.0401x over previous
#include <cuda_runtime.h>
#include <cuda_fp16.h>
#include <cstdint>

// ---------------------------------------------------------------------------
// CrossOnlyAttention  (B=64, T=469, C=1024, H=16, hd=64)
// Round 10: GEMM BK=64 chunks (half the barriers), 128B-row smem tiles with
// 8-way XOR swizzle, 3-stage cp.async ring, 2 CTAs/SM. Attention unchanged.
// ---------------------------------------------------------------------------

#define TSEQ   469
#define NB     64
#define NC     1024
#define NH     16
#define HD     64
#define MROWS  (NB * TSEQ)   // 30016
#define NQKV   (3 * NC)      // 3072
#define GK     1024

typedef __half f16;

__device__ f16 g_a_h[(size_t)MROWS * NC];        // activations (x, then y)
__device__ f16 g_qkv_h[(size_t)MROWS * NQKV];    // qkv
__device__ f16 g_wq_h[(size_t)NQKV * GK];        // W_attn^T
__device__ f16 g_wp_h[(size_t)NC * GK];          // W_proj^T

// ---------------------------------------------------------------------------
// helpers
// ---------------------------------------------------------------------------
__device__ __forceinline__ uint32_t smem_u32(const void* p) {
    uint32_t a;
    asm("{ .reg .u64 t; cvta.to.shared.u64 t, %1; cvt.u32.u64 %0, t; }" : "=r"(a) : "l"(p));
    return a;
}

#define CP_ASYNC16(dst, src, sz) \
    asm volatile("cp.async.cg.shared.global [%0], [%1], 16, %2;" \
                 :: "r"(dst), "l"(src), "r"(sz) : "memory")
#define CP_COMMIT() asm volatile("cp.async.commit_group;" ::: "memory")
#define CP_WAIT(N)  asm volatile("cp.async.wait_group %0;" :: "n"(N) : "memory")

__device__ __forceinline__ void ldmatrix_x4(uint32_t* r, uint32_t addr) {
    asm volatile("ldmatrix.sync.aligned.m8n8.x4.shared.b16 {%0,%1,%2,%3}, [%4];"
                 : "=r"(r[0]), "=r"(r[1]), "=r"(r[2]), "=r"(r[3]) : "r"(addr));
}
__device__ __forceinline__ void ldmatrix_x4_trans(uint32_t* r, uint32_t addr) {
    asm volatile("ldmatrix.sync.aligned.m8n8.x4.trans.shared.b16 {%0,%1,%2,%3}, [%4];"
                 : "=r"(r[0]), "=r"(r[1]), "=r"(r[2]), "=r"(r[3]) : "r"(addr));
}
__device__ __forceinline__ void mma_f16(float* c, const uint32_t* a, const uint32_t* b) {
    asm volatile("mma.sync.aligned.m16n8k16.row.col.f32.f16.f16.f32 "
                 "{%0,%1,%2,%3},{%4,%5,%6,%7},{%8,%9},{%0,%1,%2,%3};"
                 : "+f"(c[0]), "+f"(c[1]), "+f"(c[2]), "+f"(c[3])
                 : "r"(a[0]), "r"(a[1]), "r"(a[2]), "r"(a[3]), "r"(b[0]), "r"(b[1]));
}
__device__ __forceinline__ uint32_t pack_f16(float a, float b) {
    __half2 h = __floats2half2_rn(a, b);
    return *(uint32_t*)&h;
}

// ---------------------------------------------------------------------------
// conversion kernels
// ---------------------------------------------------------------------------
__global__ void cvt_f16(const float* __restrict__ src, f16* __restrict__ dst, size_t n4)
{
    size_t i = (size_t)blockIdx.x * blockDim.x + threadIdx.x;
    if (i >= n4) return;
    float4 v = ((const float4*)src)[i];
    __half2 a = __floats2half2_rn(v.x, v.y);
    __half2 b = __floats2half2_rn(v.z, v.w);
    uint2 o; o.x = *(uint32_t*)&a; o.y = *(uint32_t*)&b;
    ((uint2*)dst)[i] = o;
}

// src [K][N] fp32 -> dst [N][K] f16
__global__ void transpose_f16(const float* __restrict__ src,
                              f16* __restrict__ dst, int K, int N)
{
    __shared__ float tile[32][33];
    const int n0 = blockIdx.x * 32, k0 = blockIdx.y * 32;
    const int tx = threadIdx.x & 31, ty0 = threadIdx.x >> 5;
#pragma unroll
    for (int i = 0; i < 4; i++) {
        int ty = ty0 + i * 8;
        tile[ty][tx] = src[(size_t)(k0 + ty) * N + n0 + tx];
    }
    __syncthreads();
#pragma unroll
    for (int i = 0; i < 4; i++) {
        int ty = ty0 + i * 8;
        dst[(size_t)(n0 + ty) * K + k0 + tx] = __float2half_rn(tile[tx][ty]);
    }
}

// ---------------------------------------------------------------------------
// fp16 GEMM: out[M,N] = A[M,GK] @ B[N,GK]^T + bias
// 128x128 tile, BK=64, 3-stage ring, 128B rows w/ 8-way swizzle, 2 CTAs/SM.
// ---------------------------------------------------------------------------
#define BK        64
#define NCHUNK    (GK / BK)              // 16
#define TILE_BYTES 16384                 // 128 rows x 128 B
#define STAGE_BYTES (2 * TILE_BYTES)     // A, B = 32768
#define GEMM_SMEM  (3 * STAGE_BYTES)     // 98304

// store element (r, seg) -> r*128 + ((seg ^ (r&7))*16), seg = 16B column
__device__ __forceinline__ void tile_cp(const f16* __restrict__ src,
                                        int row0, int maxrow, int k0,
                                        uint32_t sdst, int tid)
{
#pragma unroll
    for (int i = 0; i < 4; i++) {
        const int idx = tid + i * 256;       // 0..1023
        const int r = idx >> 3, seg = idx & 7;
        const int gr = row0 + r;
        const int ok = (gr < maxrow) ? 16 : 0;
        const f16* gp = src + (size_t)min(gr, maxrow - 1) * GK + k0 + seg * 8;
        CP_ASYNC16(sdst + r * 128 + ((seg ^ (r & 7)) << 4), gp, ok);
    }
}

__global__ void __launch_bounds__(256, 2)
gemm_f16(const f16* __restrict__ A, const f16* __restrict__ B,
         const float* __restrict__ bias,
         float* __restrict__ outF, f16* __restrict__ outH,
         int M, int N)
{
    extern __shared__ char smem[];
    const uint32_t sbase = smem_u32(smem);
    const int tid = threadIdx.x, wid = tid >> 5, lane = tid & 31;
    const int warpM = wid >> 2, warpN = wid & 3;
    const int n0 = blockIdx.x * 128, m0 = blockIdx.y * 128;

    float acc[4][4][4];
#pragma unroll
    for (int i = 0; i < 4; i++)
#pragma unroll
        for (int j = 0; j < 4; j++)
#pragma unroll
            for (int q = 0; q < 4; q++) acc[i][j][q] = 0.f;

    // 8-way swizzle: row term (r&7) == (lane&7) for both A and B lane maps
    // (all mi/np/warp row offsets are multiples of 8).
    const uint32_t swz = lane & 7;
    const uint32_t aBase = (uint32_t)(warpM * 64 + (lane & 15)) * 128;
    const uint32_t bBase = (uint32_t)(warpN * 32 + (lane & 7) + ((lane >> 4) << 3)) * 128;
    uint32_t aChunk[4], bChunk[4];
#pragma unroll
    for (int ks = 0; ks < 4; ks++) {
        aChunk[ks] = (((uint32_t)(ks * 2) + (lane >> 4)) ^ swz) << 4;
        bChunk[ks] = (((uint32_t)(ks * 2) + ((lane >> 3) & 1)) ^ swz) << 4;
    }

    // prologue: stages 0, 1
    tile_cp(A, m0, M, 0, sbase, tid);
    tile_cp(B, n0, N, 0, sbase + TILE_BYTES, tid);
    CP_COMMIT();
    tile_cp(A, m0, M, BK, sbase + STAGE_BYTES, tid);
    tile_cp(B, n0, N, BK, sbase + STAGE_BYTES + TILE_BYTES, tid);
    CP_COMMIT();

    for (int c = 0; c < NCHUNK; c++) {
        if (c + 1 < NCHUNK) { CP_WAIT(1); } else { CP_WAIT(0); }
        __syncthreads();           // stage c ready; stage c-1 fully consumed

        if (c + 2 < NCHUNK) {      // refill stage (c+2)%3
            const uint32_t st = sbase + ((c + 2) % 3) * STAGE_BYTES;
            const int k0 = (c + 2) * BK;
            tile_cp(A, m0, M, k0, st, tid);
            tile_cp(B, n0, N, k0, st + TILE_BYTES, tid);
            CP_COMMIT();
        }

        const uint32_t st = sbase + (c % 3) * STAGE_BYTES;
        const uint32_t sA = st, sB = st + TILE_BYTES;

#pragma unroll
        for (int ks = 0; ks < 4; ks++) {
            uint32_t b4[2][4];
#pragma unroll
            for (int np = 0; np < 2; np++) {
                const uint32_t bo = bBase + (uint32_t)(np * 16) * 128 + bChunk[ks];
                ldmatrix_x4(b4[np], sB + bo);
            }
#pragma unroll
            for (int mi = 0; mi < 4; mi++) {
                const uint32_t ao = aBase + (uint32_t)(mi * 16) * 128 + aChunk[ks];
                uint32_t av[4];
                ldmatrix_x4(av, sA + ao);
#pragma unroll
                for (int ni = 0; ni < 4; ni++)
                    mma_f16(acc[mi][ni], av, &b4[ni >> 1][(ni & 1) * 2]);
            }
        }
    }

    const int cBase = n0 + warpN * 32 + (lane & 3) * 2;
    const int rBase = m0 + warpM * 64 + (lane >> 2);
#pragma unroll
    for (int mi = 0; mi < 4; mi++) {
#pragma unroll
        for (int ni = 0; ni < 4; ni++) {
            const int col = cBase + ni * 8;
            const float b0 = bias[col], b1 = bias[col + 1];
#pragma unroll
            for (int half = 0; half < 2; half++) {
                const int r = rBase + mi * 16 + half * 8;
                if (r >= M) continue;
                const float v0 = acc[mi][ni][half * 2 + 0] + b0;
                const float v1 = acc[mi][ni][half * 2 + 1] + b1;
                const size_t o = (size_t)r * N + col;
                if (outH) {
                    __half2 hh = __floats2half2_rn(v0, v1);
                    *(__half2*)(outH + o) = hh;
                } else {
                    *(float2*)(outF + o) = make_float2(v0, v1);
                }
            }
        }
    }
}

// ---------------------------------------------------------------------------
// flash attention (unchanged from round 9): fp16, 128 q-rows/CTA,
// online softmax, 3-stage K/V ring, 2 CTAs/SM.
// ---------------------------------------------------------------------------
#define AQR    128
#define NKB    8
#define APB    144

#define OFF_QH   0
#define OFF_KV   (128 * APB)                 // 18432
#define KVSTG    (2 * 64 * APB)              // 18432: K, V
#define ATTN_SMEM (OFF_KV + 3 * KVSTG)       // 73728

__device__ __forceinline__ float cross_bias(int i, int j)
{
    if (i == 0 || j == 0) return 1.0f;
    return ((i <= 234) != (j <= 234)) ? 1.0f : 0.0f;
}

__device__ __forceinline__ void kv_stage(const f16* khg, const f16* vhg,
                                         int j0, uint32_t buf, int tid)
{
#pragma unroll
    for (int i = 0; i < 2; i++) {
        const int idx = tid + i * 256;
        const int r = idx >> 3, seg = idx & 7;
        const int ok = (j0 + r < TSEQ) ? 16 : 0;
        const size_t g = (size_t)(j0 + r) * NQKV + seg * 8;
        const uint32_t s = buf + r * APB + seg * 16;
        CP_ASYNC16(s,            khg + g, ok);
        CP_ASYNC16(s + 64 * APB, vhg + g, ok);
    }
}

__global__ void __launch_bounds__(256, 2)
attn_flash()
{
    extern __shared__ char smem[];
    const uint32_t sbase = smem_u32(smem);

    const int tid = threadIdx.x, wid = tid >> 5, lane = tid & 31;
    const int bh = blockIdx.y;
    const int b  = bh >> 4, h = bh & 15;
    const int q0 = blockIdx.x * AQR;

    const size_t rowb = (size_t)b * TSEQ * NQKV + h * HD;
    const f16* qhg = g_qkv_h + rowb;
    const f16* khg = qhg + NC;
    const f16* vhg = qhg + 2 * NC;

#pragma unroll
    for (int i = 0; i < 4; i++) {
        const int idx = tid + i * 256;
        const int r = idx >> 3, seg = idx & 7;
        const int ok = (q0 + r < TSEQ) ? 16 : 0;
        CP_ASYNC16(sbase + OFF_QH + r * APB + seg * 16,
                   qhg + (size_t)(q0 + r) * NQKV + seg * 8, ok);
    }
    kv_stage(khg, vhg, 0, sbase + OFF_KV, tid);
    CP_COMMIT();
    kv_stage(khg, vhg, 64, sbase + OFF_KV + KVSTG, tid);
    CP_COMMIT();

    const uint32_t aRowQ = (uint32_t)(wid * 16 + (lane & 15)) * APB;
    const uint32_t aColQ = (uint32_t)((lane >> 4) * 8) * 2;
    const uint32_t kRow4 = (uint32_t)((lane & 7) + ((lane >> 4) << 3)) * APB;
    const uint32_t kColB = (uint32_t)(((lane >> 3) & 1) * 8) * 2;
    const uint32_t vRow4 = (uint32_t)((lane & 7) + ((lane >> 3) & 1) * 8) * APB;
    const uint32_t vCol4 = (uint32_t)((lane >> 4) << 3) * 2;

    uint32_t qf[4][4];
    float yc[8][4];
    float m_run[2] = {-1e30f, -1e30f};
    float s_run[2] = {0.f, 0.f};
#pragma unroll
    for (int ni = 0; ni < 8; ni++)
#pragma unroll
        for (int q = 0; q < 4; q++) yc[ni][q] = 0.f;

    for (int c = 0; c < NKB; c++) {
        if (c + 1 < NKB) { CP_WAIT(1); } else { CP_WAIT(0); }
        __syncthreads();

        if (c + 2 < NKB) {
            kv_stage(khg, vhg, (c + 2) * 64,
                     sbase + OFF_KV + ((c + 2) % 3) * KVSTG, tid);
            CP_COMMIT();
        }

        if (c == 0) {
#pragma unroll
            for (int ks = 0; ks < 4; ks++)
                ldmatrix_x4(qf[ks], sbase + OFF_QH + aRowQ + aColQ + ks * 32);
        }

        const uint32_t stg = sbase + OFF_KV + (c % 3) * KVSTG;
        const uint32_t skh = stg, svh = stg + 64 * APB;

        float sc[8][4];
#pragma unroll
        for (int ni = 0; ni < 8; ni++)
#pragma unroll
            for (int q = 0; q < 4; q++) sc[ni][q] = 0.f;

#pragma unroll
        for (int ks = 0; ks < 4; ks++) {
#pragma unroll
            for (int np = 0; np < 4; np++) {
                uint32_t k4[4];
                const uint32_t bo = kRow4 + (uint32_t)(np * 16) * APB + kColB + ks * 32;
                ldmatrix_x4(k4, skh + bo);
                mma_f16(sc[np * 2 + 0], qf[ks], &k4[0]);
                mma_f16(sc[np * 2 + 1], qf[ks], &k4[2]);
            }
        }

        const int j0 = c * 64;
#pragma unroll
        for (int ni = 0; ni < 8; ni++) {
#pragma unroll
            for (int q = 0; q < 4; q++) {
                const int e = q & 1, hh = q >> 1;
                const int jg = j0 + ni * 8 + (lane & 3) * 2 + e;
                const int qi = q0 + wid * 16 + (lane >> 2) + hh * 8;
                const float v = sc[ni][q] * 0.125f + cross_bias(qi, jg);
                sc[ni][q] = (jg < TSEQ) ? v : -1e30f;
            }
        }

#pragma unroll
        for (int hh = 0; hh < 2; hh++) {
            float mb = -1e30f;
#pragma unroll
            for (int ni = 0; ni < 8; ni++)
                mb = fmaxf(mb, fmaxf(sc[ni][hh * 2], sc[ni][hh * 2 + 1]));
            mb = fmaxf(mb, __shfl_xor_sync(0xffffffffu, mb, 1));
            mb = fmaxf(mb, __shfl_xor_sync(0xffffffffu, mb, 2));
            const float mn = fmaxf(m_run[hh], mb);
            const float f = __expf(m_run[hh] - mn);
            m_run[hh] = mn;
            float sb = 0.f;
#pragma unroll
            for (int ni = 0; ni < 8; ni++) {
                const float p0 = __expf(sc[ni][hh * 2] - mn);
                const float p1 = __expf(sc[ni][hh * 2 + 1] - mn);
                sc[ni][hh * 2] = p0; sc[ni][hh * 2 + 1] = p1;
                sb += p0 + p1;
            }
            sb += __shfl_xor_sync(0xffffffffu, sb, 1);
            sb += __shfl_xor_sync(0xffffffffu, sb, 2);
            s_run[hh] = s_run[hh] * f + sb;
#pragma unroll
            for (int ni = 0; ni < 8; ni++) {
                yc[ni][hh * 2]     *= f;
                yc[ni][hh * 2 + 1] *= f;
            }
        }

#pragma unroll
        for (int kk = 0; kk < 4; kk++) {
            uint32_t pa[4];
#pragma unroll
            for (int t = 0; t < 2; t++) {
                const float* s0 = sc[kk * 2 + t];
                pa[t * 2 + 0] = pack_f16(s0[0], s0[1]);
                pa[t * 2 + 1] = pack_f16(s0[2], s0[3]);
            }
#pragma unroll
            for (int np = 0; np < 4; np++) {
                uint32_t v4[4];
                const uint32_t vo = vRow4 + (uint32_t)(kk * 16) * APB
                                  + (uint32_t)(np * 16) * 2 + vCol4;
                ldmatrix_x4_trans(v4, svh + vo);
                mma_f16(yc[np * 2 + 0], pa, &v4[0]);
                mma_f16(yc[np * 2 + 1], pa, &v4[2]);
            }
        }
    }

#pragma unroll
    for (int hh = 0; hh < 2; hh++) {
        const float ri = 1.0f / s_run[hh];
        const int r = wid * 16 + (lane >> 2) + hh * 8;
        const int t = q0 + r;
        if (t >= TSEQ) continue;
        const size_t base = ((size_t)b * TSEQ + t) * NC + h * HD;
#pragma unroll
        for (int ni = 0; ni < 8; ni++) {
            const int d = ni * 8 + (lane & 3) * 2;
            __half2 hv = __floats2half2_rn(yc[ni][hh * 2] * ri, yc[ni][hh * 2 + 1] * ri);
            *(__half2*)(g_a_h + base + d) = hv;
        }
    }
}

// ---------------------------------------------------------------------------
extern "C" void kernel_launch(void* const* d_in, const int* in_sizes, int n_in,
                              void* d_out, int out_size)
{
    const float* x      = (const float*)d_in[0];
    const float* W_attn = (const float*)d_in[1];
    const float* b_attn = (const float*)d_in[2];
    const float* W_proj = (const float*)d_in[3];
    const float* b_proj = (const float*)d_in[4];
    float* out = (float*)d_out;

    cudaFuncSetAttribute(gemm_f16, cudaFuncAttributeMaxDynamicSharedMemorySize, GEMM_SMEM);
    cudaFuncSetAttribute(attn_flash, cudaFuncAttributeMaxDynamicSharedMemorySize, ATTN_SMEM);

    void *pAh, *pQh, *pWqH, *pWpH;
    cudaGetSymbolAddress(&pAh,  g_a_h);
    cudaGetSymbolAddress(&pQh,  g_qkv_h);
    cudaGetSymbolAddress(&pWqH, g_wq_h);
    cudaGetSymbolAddress(&pWpH, g_wp_h);

    const size_t n4 = (size_t)MROWS * NC / 4;
    cvt_f16<<<(int)((n4 + 255) / 256), 256>>>(x, (f16*)pAh, n4);
    transpose_f16<<<dim3(NQKV / 32, GK / 32), 256>>>(W_attn, (f16*)pWqH, GK, NQKV);
    transpose_f16<<<dim3(NC / 32, GK / 32), 256>>>(W_proj, (f16*)pWpH, GK, NC);

    // qkv = x @ W_attn + b_attn
    dim3 g1(NQKV / 128, (MROWS + 127) / 128);
    gemm_f16<<<g1, 256, GEMM_SMEM>>>((f16*)pAh, (f16*)pWqH, b_attn,
                                     nullptr, (f16*)pQh, MROWS, NQKV);

    // attention (writes y into g_a_h)
    dim3 ga((TSEQ + AQR - 1) / AQR, NB * NH);
    attn_flash<<<ga, 256, ATTN_SMEM>>>();

    // out = y @ W_proj + b_proj
    dim3 g2(NC / 128, (MROWS + 127) / 128);
    gemm_f16<<<g2, 256, GEMM_SMEM>>>((f16*)pAh, (f16*)pWpH, b_proj,
                                     out, nullptr, MROWS, NC);
}